// round 1
// baseline (speedup 1.0000x reference)
#include <cuda_runtime.h>
#include <math.h>

#define Bb 16
#define Cc 384
#define Nn 4096
#define HEADS 8
#define CH 48

// Scratch (allocation-free: device globals)
__device__ float g_S [Bb*Cc*Cc];   // X X^T per batch
__device__ float g_U1[Bb*Cc*Cc];   // W1 @ S
__device__ float g_U2[Bb*Cc*Cc];   // W2 @ S
__device__ float g_M [Bb*Cc*Cc];   // folded (A+I)W3 per batch
__device__ float g_sx[Bb*Cc];      // row sums of X
__device__ float g_mb[Bb*Cc];      // folded bias (A+I)b3

// ---------------------------------------------------------------------------
// Kernel 0: row sums sx[b,c] = sum_n x[b,c,n]
// ---------------------------------------------------------------------------
__global__ void __launch_bounds__(256) k_rowsum(const float* __restrict__ x) {
    int row = blockIdx.x;                       // 0 .. B*C-1
    const float4* xr = (const float4*)(x + (size_t)row * Nn);
    float s = 0.f;
    for (int i = threadIdx.x; i < Nn / 4; i += 256) {
        float4 v = xr[i];
        s += (v.x + v.y) + (v.z + v.w);
    }
    __shared__ float red[256];
    red[threadIdx.x] = s;
    __syncthreads();
    for (int o = 128; o; o >>= 1) {
        if (threadIdx.x < o) red[threadIdx.x] += red[threadIdx.x + o];
        __syncthreads();
    }
    if (threadIdx.x == 0) g_sx[row] = red[0];
}

// ---------------------------------------------------------------------------
// Generic NT GEMM: C[i,j] = sum_k A[i,k] * B[j,k]   (both K-contiguous)
// 128x128 tile, 256 threads, 8x8 per thread, KT=16. ldc fixed = 384.
// Used for: S = X X^T (K=4096), U1 = W1 S, U2 = W2 S (K=384, S symmetric).
// ---------------------------------------------------------------------------
__global__ void __launch_bounds__(256) gemm_nt(
    const float* __restrict__ Ag, const float* __restrict__ Bg,
    float* __restrict__ Cg, int K,
    size_t strA, size_t strB, size_t strC)
{
    __shared__ float sA[16][132];
    __shared__ float sB[16][132];

    const int tid = threadIdx.x;
    const int tx = tid & 15, ty = tid >> 4;
    const int lf = tid & 3,  lr = tid >> 2;   // loader: float4 index, row

    const float* A  = Ag + blockIdx.z * strA + (size_t)blockIdx.x * 128 * K;
    const float* Bp = Bg + blockIdx.z * strB + (size_t)blockIdx.y * 128 * K;
    float*       Cp = Cg + blockIdx.z * strC + (size_t)blockIdx.x * 128 * Cc
                         + blockIdx.y * 128;

    const float* Ar0 = A  + (size_t)lr        * K + lf * 4;
    const float* Ar1 = A  + (size_t)(lr + 64) * K + lf * 4;
    const float* Br0 = Bp + (size_t)lr        * K + lf * 4;
    const float* Br1 = Bp + (size_t)(lr + 64) * K + lf * 4;

    float acc[8][8];
#pragma unroll
    for (int i = 0; i < 8; i++)
#pragma unroll
        for (int j = 0; j < 8; j++) acc[i][j] = 0.f;

    const int lf4 = lf * 4;

    for (int k0 = 0; k0 < K; k0 += 16) {
        float4 a0 = *(const float4*)(Ar0 + k0);
        float4 a1 = *(const float4*)(Ar1 + k0);
        float4 b0 = *(const float4*)(Br0 + k0);
        float4 b1 = *(const float4*)(Br1 + k0);
        __syncthreads();
        sA[lf4+0][lr]    = a0.x; sA[lf4+1][lr]    = a0.y;
        sA[lf4+2][lr]    = a0.z; sA[lf4+3][lr]    = a0.w;
        sA[lf4+0][lr+64] = a1.x; sA[lf4+1][lr+64] = a1.y;
        sA[lf4+2][lr+64] = a1.z; sA[lf4+3][lr+64] = a1.w;
        sB[lf4+0][lr]    = b0.x; sB[lf4+1][lr]    = b0.y;
        sB[lf4+2][lr]    = b0.z; sB[lf4+3][lr]    = b0.w;
        sB[lf4+0][lr+64] = b1.x; sB[lf4+1][lr+64] = b1.y;
        sB[lf4+2][lr+64] = b1.z; sB[lf4+3][lr+64] = b1.w;
        __syncthreads();
#pragma unroll
        for (int kk = 0; kk < 16; kk++) {
            float av[8], bv[8];
            *(float4*)&av[0] = *(const float4*)&sA[kk][ty * 4];
            *(float4*)&av[4] = *(const float4*)&sA[kk][64 + ty * 4];
            *(float4*)&bv[0] = *(const float4*)&sB[kk][tx * 4];
            *(float4*)&bv[4] = *(const float4*)&sB[kk][64 + tx * 4];
#pragma unroll
            for (int i = 0; i < 8; i++)
#pragma unroll
                for (int j = 0; j < 8; j++) acc[i][j] += av[i] * bv[j];
        }
    }

#pragma unroll
    for (int i = 0; i < 8; i++) {
        int row = (i < 4) ? (ty * 4 + i) : (64 + ty * 4 + i - 4);
        float4 v0 = make_float4(acc[i][0], acc[i][1], acc[i][2], acc[i][3]);
        float4 v1 = make_float4(acc[i][4], acc[i][5], acc[i][6], acc[i][7]);
        *(float4*)(Cp + (size_t)row * Cc +      tx * 4) = v0;
        *(float4*)(Cp + (size_t)row * Cc + 64 + tx * 4) = v1;
    }
}

// ---------------------------------------------------------------------------
// Attention + fold kernel: one block per (head, batch), 256 threads.
// Computes attn = softmax( (Gqk / (nq nk)) * temp ), then folds
// M = (attn + I) @ W3h  and  mb = (attn + I) @ b3h.
// ---------------------------------------------------------------------------
__global__ void __launch_bounds__(256) k_attn_fold(
    const float* __restrict__ w1, const float* __restrict__ b1,
    const float* __restrict__ w2, const float* __restrict__ b2,
    const float* __restrict__ w3, const float* __restrict__ b3,
    const float* __restrict__ temp)
{
    const int h = blockIdx.x, b = blockIdx.y;
    const int tid = threadIdx.x;
    const int warp = tid >> 5, lane = tid & 31;

    __shared__ float sU[CH * 65];
    __shared__ float sW[CH * 65];
    __shared__ float sAa[CH * 49];
    __shared__ float sNq[CH], sNk[CH], sP1[CH], sP2[CH];
    __shared__ float sB1[CH], sB2[CH], sB3[CH];

    const float* U1  = &g_U1[(size_t)b * Cc * Cc + (size_t)h * CH * Cc];
    const float* U2  = &g_U2[(size_t)b * Cc * Cc + (size_t)h * CH * Cc];
    const float* w1h = w1 + (size_t)h * CH * Cc;
    const float* w2h = w2 + (size_t)h * CH * Cc;
    const float* w3h = w3 + (size_t)h * CH * Cc;
    const float* sx  = &g_sx[b * Cc];

    if (tid < CH) {
        sB1[tid] = b1[h * CH + tid];
        sB2[tid] = b2[h * CH + tid];
        sB3[tid] = b3[h * CH + tid];
    }

    // Phase 1: Gqk[c,d] partial = dot(U1_c, w2h_d), chunked through smem
    float acc[9];
#pragma unroll
    for (int e = 0; e < 9; e++) acc[e] = 0.f;

    for (int k0 = 0; k0 < Cc; k0 += 64) {
        __syncthreads();
        for (int i = tid; i < CH * 64; i += 256) {
            int c = i >> 6, kk = i & 63;
            sU[c * 65 + kk] = U1[c * Cc + k0 + kk];
            sW[c * 65 + kk] = w2h[c * Cc + k0 + kk];
        }
        __syncthreads();
#pragma unroll
        for (int e = 0; e < 9; e++) {
            int idx = tid + 256 * e;        // 0..2303
            int c = idx / CH, d = idx - c * CH;
            float s = 0.f;
#pragma unroll 16
            for (int kk = 0; kk < 64; kk++)
                s += sU[c * 65 + kk] * sW[d * 65 + kk];
            acc[e] += s;
        }
    }

    // Phase 2: per-row reductions (quadratic forms + sx projections)
    __syncthreads();
    for (int c = warp * 6; c < warp * 6 + 6; c++) {
        float aq = 0.f, ak = 0.f, p1 = 0.f, p2 = 0.f;
        for (int k = lane; k < Cc; k += 32) {
            float w1v = w1h[c * Cc + k];
            float w2v = w2h[c * Cc + k];
            aq += U1[c * Cc + k] * w1v;
            ak += U2[c * Cc + k] * w2v;
            float sv = sx[k];
            p1 += w1v * sv;
            p2 += w2v * sv;
        }
#pragma unroll
        for (int o = 16; o; o >>= 1) {
            aq += __shfl_xor_sync(0xffffffffu, aq, o);
            ak += __shfl_xor_sync(0xffffffffu, ak, o);
            p1 += __shfl_xor_sync(0xffffffffu, p1, o);
            p2 += __shfl_xor_sync(0xffffffffu, p2, o);
        }
        if (lane == 0) { sNq[c] = aq; sNk[c] = ak; sP1[c] = p1; sP2[c] = p2; }
    }
    __syncthreads();

    // Phase 3: normalized logits
    const float tH = temp[h];
#pragma unroll
    for (int e = 0; e < 9; e++) {
        int idx = tid + 256 * e;
        int c = idx / CH, d = idx - c * CH;
        float b1c = sB1[c], b2d = sB2[d];
        float nq = sqrtf(fmaxf(sNq[c] + 2.f * b1c * sP1[c] + 4096.f * b1c * b1c, 0.f));
        float nk = sqrtf(fmaxf(sNk[d] + 2.f * b2d * sP2[d] + 4096.f * b2d * b2d, 0.f));
        float g  = acc[e] + b1c * sP2[d] + b2d * sP1[c] + 4096.f * b1c * b2d;
        sAa[c * 49 + d] = g / (fmaxf(nq, 1e-12f) * fmaxf(nk, 1e-12f)) * tH;
    }
    __syncthreads();

    // Phase 4: softmax over rows (48 wide), one warp per 6 rows
    for (int c = warp * 6; c < warp * 6 + 6; c++) {
        float a0 = sAa[c * 49 + lane];
        float a1 = (lane < 16) ? sAa[c * 49 + 32 + lane] : -3.402823466e38f;
        float m = fmaxf(a0, a1);
#pragma unroll
        for (int o = 16; o; o >>= 1) m = fmaxf(m, __shfl_xor_sync(0xffffffffu, m, o));
        float e0 = __expf(a0 - m);
        float e1 = (lane < 16) ? __expf(a1 - m) : 0.f;
        float s = e0 + e1;
#pragma unroll
        for (int o = 16; o; o >>= 1) s += __shfl_xor_sync(0xffffffffu, s, o);
        float inv = 1.f / s;
        sAa[c * 49 + lane] = e0 * inv;
        if (lane < 16) sAa[c * 49 + 32 + lane] = e1 * inv;
    }
    __syncthreads();

    // Phase 5: folded bias mb = (A+I) b3h
    if (tid < CH) {
        float s = sB3[tid];
#pragma unroll 8
        for (int d = 0; d < CH; d++) s += sAa[tid * 49 + d] * sB3[d];
        g_mb[b * Cc + h * CH + tid] = s;
    }

    // Phase 6: fold M = (A+I) @ W3h, chunked through smem (reuse sW)
    for (int k0 = 0; k0 < Cc; k0 += 64) {
        __syncthreads();
        for (int i = tid; i < CH * 64; i += 256) {
            int d = i >> 6, kk = i & 63;
            sW[d * 65 + kk] = w3h[d * Cc + k0 + kk];
        }
        __syncthreads();
        for (int i = tid; i < CH * 64; i += 256) {
            int c = i >> 6, kk = i & 63;
            float s = sW[c * 65 + kk];   // identity term
#pragma unroll 8
            for (int d = 0; d < CH; d++) s += sAa[c * 49 + d] * sW[d * 65 + kk];
            g_M[(size_t)b * Cc * Cc + (size_t)(h * CH + c) * Cc + k0 + kk] = s;
        }
    }
}

// ---------------------------------------------------------------------------
// Final NN GEMM with epilogue: out = M_b @ X_b + mb_b + X_b
// 128x128 tile, K=384.
// ---------------------------------------------------------------------------
__global__ void __launch_bounds__(256) gemm_nn_out(
    const float* __restrict__ x, float* __restrict__ out)
{
    __shared__ float sA[16][132];
    __shared__ float sB[16][132];

    const int tid = threadIdx.x;
    const int tx = tid & 15, ty = tid >> 4;
    const int lf = tid & 3,  lr = tid >> 2;   // A loader
    const int bf = tid & 31, br = tid >> 5;   // B loader
    const int b = blockIdx.z;

    const float* A  = g_M + (size_t)b * Cc * Cc + (size_t)blockIdx.x * 128 * Cc;
    const float* Bx = x + (size_t)b * Cc * Nn + blockIdx.y * 128;

    float acc[8][8];
#pragma unroll
    for (int i = 0; i < 8; i++)
#pragma unroll
        for (int j = 0; j < 8; j++) acc[i][j] = 0.f;

    const int lf4 = lf * 4;

    for (int k0 = 0; k0 < Cc; k0 += 16) {
        float4 a0 = *(const float4*)(A + (size_t)lr        * Cc + k0 + lf4);
        float4 a1 = *(const float4*)(A + (size_t)(lr + 64) * Cc + k0 + lf4);
        float4 v0 = *(const float4*)(Bx + (size_t)(k0 + br)     * Nn + bf * 4);
        float4 v1 = *(const float4*)(Bx + (size_t)(k0 + br + 8) * Nn + bf * 4);
        __syncthreads();
        sA[lf4+0][lr]    = a0.x; sA[lf4+1][lr]    = a0.y;
        sA[lf4+2][lr]    = a0.z; sA[lf4+3][lr]    = a0.w;
        sA[lf4+0][lr+64] = a1.x; sA[lf4+1][lr+64] = a1.y;
        sA[lf4+2][lr+64] = a1.z; sA[lf4+3][lr+64] = a1.w;
        *(float4*)&sB[br][bf * 4]     = v0;
        *(float4*)&sB[br + 8][bf * 4] = v1;
        __syncthreads();
#pragma unroll
        for (int kk = 0; kk < 16; kk++) {
            float av[8], bv[8];
            *(float4*)&av[0] = *(const float4*)&sA[kk][ty * 4];
            *(float4*)&av[4] = *(const float4*)&sA[kk][64 + ty * 4];
            *(float4*)&bv[0] = *(const float4*)&sB[kk][tx * 4];
            *(float4*)&bv[4] = *(const float4*)&sB[kk][64 + tx * 4];
#pragma unroll
            for (int i = 0; i < 8; i++)
#pragma unroll
                for (int j = 0; j < 8; j++) acc[i][j] += av[i] * bv[j];
        }
    }

    // Epilogue: + mb[row] + x[row, col]
#pragma unroll
    for (int i = 0; i < 8; i++) {
        int row  = (i < 4) ? (ty * 4 + i) : (64 + ty * 4 + i - 4);
        int grow = blockIdx.x * 128 + row;
        float bias = g_mb[b * Cc + grow];
        const float* xr = x   + ((size_t)b * Cc + grow) * Nn + blockIdx.y * 128;
        float*       orr = out + ((size_t)b * Cc + grow) * Nn + blockIdx.y * 128;
        float4 xv0 = *(const float4*)(xr +      tx * 4);
        float4 xv1 = *(const float4*)(xr + 64 + tx * 4);
        float4 o0 = make_float4(acc[i][0] + bias + xv0.x,
                                acc[i][1] + bias + xv0.y,
                                acc[i][2] + bias + xv0.z,
                                acc[i][3] + bias + xv0.w);
        float4 o1 = make_float4(acc[i][4] + bias + xv1.x,
                                acc[i][5] + bias + xv1.y,
                                acc[i][6] + bias + xv1.z,
                                acc[i][7] + bias + xv1.w);
        *(float4*)(orr +      tx * 4) = o0;
        *(float4*)(orr + 64 + tx * 4) = o1;
    }
}

// ---------------------------------------------------------------------------
extern "C" void kernel_launch(void* const* d_in, const int* in_sizes, int n_in,
                              void* d_out, int out_size)
{
    (void)in_sizes; (void)n_in; (void)out_size;
    const float* x    = (const float*)d_in[0];
    const float* w1   = (const float*)d_in[1];
    const float* b1   = (const float*)d_in[2];
    const float* w2   = (const float*)d_in[3];
    const float* b2   = (const float*)d_in[4];
    const float* w3   = (const float*)d_in[5];
    const float* b3   = (const float*)d_in[6];
    const float* temp = (const float*)d_in[7];
    float* out = (float*)d_out;

    void *pS = nullptr, *pU1 = nullptr, *pU2 = nullptr;
    cudaGetSymbolAddress(&pS,  g_S);
    cudaGetSymbolAddress(&pU1, g_U1);
    cudaGetSymbolAddress(&pU2, g_U2);

    // 0) row sums of x
    k_rowsum<<<Bb * Cc, 256>>>(x);
    // 1) S_b = X_b X_b^T
    gemm_nt<<<dim3(3, 3, Bb), 256>>>(x, x, (float*)pS, Nn,
                                     (size_t)Cc * Nn, (size_t)Cc * Nn,
                                     (size_t)Cc * Cc);
    // 2) U1 = W1 @ S_b, U2 = W2 @ S_b  (S symmetric -> NT form)
    gemm_nt<<<dim3(3, 3, Bb), 256>>>(w1, (const float*)pS, (float*)pU1, Cc,
                                     0, (size_t)Cc * Cc, (size_t)Cc * Cc);
    gemm_nt<<<dim3(3, 3, Bb), 256>>>(w2, (const float*)pS, (float*)pU2, Cc,
                                     0, (size_t)Cc * Cc, (size_t)Cc * Cc);
    // 3) attention + fold M, mb
    k_attn_fold<<<dim3(HEADS, Bb), 256>>>(w1, b1, w2, b2, w3, b3, temp);
    // 4) out = M_b @ X_b + mb + x
    gemm_nn_out<<<dim3(3, 32, Bb), 256>>>(x, out);
}

// round 3
// speedup vs baseline: 1.6702x; 1.6702x over previous
#include <cuda_runtime.h>
#include <cuda_bf16.h>
#include <math.h>
#include <stdint.h>

#define Bb 16
#define Cc 384
#define Nn 4096
#define HEADS 8
#define CH 48

#define XSZ (Bb*Cc*Nn)
#define SSZ (Bb*Cc*Cc)
#define WSZ (Cc*Cc)

// ---------------- scratch (device globals; allocation-free) ----------------
__device__ __nv_bfloat16 g_Xh[XSZ], g_Xl[XSZ];     // x split, [b][c][n]
__device__ __nv_bfloat16 g_Xth[XSZ], g_Xtl[XSZ];   // x^T split, [b][n][c]
__device__ __nv_bfloat16 g_Sh[SSZ], g_Sl[SSZ];     // S split
__device__ __nv_bfloat16 g_Mh[SSZ], g_Ml[SSZ];     // folded M split
__device__ __nv_bfloat16 g_W1h[WSZ], g_W1l[WSZ], g_W2h[WSZ], g_W2l[WSZ];
__device__ float g_U1[SSZ], g_U2[SSZ];
__device__ float g_sx[Bb*Cc], g_mb[Bb*Cc];

// ---------------- PTX helpers (non-'a'-gated only: sm_80-class) -----------
__device__ __forceinline__ uint32_t smem_u32(const void* p) {
    uint32_t a;
    asm("{ .reg .u64 t; cvta.to.shared.u64 t, %1; cvt.u32.u64 %0, t; }"
        : "=r"(a) : "l"(p));
    return a;
}

__device__ __forceinline__ void ldsm4(uint32_t* r, uint32_t addr) {
    asm volatile("ldmatrix.sync.aligned.m8n8.x4.shared.b16 {%0,%1,%2,%3}, [%4];"
                 : "=r"(r[0]), "=r"(r[1]), "=r"(r[2]), "=r"(r[3]) : "r"(addr));
}

__device__ __forceinline__ void mma16816(float* c, const uint32_t* a, const uint32_t* b) {
    asm volatile(
        "mma.sync.aligned.m16n8k16.row.col.f32.bf16.bf16.f32 "
        "{%0,%1,%2,%3}, {%4,%5,%6,%7}, {%8,%9}, {%0,%1,%2,%3};"
        : "+f"(c[0]), "+f"(c[1]), "+f"(c[2]), "+f"(c[3])
        : "r"(a[0]), "r"(a[1]), "r"(a[2]), "r"(a[3]), "r"(b[0]), "r"(b[1]));
}

// smem geometry: K-major tiles, 128 rows x 32 bf16, padded row = 40 bf16 (80 B)
#define SROW 40
#define MATB (128 * SROW * 2)   // 10240 bytes per matrix buffer
#define DSMEM_BYTES 69632       // >= max(4*MATB=40960, 128*132*4=67584)

// ---------------------------------------------------------------------------
// convert: x -> (Xh, Xl) [b][c][n] and (Xth, Xtl) [b][n][c], bf16 hi/lo split
// ---------------------------------------------------------------------------
__global__ void __launch_bounds__(256) k_convert(const float* __restrict__ x) {
    __shared__ float t[32][33];
    const int b = blockIdx.z, c0 = blockIdx.y * 32, n0 = blockIdx.x * 32;
    const int tx = threadIdx.x & 31, ty = threadIdx.x >> 5;
#pragma unroll
    for (int r = 0; r < 4; r++) {
        int c = c0 + ty + r * 8;
        size_t idx = ((size_t)b * Cc + c) * Nn + n0 + tx;
        float v = x[idx];
        t[ty + r * 8][tx] = v;
        __nv_bfloat16 h = __float2bfloat16(v);
        g_Xh[idx] = h;
        g_Xl[idx] = __float2bfloat16(v - __bfloat162float(h));
    }
    __syncthreads();
#pragma unroll
    for (int r = 0; r < 4; r++) {
        int n = n0 + ty + r * 8;
        float v = t[tx][ty + r * 8];
        __nv_bfloat16 h = __float2bfloat16(v);
        size_t idx = ((size_t)b * Nn + n) * Cc + c0 + tx;
        g_Xth[idx] = h;
        g_Xtl[idx] = __float2bfloat16(v - __bfloat162float(h));
    }
}

// elementwise hi/lo split (weights)
__global__ void __launch_bounds__(256) k_split(const float* __restrict__ s,
                                               __nv_bfloat16* __restrict__ h,
                                               __nv_bfloat16* __restrict__ l, int n) {
    int i = blockIdx.x * 256 + threadIdx.x;
    if (i < n) {
        float v = s[i];
        __nv_bfloat16 hv = __float2bfloat16(v);
        h[i] = hv;
        l[i] = __float2bfloat16(v - __bfloat162float(hv));
    }
}

// row sums sx[b,c] = sum_n x[b,c,n]
__global__ void __launch_bounds__(256) k_rowsum(const float* __restrict__ x) {
    int row = blockIdx.x;
    const float4* xr = (const float4*)(x + (size_t)row * Nn);
    float s = 0.f;
    for (int i = threadIdx.x; i < Nn / 4; i += 256) {
        float4 v = xr[i];
        s += (v.x + v.y) + (v.z + v.w);
    }
    __shared__ float red[256];
    red[threadIdx.x] = s;
    __syncthreads();
    for (int o = 128; o; o >>= 1) {
        if (threadIdx.x < o) red[threadIdx.x] += red[threadIdx.x + o];
        __syncthreads();
    }
    if (threadIdx.x == 0) g_sx[row] = red[0];
}

// ---------------------------------------------------------------------------
// mma.sync NT GEMM with bf16 2-term compensated split:
//   D = Ah Bh^T + Ah Bl^T + Al Bh^T    (fp32 accumulate)
// 128x128 tile, BK=32, 8 warps (warp tile 32x64), register-prefetch pipeline.
// mode 0: write Sh/Sl bf16 split.  mode 1: write Cf fp32.
// mode 2: out = D + g_mb[row] + xres[row,col]  (ldc = Nn)
// ---------------------------------------------------------------------------
__global__ void __launch_bounds__(256) gemm_bsplit(
    const __nv_bfloat16* __restrict__ Ah, const __nv_bfloat16* __restrict__ Al,
    const __nv_bfloat16* __restrict__ Bh, const __nv_bfloat16* __restrict__ Bl,
    int K, size_t strA, size_t strB, int mode,
    float* __restrict__ Cf,
    __nv_bfloat16* __restrict__ Ch, __nv_bfloat16* __restrict__ Cl,
    const float* __restrict__ xres)
{
    extern __shared__ char dsm[];
    const int tid = threadIdx.x;
    const int lane = tid & 31, wid = tid >> 5;
    const int wm = wid & 3, wn = wid >> 2;      // warp tile origin: (wm*32, wn*64)
    const int bx = blockIdx.x, by = blockIdx.y, bz = blockIdx.z;

    const uint32_t smb = smem_u32(dsm);

    const __nv_bfloat16* ptr[4];
    ptr[0] = Ah + bz * strA + (size_t)bx * 128 * K;
    ptr[1] = Al + bz * strA + (size_t)bx * 128 * K;
    ptr[2] = Bh + bz * strB + (size_t)by * 128 * K;
    ptr[3] = Bl + bz * strB + (size_t)by * 128 * K;

    // fill coords: 2 uint4 per matrix per chunk per thread
    int frow[2], fq[2];
#pragma unroll
    for (int j = 0; j < 2; j++) {
        int u = tid + 256 * j;
        frow[j] = u >> 2;          // 0..127
        fq[j]   = u & 3;           // 16B quarter within 64B row
    }

    float acc[2][8][4];
#pragma unroll
    for (int i = 0; i < 2; i++)
#pragma unroll
        for (int j = 0; j < 8; j++)
#pragma unroll
            for (int q = 0; q < 4; q++) acc[i][j][q] = 0.f;

    // ldmatrix lane-address components
    const int grp = lane >> 3, lr = lane & 7;

    uint4 v[4][2];
#pragma unroll
    for (int m = 0; m < 4; m++)
#pragma unroll
        for (int j = 0; j < 2; j++)
            v[m][j] = *(const uint4*)(ptr[m] + (size_t)frow[j] * K + fq[j] * 8);

    const int nch = K / 32;
    for (int i = 0; i < nch; i++) {
        // store prefetched chunk
#pragma unroll
        for (int m = 0; m < 4; m++)
#pragma unroll
            for (int j = 0; j < 2; j++)
                *(uint4*)(dsm + m * MATB + frow[j] * (SROW * 2) + fq[j] * 16) = v[m][j];
        __syncthreads();

        if (i + 1 < nch) {
            const int k0 = (i + 1) * 32;
#pragma unroll
            for (int m = 0; m < 4; m++)
#pragma unroll
                for (int j = 0; j < 2; j++)
                    v[m][j] = *(const uint4*)(ptr[m] + (size_t)frow[j] * K + k0 + fq[j] * 8);
        }

        // compute: 2 k-steps of 16
#pragma unroll
        for (int ks = 0; ks < 2; ks++) {
            const int kc = ks * 16;
            uint32_t ah[2][4], al[2][4];
#pragma unroll
            for (int ti = 0; ti < 2; ti++) {
                int row = wm * 32 + ti * 16 + lr + (grp & 1) * 8;
                int col = kc + (grp >> 1) * 8;
                uint32_t addr = smb + row * (SROW * 2) + col * 2;
                ldsm4(ah[ti], addr);             // Ah at matrix 0
                ldsm4(al[ti], addr + MATB);      // Al at matrix 1
            }
#pragma unroll
            for (int half = 0; half < 2; half++) {
                uint32_t bhf[4][2], blf[4][2];
#pragma unroll
                for (int p = 0; p < 2; p++) {
                    int nrow = wn * 64 + half * 32 + p * 16 + (grp >> 1) * 8 + lr;
                    int col = kc + (grp & 1) * 8;
                    uint32_t addr = smb + 2 * MATB + nrow * (SROW * 2) + col * 2;
                    uint32_t r4[4];
                    ldsm4(r4, addr);
                    bhf[2*p][0] = r4[0]; bhf[2*p][1] = r4[1];
                    bhf[2*p+1][0] = r4[2]; bhf[2*p+1][1] = r4[3];
                    ldsm4(r4, addr + MATB);
                    blf[2*p][0] = r4[0]; blf[2*p][1] = r4[1];
                    blf[2*p+1][0] = r4[2]; blf[2*p+1][1] = r4[3];
                }
#pragma unroll
                for (int ti = 0; ti < 2; ti++)
#pragma unroll
                    for (int tj = 0; tj < 4; tj++) {
                        float* c = acc[ti][half * 4 + tj];
                        mma16816(c, ah[ti], bhf[tj]);
                        mma16816(c, ah[ti], blf[tj]);
                        mma16816(c, al[ti], bhf[tj]);
                    }
            }
        }
        __syncthreads();
    }

    // epilogue: acc -> smem (fp32, padded 132) -> gmem coalesced
    float* sC = (float*)dsm;
#pragma unroll
    for (int ti = 0; ti < 2; ti++)
#pragma unroll
        for (int j = 0; j < 8; j++) {
            int row0 = wm * 32 + ti * 16 + (lane >> 2);
            int col  = wn * 64 + j * 8 + (lane & 3) * 2;
            *(float2*)(sC + row0 * 132 + col)       = make_float2(acc[ti][j][0], acc[ti][j][1]);
            *(float2*)(sC + (row0 + 8) * 132 + col) = make_float2(acc[ti][j][2], acc[ti][j][3]);
        }
    __syncthreads();

    const int r0 = tid >> 1, half = tid & 1;
    const float* src = sC + r0 * 132 + half * 64;
    const int grow = bx * 128 + r0;
    const int gcol = by * 128 + half * 64;

    if (mode == 0) {
        size_t base = ((size_t)bz * Cc + grow) * Cc + gcol;
#pragma unroll
        for (int j = 0; j < 64; j += 2) {
            float v0 = src[j], v1 = src[j + 1];
            __nv_bfloat162 h2 = __floats2bfloat162_rn(v0, v1);
            *(__nv_bfloat162*)(Ch + base + j) = h2;
            float l0 = v0 - __bfloat162float(h2.x);
            float l1 = v1 - __bfloat162float(h2.y);
            *(__nv_bfloat162*)(Cl + base + j) = __floats2bfloat162_rn(l0, l1);
        }
    } else if (mode == 1) {
        size_t base = ((size_t)bz * Cc + grow) * Cc + gcol;
#pragma unroll
        for (int j = 0; j < 64; j += 4)
            *(float4*)(Cf + base + j) = *(const float4*)(src + j);
    } else {
        size_t base = ((size_t)bz * Cc + grow) * (size_t)Nn + gcol;
        float bias = g_mb[bz * Cc + grow];
#pragma unroll
        for (int j = 0; j < 64; j += 4) {
            float4 v4 = *(const float4*)(src + j);
            float4 xv = *(const float4*)(xres + base + j);
            *(float4*)(Cf + base + j) = make_float4(v4.x + bias + xv.x, v4.y + bias + xv.y,
                                                    v4.z + bias + xv.z, v4.w + bias + xv.w);
        }
    }
}

// ---------------------------------------------------------------------------
// attention + fold: M written as bf16 hi/lo split
// ---------------------------------------------------------------------------
__global__ void __launch_bounds__(256) k_attn_fold(
    const float* __restrict__ w1, const float* __restrict__ b1,
    const float* __restrict__ w2, const float* __restrict__ b2,
    const float* __restrict__ w3, const float* __restrict__ b3,
    const float* __restrict__ temp)
{
    const int h = blockIdx.x, b = blockIdx.y;
    const int tid = threadIdx.x;
    const int warp = tid >> 5, lane = tid & 31;

    __shared__ float sU[CH * 65];
    __shared__ float sW[CH * 65];
    __shared__ float sAa[CH * 49];
    __shared__ float sNq[CH], sNk[CH], sP1[CH], sP2[CH];
    __shared__ float sB1[CH], sB2[CH], sB3[CH];

    const float* U1  = &g_U1[(size_t)b * Cc * Cc + (size_t)h * CH * Cc];
    const float* U2  = &g_U2[(size_t)b * Cc * Cc + (size_t)h * CH * Cc];
    const float* w1h = w1 + (size_t)h * CH * Cc;
    const float* w2h = w2 + (size_t)h * CH * Cc;
    const float* w3h = w3 + (size_t)h * CH * Cc;
    const float* sx  = &g_sx[b * Cc];

    if (tid < CH) {
        sB1[tid] = b1[h * CH + tid];
        sB2[tid] = b2[h * CH + tid];
        sB3[tid] = b3[h * CH + tid];
    }

    float acc[9];
#pragma unroll
    for (int e = 0; e < 9; e++) acc[e] = 0.f;

    for (int k0 = 0; k0 < Cc; k0 += 64) {
        __syncthreads();
        for (int i = tid; i < CH * 64; i += 256) {
            int c = i >> 6, kk = i & 63;
            sU[c * 65 + kk] = U1[c * Cc + k0 + kk];
            sW[c * 65 + kk] = w2h[c * Cc + k0 + kk];
        }
        __syncthreads();
#pragma unroll
        for (int e = 0; e < 9; e++) {
            int idx = tid + 256 * e;
            int c = idx / CH, d = idx - c * CH;
            float s = 0.f;
#pragma unroll 16
            for (int kk = 0; kk < 64; kk++)
                s += sU[c * 65 + kk] * sW[d * 65 + kk];
            acc[e] += s;
        }
    }

    __syncthreads();
    for (int c = warp * 6; c < warp * 6 + 6; c++) {
        float aq = 0.f, ak = 0.f, p1 = 0.f, p2 = 0.f;
        for (int k = lane; k < Cc; k += 32) {
            float w1v = w1h[c * Cc + k];
            float w2v = w2h[c * Cc + k];
            aq += U1[c * Cc + k] * w1v;
            ak += U2[c * Cc + k] * w2v;
            float sv = sx[k];
            p1 += w1v * sv;
            p2 += w2v * sv;
        }
#pragma unroll
        for (int o = 16; o; o >>= 1) {
            aq += __shfl_xor_sync(0xffffffffu, aq, o);
            ak += __shfl_xor_sync(0xffffffffu, ak, o);
            p1 += __shfl_xor_sync(0xffffffffu, p1, o);
            p2 += __shfl_xor_sync(0xffffffffu, p2, o);
        }
        if (lane == 0) { sNq[c] = aq; sNk[c] = ak; sP1[c] = p1; sP2[c] = p2; }
    }
    __syncthreads();

    const float tH = temp[h];
#pragma unroll
    for (int e = 0; e < 9; e++) {
        int idx = tid + 256 * e;
        int c = idx / CH, d = idx - c * CH;
        float b1c = sB1[c], b2d = sB2[d];
        float nq = sqrtf(fmaxf(sNq[c] + 2.f * b1c * sP1[c] + 4096.f * b1c * b1c, 0.f));
        float nk = sqrtf(fmaxf(sNk[d] + 2.f * b2d * sP2[d] + 4096.f * b2d * b2d, 0.f));
        float g  = acc[e] + b1c * sP2[d] + b2d * sP1[c] + 4096.f * b1c * b2d;
        sAa[c * 49 + d] = g / (fmaxf(nq, 1e-12f) * fmaxf(nk, 1e-12f)) * tH;
    }
    __syncthreads();

    for (int c = warp * 6; c < warp * 6 + 6; c++) {
        float a0 = sAa[c * 49 + lane];
        float a1 = (lane < 16) ? sAa[c * 49 + 32 + lane] : -3.402823466e38f;
        float m = fmaxf(a0, a1);
#pragma unroll
        for (int o = 16; o; o >>= 1) m = fmaxf(m, __shfl_xor_sync(0xffffffffu, m, o));
        float e0 = __expf(a0 - m);
        float e1 = (lane < 16) ? __expf(a1 - m) : 0.f;
        float s = e0 + e1;
#pragma unroll
        for (int o = 16; o; o >>= 1) s += __shfl_xor_sync(0xffffffffu, s, o);
        float inv = 1.f / s;
        sAa[c * 49 + lane] = e0 * inv;
        if (lane < 16) sAa[c * 49 + 32 + lane] = e1 * inv;
    }
    __syncthreads();

    if (tid < CH) {
        float s = sB3[tid];
#pragma unroll 8
        for (int d = 0; d < CH; d++) s += sAa[tid * 49 + d] * sB3[d];
        g_mb[b * Cc + h * CH + tid] = s;
    }

    for (int k0 = 0; k0 < Cc; k0 += 64) {
        __syncthreads();
        for (int i = tid; i < CH * 64; i += 256) {
            int d = i >> 6, kk = i & 63;
            sW[d * 65 + kk] = w3h[d * Cc + k0 + kk];
        }
        __syncthreads();
        for (int i = tid; i < CH * 64; i += 256) {
            int c = i >> 6, kk = i & 63;
            float s = sW[c * 65 + kk];
#pragma unroll 8
            for (int d = 0; d < CH; d++) s += sAa[c * 49 + d] * sW[d * 65 + kk];
            size_t idx = (size_t)b * Cc * Cc + (size_t)(h * CH + c) * Cc + k0 + kk;
            __nv_bfloat16 hv = __float2bfloat16(s);
            g_Mh[idx] = hv;
            g_Ml[idx] = __float2bfloat16(s - __bfloat162float(hv));
        }
    }
}

// ---------------------------------------------------------------------------
extern "C" void kernel_launch(void* const* d_in, const int* in_sizes, int n_in,
                              void* d_out, int out_size)
{
    (void)in_sizes; (void)n_in; (void)out_size;
    const float* x    = (const float*)d_in[0];
    const float* w1   = (const float*)d_in[1];
    const float* b1   = (const float*)d_in[2];
    const float* w2   = (const float*)d_in[3];
    const float* b2   = (const float*)d_in[4];
    const float* w3   = (const float*)d_in[5];
    const float* b3   = (const float*)d_in[6];
    const float* temp = (const float*)d_in[7];
    float* out = (float*)d_out;

    cudaFuncSetAttribute(gemm_bsplit, cudaFuncAttributeMaxDynamicSharedMemorySize, DSMEM_BYTES);

    void *pXh, *pXl, *pXth, *pXtl, *pSh, *pSl, *pMh, *pMl;
    void *pW1h, *pW1l, *pW2h, *pW2l, *pU1, *pU2;
    cudaGetSymbolAddress(&pXh,  g_Xh);  cudaGetSymbolAddress(&pXl,  g_Xl);
    cudaGetSymbolAddress(&pXth, g_Xth); cudaGetSymbolAddress(&pXtl, g_Xtl);
    cudaGetSymbolAddress(&pSh,  g_Sh);  cudaGetSymbolAddress(&pSl,  g_Sl);
    cudaGetSymbolAddress(&pMh,  g_Mh);  cudaGetSymbolAddress(&pMl,  g_Ml);
    cudaGetSymbolAddress(&pW1h, g_W1h); cudaGetSymbolAddress(&pW1l, g_W1l);
    cudaGetSymbolAddress(&pW2h, g_W2h); cudaGetSymbolAddress(&pW2l, g_W2l);
    cudaGetSymbolAddress(&pU1,  g_U1);  cudaGetSymbolAddress(&pU2,  g_U2);

    // 0) splits + transpose + row sums
    k_convert<<<dim3(Nn / 32, Cc / 32, Bb), 256>>>(x);
    k_split<<<(WSZ + 255) / 256, 256>>>(w1, (__nv_bfloat16*)pW1h, (__nv_bfloat16*)pW1l, WSZ);
    k_split<<<(WSZ + 255) / 256, 256>>>(w2, (__nv_bfloat16*)pW2h, (__nv_bfloat16*)pW2l, WSZ);
    k_rowsum<<<Bb * Cc, 256>>>(x);

    // 1) S_b = X_b X_b^T  (split) -> Sh/Sl
    gemm_bsplit<<<dim3(3, 3, Bb), 256, DSMEM_BYTES>>>(
        (const __nv_bfloat16*)pXh, (const __nv_bfloat16*)pXl,
        (const __nv_bfloat16*)pXh, (const __nv_bfloat16*)pXl,
        Nn, (size_t)Cc * Nn, (size_t)Cc * Nn, 0,
        nullptr, (__nv_bfloat16*)pSh, (__nv_bfloat16*)pSl, nullptr);

    // 2) U1 = W1 S_b, U2 = W2 S_b  (S symmetric -> NT form)
    gemm_bsplit<<<dim3(3, 3, Bb), 256, DSMEM_BYTES>>>(
        (const __nv_bfloat16*)pW1h, (const __nv_bfloat16*)pW1l,
        (const __nv_bfloat16*)pSh,  (const __nv_bfloat16*)pSl,
        Cc, 0, (size_t)Cc * Cc, 1, (float*)pU1, nullptr, nullptr, nullptr);
    gemm_bsplit<<<dim3(3, 3, Bb), 256, DSMEM_BYTES>>>(
        (const __nv_bfloat16*)pW2h, (const __nv_bfloat16*)pW2l,
        (const __nv_bfloat16*)pSh,  (const __nv_bfloat16*)pSl,
        Cc, 0, (size_t)Cc * Cc, 1, (float*)pU2, nullptr, nullptr, nullptr);

    // 3) attention + fold -> Mh/Ml, mb
    k_attn_fold<<<dim3(HEADS, Bb), 256>>>(w1, b1, w2, b2, w3, b3, temp);

    // 4) out = M_b X_b + mb + x   (B operand = X^T, K-major)
    gemm_bsplit<<<dim3(3, 32, Bb), 256, DSMEM_BYTES>>>(
        (const __nv_bfloat16*)pMh,  (const __nv_bfloat16*)pMl,
        (const __nv_bfloat16*)pXth, (const __nv_bfloat16*)pXtl,
        Cc, (size_t)Cc * Cc, (size_t)Nn * Cc, 2,
        out, nullptr, nullptr, x);
}

// round 4
// speedup vs baseline: 1.8273x; 1.0941x over previous
#include <cuda_runtime.h>
#include <cuda_bf16.h>
#include <math.h>
#include <stdint.h>

#define Bb 16
#define Cc 384
#define Nn 4096
#define HEADS 8
#define CH 48
#define SSZ (Bb*Cc*Cc)
#define WSZ (Cc*Cc)

// ---------------- scratch (device globals; allocation-free) ----------------
__device__ __nv_bfloat16 g_Sh[SSZ], g_Sl[SSZ];     // S bf16 split
__device__ __nv_bfloat16 g_Mh[SSZ], g_Ml[SSZ];     // folded (A+I)W3 + I, split
__device__ __nv_bfloat16 g_W1h[WSZ], g_W1l[WSZ], g_W2h[WSZ], g_W2l[WSZ];
__device__ float g_U1[SSZ], g_U2[SSZ];
__device__ float g_sx[Bb*Cc], g_mb[Bb*Cc];

// ---------------- PTX helpers (sm_80-class only; no 'a'-gated features) ----
__device__ __forceinline__ uint32_t smem_u32(const void* p) {
    uint32_t a;
    asm("{ .reg .u64 t; cvta.to.shared.u64 t, %1; cvt.u32.u64 %0, t; }"
        : "=r"(a) : "l"(p));
    return a;
}
__device__ __forceinline__ void ldsm4(uint32_t* r, uint32_t addr) {
    asm volatile("ldmatrix.sync.aligned.m8n8.x4.shared.b16 {%0,%1,%2,%3}, [%4];"
                 : "=r"(r[0]), "=r"(r[1]), "=r"(r[2]), "=r"(r[3]) : "r"(addr));
}
__device__ __forceinline__ void ldsm4t(uint32_t* r, uint32_t addr) {
    asm volatile("ldmatrix.sync.aligned.m8n8.x4.trans.shared.b16 {%0,%1,%2,%3}, [%4];"
                 : "=r"(r[0]), "=r"(r[1]), "=r"(r[2]), "=r"(r[3]) : "r"(addr));
}
__device__ __forceinline__ void mma16816(float* c, const uint32_t* a, const uint32_t* b) {
    asm volatile(
        "mma.sync.aligned.m16n8k16.row.col.f32.bf16.bf16.f32 "
        "{%0,%1,%2,%3}, {%4,%5,%6,%7}, {%8,%9}, {%0,%1,%2,%3};"
        : "+f"(c[0]), "+f"(c[1]), "+f"(c[2]), "+f"(c[3])
        : "r"(a[0]), "r"(a[1]), "r"(a[2]), "r"(a[3]), "r"(b[0]), "r"(b[1]));
}

// smem geometry
#define SROW80   80        // K-major tile row pitch bytes (32 bf16 + 8 pad)
#define ATILE    10240     // 128 * 80
#define STAGE_NT 40960     // Ah,Al,Bh,Bl
#define BPITCH   272       // trans B-tile row pitch bytes (128 bf16 + 8 pad)
#define BTILE    8704      // 32 * 272
#define STAGE_TR 37888     // 2*ATILE + 2*BTILE
#define DSMEM_NT 81920     // 2 stages (>= 128*132*4 = 67584 epilogue)
#define DSMEM_TR 75776

// ---------------------------------------------------------------------------
// shared compute bodies (warp tile 32x64; acc[2][8][4])
// ---------------------------------------------------------------------------
__device__ __forceinline__ void compute_nt(uint32_t smb, int wm, int wn, int lane,
                                           float acc[2][8][4]) {
    const int grp = lane >> 3, lr = lane & 7;
#pragma unroll
    for (int ks = 0; ks < 2; ks++) {
        const int kc = ks * 16;
        uint32_t ah[2][4], al[2][4];
#pragma unroll
        for (int ti = 0; ti < 2; ti++) {
            int row = wm * 32 + ti * 16 + lr + (grp & 1) * 8;
            int col = kc + (grp >> 1) * 8;
            uint32_t addr = smb + row * SROW80 + col * 2;
            ldsm4(ah[ti], addr);
            ldsm4(al[ti], addr + ATILE);
        }
#pragma unroll
        for (int half = 0; half < 2; half++) {
            uint32_t bhf[4][2], blf[4][2];
#pragma unroll
            for (int p = 0; p < 2; p++) {
                int nrow = wn * 64 + half * 32 + p * 16 + (grp >> 1) * 8 + lr;
                int col = kc + (grp & 1) * 8;
                uint32_t addr = smb + 2 * ATILE + nrow * SROW80 + col * 2;
                uint32_t r4[4];
                ldsm4(r4, addr);
                bhf[2*p][0] = r4[0]; bhf[2*p][1] = r4[1];
                bhf[2*p+1][0] = r4[2]; bhf[2*p+1][1] = r4[3];
                ldsm4(r4, addr + ATILE);
                blf[2*p][0] = r4[0]; blf[2*p][1] = r4[1];
                blf[2*p+1][0] = r4[2]; blf[2*p+1][1] = r4[3];
            }
#pragma unroll
            for (int ti = 0; ti < 2; ti++)
#pragma unroll
                for (int tj = 0; tj < 4; tj++) {
                    float* c = acc[ti][half * 4 + tj];
                    mma16816(c, ah[ti], bhf[tj]);
                    mma16816(c, ah[ti], blf[tj]);
                    mma16816(c, al[ti], bhf[tj]);
                }
        }
    }
}

__device__ __forceinline__ void compute_tr(uint32_t smbA, uint32_t smbB,
                                           int wm, int wn, int lane,
                                           float acc[2][8][4]) {
    const int grp = lane >> 3, lr = lane & 7;
#pragma unroll
    for (int ks = 0; ks < 2; ks++) {
        const int kc = ks * 16;
        uint32_t ah[2][4], al[2][4];
#pragma unroll
        for (int ti = 0; ti < 2; ti++) {
            int row = wm * 32 + ti * 16 + lr + (grp & 1) * 8;
            int col = kc + (grp >> 1) * 8;
            uint32_t addr = smbA + row * SROW80 + col * 2;
            ldsm4(ah[ti], addr);
            ldsm4(al[ti], addr + ATILE);
        }
#pragma unroll
        for (int half = 0; half < 2; half++) {
            uint32_t bhf[4][2], blf[4][2];
#pragma unroll
            for (int p = 0; p < 2; p++) {
                int krow = kc + ((lane >> 3) & 1) * 8 + (lane & 7);
                int ncol = wn * 64 + half * 32 + p * 16 + (lane >> 4) * 8;
                uint32_t addr = smbB + krow * BPITCH + ncol * 2;
                uint32_t r4[4];
                ldsm4t(r4, addr);
                bhf[2*p][0] = r4[0]; bhf[2*p][1] = r4[1];
                bhf[2*p+1][0] = r4[2]; bhf[2*p+1][1] = r4[3];
                ldsm4t(r4, addr + BTILE);
                blf[2*p][0] = r4[0]; blf[2*p][1] = r4[1];
                blf[2*p+1][0] = r4[2]; blf[2*p+1][1] = r4[3];
            }
#pragma unroll
            for (int ti = 0; ti < 2; ti++)
#pragma unroll
                for (int tj = 0; tj < 4; tj++) {
                    float* c = acc[ti][half * 4 + tj];
                    mma16816(c, ah[ti], bhf[tj]);
                    mma16816(c, ah[ti], blf[tj]);
                    mma16816(c, al[ti], bhf[tj]);
                }
        }
    }
}

// split one float4 into bf16 hi/lo pairs and store (8B each)
__device__ __forceinline__ void sts_split4(char* ph, char* pl, float4 f) {
    __nv_bfloat162 h01 = __floats2bfloat162_rn(f.x, f.y);
    __nv_bfloat162 h23 = __floats2bfloat162_rn(f.z, f.w);
    __nv_bfloat162 l01 = __floats2bfloat162_rn(f.x - __bfloat162float(h01.x),
                                               f.y - __bfloat162float(h01.y));
    __nv_bfloat162 l23 = __floats2bfloat162_rn(f.z - __bfloat162float(h23.x),
                                               f.w - __bfloat162float(h23.y));
    uint2 hh, ll;
    hh.x = *(uint32_t*)&h01; hh.y = *(uint32_t*)&h23;
    ll.x = *(uint32_t*)&l01; ll.y = *(uint32_t*)&l23;
    *(uint2*)ph = hh;
    *(uint2*)pl = ll;
}

// ---------------------------------------------------------------------------
// row sums sx[b,c] = sum_n x[b,c,n]
// ---------------------------------------------------------------------------
__global__ void __launch_bounds__(256) k_rowsum(const float* __restrict__ x) {
    int row = blockIdx.x;
    const float4* xr = (const float4*)(x + (size_t)row * Nn);
    float s = 0.f;
    for (int i = threadIdx.x; i < Nn / 4; i += 256) {
        float4 v = xr[i];
        s += (v.x + v.y) + (v.z + v.w);
    }
    __shared__ float red[256];
    red[threadIdx.x] = s;
    __syncthreads();
    for (int o = 128; o; o >>= 1) {
        if (threadIdx.x < o) red[threadIdx.x] += red[threadIdx.x + o];
        __syncthreads();
    }
    if (threadIdx.x == 0) g_sx[row] = red[0];
}

// elementwise hi/lo split (weights)
__global__ void __launch_bounds__(256) k_split(const float* __restrict__ s,
                                               __nv_bfloat16* __restrict__ h,
                                               __nv_bfloat16* __restrict__ l, int n) {
    int i = blockIdx.x * 256 + threadIdx.x;
    if (i < n) {
        float v = s[i];
        __nv_bfloat16 hv = __float2bfloat16(v);
        h[i] = hv;
        l[i] = __float2bfloat16(v - __bfloat162float(hv));
    }
}

// ---------------------------------------------------------------------------
// S GEMM: S_b = X_b X_b^T.  fp32 in, inline bf16 split, 3-pass compensated.
// grid (3,3,16). Writes Sh/Sl.
// ---------------------------------------------------------------------------
__global__ void __launch_bounds__(256) gemm_S(const float* __restrict__ x) {
    extern __shared__ char dsm[];
    const int tid = threadIdx.x, lane = tid & 31, wid = tid >> 5;
    const int wm = wid & 3, wn = wid >> 2;
    const int bx = blockIdx.x, by = blockIdx.y, bz = blockIdx.z;
    const uint32_t smb = smem_u32(dsm);

    const float* Ax = x + ((size_t)bz * Cc + bx * 128) * Nn;
    const float* Bx = x + ((size_t)bz * Cc + by * 128) * Nn;

    int rw[4], qq[4];
#pragma unroll
    for (int j = 0; j < 4; j++) { int u = tid + 256 * j; rw[j] = u >> 3; qq[j] = u & 7; }

    float acc[2][8][4];
#pragma unroll
    for (int i = 0; i < 2; i++)
#pragma unroll
        for (int j = 0; j < 8; j++)
#pragma unroll
            for (int q = 0; q < 4; q++) acc[i][j][q] = 0.f;

    float4 vA[4], vB[4];
#pragma unroll
    for (int j = 0; j < 4; j++) {
        vA[j] = *(const float4*)(Ax + (size_t)rw[j] * Nn + qq[j] * 4);
        vB[j] = *(const float4*)(Bx + (size_t)rw[j] * Nn + qq[j] * 4);
    }
    {
        char* base = dsm;
#pragma unroll
        for (int j = 0; j < 4; j++) {
            int off = rw[j] * SROW80 + qq[j] * 8;
            sts_split4(base + off, base + ATILE + off, vA[j]);
            sts_split4(base + 2 * ATILE + off, base + 3 * ATILE + off, vB[j]);
        }
    }
#pragma unroll
    for (int j = 0; j < 4; j++) {
        vA[j] = *(const float4*)(Ax + (size_t)rw[j] * Nn + 32 + qq[j] * 4);
        vB[j] = *(const float4*)(Bx + (size_t)rw[j] * Nn + 32 + qq[j] * 4);
    }
    __syncthreads();

    const int nch = Nn / 32;   // 128
    for (int i = 0; i < nch; i++) {
        if (i + 1 < nch) {
            char* base = dsm + ((i + 1) & 1) * STAGE_NT;
#pragma unroll
            for (int j = 0; j < 4; j++) {
                int off = rw[j] * SROW80 + qq[j] * 8;
                sts_split4(base + off, base + ATILE + off, vA[j]);
                sts_split4(base + 2 * ATILE + off, base + 3 * ATILE + off, vB[j]);
            }
        }
        if (i + 2 < nch) {
            int k0 = (i + 2) * 32;
#pragma unroll
            for (int j = 0; j < 4; j++) {
                vA[j] = *(const float4*)(Ax + (size_t)rw[j] * Nn + k0 + qq[j] * 4);
                vB[j] = *(const float4*)(Bx + (size_t)rw[j] * Nn + k0 + qq[j] * 4);
            }
        }
        compute_nt(smb + (i & 1) * STAGE_NT, wm, wn, lane, acc);
        __syncthreads();
    }

    // epilogue: acc -> smem fp32 -> split bf16 write
    float* sC = (float*)dsm;
#pragma unroll
    for (int ti = 0; ti < 2; ti++)
#pragma unroll
        for (int j = 0; j < 8; j++) {
            int row0 = wm * 32 + ti * 16 + (lane >> 2);
            int col  = wn * 64 + j * 8 + (lane & 3) * 2;
            *(float2*)(sC + row0 * 132 + col)       = make_float2(acc[ti][j][0], acc[ti][j][1]);
            *(float2*)(sC + (row0 + 8) * 132 + col) = make_float2(acc[ti][j][2], acc[ti][j][3]);
        }
    __syncthreads();

    const int r0 = tid >> 1, half = tid & 1;
    const float* src = sC + r0 * 132 + half * 64;
    const int grow = bx * 128 + r0;
    const int gcol = by * 128 + half * 64;
    size_t base = ((size_t)bz * Cc + grow) * Cc + gcol;
#pragma unroll
    for (int j = 0; j < 64; j += 2) {
        float v0 = src[j], v1 = src[j + 1];
        __nv_bfloat162 h2 = __floats2bfloat162_rn(v0, v1);
        *(__nv_bfloat162*)(g_Sh + base + j) = h2;
        float l0 = v0 - __bfloat162float(h2.x);
        float l1 = v1 - __bfloat162float(h2.y);
        *(__nv_bfloat162*)(g_Sl + base + j) = __floats2bfloat162_rn(l0, l1);
    }
}

// ---------------------------------------------------------------------------
// U GEMM: U = W @ S (NT, S symmetric). bf16 split operands, writes fp32.
// grid (3,3,16). A batch-invariant, B stride Cc*Cc.
// ---------------------------------------------------------------------------
__global__ void __launch_bounds__(256) gemm_U(
    const __nv_bfloat16* __restrict__ Ah_, const __nv_bfloat16* __restrict__ Al_,
    float* __restrict__ Cf)
{
    extern __shared__ char dsm[];
    const int tid = threadIdx.x, lane = tid & 31, wid = tid >> 5;
    const int wm = wid & 3, wn = wid >> 2;
    const int bx = blockIdx.x, by = blockIdx.y, bz = blockIdx.z;
    const uint32_t smb = smem_u32(dsm);

    const __nv_bfloat16* ptr[4];
    ptr[0] = Ah_ + (size_t)bx * 128 * Cc;
    ptr[1] = Al_ + (size_t)bx * 128 * Cc;
    ptr[2] = g_Sh + (size_t)bz * Cc * Cc + (size_t)by * 128 * Cc;
    ptr[3] = g_Sl + (size_t)bz * Cc * Cc + (size_t)by * 128 * Cc;

    int frow[2], fq[2];
#pragma unroll
    for (int j = 0; j < 2; j++) { int u = tid + 256 * j; frow[j] = u >> 2; fq[j] = u & 3; }

    float acc[2][8][4];
#pragma unroll
    for (int i = 0; i < 2; i++)
#pragma unroll
        for (int j = 0; j < 8; j++)
#pragma unroll
            for (int q = 0; q < 4; q++) acc[i][j][q] = 0.f;

    uint4 v[4][2];
#pragma unroll
    for (int m = 0; m < 4; m++)
#pragma unroll
        for (int j = 0; j < 2; j++)
            v[m][j] = *(const uint4*)(ptr[m] + (size_t)frow[j] * Cc + fq[j] * 8);
    {
#pragma unroll
        for (int m = 0; m < 4; m++)
#pragma unroll
            for (int j = 0; j < 2; j++)
                *(uint4*)(dsm + m * ATILE + frow[j] * SROW80 + fq[j] * 16) = v[m][j];
    }
#pragma unroll
    for (int m = 0; m < 4; m++)
#pragma unroll
        for (int j = 0; j < 2; j++)
            v[m][j] = *(const uint4*)(ptr[m] + (size_t)frow[j] * Cc + 32 + fq[j] * 8);
    __syncthreads();

    const int nch = Cc / 32;   // 12
    for (int i = 0; i < nch; i++) {
        if (i + 1 < nch) {
            char* base = dsm + ((i + 1) & 1) * STAGE_NT;
#pragma unroll
            for (int m = 0; m < 4; m++)
#pragma unroll
                for (int j = 0; j < 2; j++)
                    *(uint4*)(base + m * ATILE + frow[j] * SROW80 + fq[j] * 16) = v[m][j];
        }
        if (i + 2 < nch) {
            int k0 = (i + 2) * 32;
#pragma unroll
            for (int m = 0; m < 4; m++)
#pragma unroll
                for (int j = 0; j < 2; j++)
                    v[m][j] = *(const uint4*)(ptr[m] + (size_t)frow[j] * Cc + k0 + fq[j] * 8);
        }
        compute_nt(smb + (i & 1) * STAGE_NT, wm, wn, lane, acc);
        __syncthreads();
    }

    float* sC = (float*)dsm;
#pragma unroll
    for (int ti = 0; ti < 2; ti++)
#pragma unroll
        for (int j = 0; j < 8; j++) {
            int row0 = wm * 32 + ti * 16 + (lane >> 2);
            int col  = wn * 64 + j * 8 + (lane & 3) * 2;
            *(float2*)(sC + row0 * 132 + col)       = make_float2(acc[ti][j][0], acc[ti][j][1]);
            *(float2*)(sC + (row0 + 8) * 132 + col) = make_float2(acc[ti][j][2], acc[ti][j][3]);
        }
    __syncthreads();

    const int r0 = tid >> 1, half = tid & 1;
    const float* src = sC + r0 * 132 + half * 64;
    size_t base = ((size_t)bz * Cc + bx * 128 + r0) * Cc + by * 128 + half * 64;
#pragma unroll
    for (int j = 0; j < 64; j += 4)
        *(float4*)(Cf + base + j) = *(const float4*)(src + j);
}

// ---------------------------------------------------------------------------
// out GEMM: out = (M+I) X + mb.  A = Mh/Ml (K-major bf16), B = x fp32
// split inline into [k][n] smem consumed via ldmatrix.trans.
// grid (3,32,16).
// ---------------------------------------------------------------------------
__global__ void __launch_bounds__(256) gemm_out(const float* __restrict__ x,
                                                float* __restrict__ out)
{
    extern __shared__ char dsm[];
    const int tid = threadIdx.x, lane = tid & 31, wid = tid >> 5;
    const int wm = wid & 3, wn = wid >> 2;
    const int bx = blockIdx.x, by = blockIdx.y, bz = blockIdx.z;
    const uint32_t smb = smem_u32(dsm);

    const __nv_bfloat16* pA[2];
    pA[0] = g_Mh + (size_t)bz * Cc * Cc + (size_t)bx * 128 * Cc;
    pA[1] = g_Ml + (size_t)bz * Cc * Cc + (size_t)bx * 128 * Cc;
    const float* Bx = x + (size_t)bz * Cc * Nn + by * 128;

    int frow[2], fq[2];
#pragma unroll
    for (int j = 0; j < 2; j++) { int u = tid + 256 * j; frow[j] = u >> 2; fq[j] = u & 3; }
    int brw[4], bq[4];
#pragma unroll
    for (int j = 0; j < 4; j++) { int u = tid + 256 * j; brw[j] = u >> 5; bq[j] = u & 31; }

    float acc[2][8][4];
#pragma unroll
    for (int i = 0; i < 2; i++)
#pragma unroll
        for (int j = 0; j < 8; j++)
#pragma unroll
            for (int q = 0; q < 4; q++) acc[i][j][q] = 0.f;

    uint4 vA[2][2];
    float4 vB[4];
#pragma unroll
    for (int m = 0; m < 2; m++)
#pragma unroll
        for (int j = 0; j < 2; j++)
            vA[m][j] = *(const uint4*)(pA[m] + (size_t)frow[j] * Cc + fq[j] * 8);
#pragma unroll
    for (int j = 0; j < 4; j++)
        vB[j] = *(const float4*)(Bx + (size_t)brw[j] * Nn + bq[j] * 4);
    {
        char* base = dsm;
#pragma unroll
        for (int m = 0; m < 2; m++)
#pragma unroll
            for (int j = 0; j < 2; j++)
                *(uint4*)(base + m * ATILE + frow[j] * SROW80 + fq[j] * 16) = vA[m][j];
#pragma unroll
        for (int j = 0; j < 4; j++) {
            int off = brw[j] * BPITCH + bq[j] * 8;
            sts_split4(base + 2 * ATILE + off, base + 2 * ATILE + BTILE + off, vB[j]);
        }
    }
#pragma unroll
    for (int m = 0; m < 2; m++)
#pragma unroll
        for (int j = 0; j < 2; j++)
            vA[m][j] = *(const uint4*)(pA[m] + (size_t)frow[j] * Cc + 32 + fq[j] * 8);
#pragma unroll
    for (int j = 0; j < 4; j++)
        vB[j] = *(const float4*)(Bx + (size_t)(32 + brw[j]) * Nn + bq[j] * 4);
    __syncthreads();

    const int nch = Cc / 32;   // 12
    for (int i = 0; i < nch; i++) {
        if (i + 1 < nch) {
            char* base = dsm + ((i + 1) & 1) * STAGE_TR;
#pragma unroll
            for (int m = 0; m < 2; m++)
#pragma unroll
                for (int j = 0; j < 2; j++)
                    *(uint4*)(base + m * ATILE + frow[j] * SROW80 + fq[j] * 16) = vA[m][j];
#pragma unroll
            for (int j = 0; j < 4; j++) {
                int off = brw[j] * BPITCH + bq[j] * 8;
                sts_split4(base + 2 * ATILE + off, base + 2 * ATILE + BTILE + off, vB[j]);
            }
        }
        if (i + 2 < nch) {
            int k0 = (i + 2) * 32;
#pragma unroll
            for (int m = 0; m < 2; m++)
#pragma unroll
                for (int j = 0; j < 2; j++)
                    vA[m][j] = *(const uint4*)(pA[m] + (size_t)frow[j] * Cc + k0 + fq[j] * 8);
#pragma unroll
            for (int j = 0; j < 4; j++)
                vB[j] = *(const float4*)(Bx + (size_t)(k0 + brw[j]) * Nn + bq[j] * 4);
        }
        uint32_t st = smb + (i & 1) * STAGE_TR;
        compute_tr(st, st + 2 * ATILE, wm, wn, lane, acc);
        __syncthreads();
    }

    float* sC = (float*)dsm;
#pragma unroll
    for (int ti = 0; ti < 2; ti++)
#pragma unroll
        for (int j = 0; j < 8; j++) {
            int row0 = wm * 32 + ti * 16 + (lane >> 2);
            int col  = wn * 64 + j * 8 + (lane & 3) * 2;
            *(float2*)(sC + row0 * 132 + col)       = make_float2(acc[ti][j][0], acc[ti][j][1]);
            *(float2*)(sC + (row0 + 8) * 132 + col) = make_float2(acc[ti][j][2], acc[ti][j][3]);
        }
    __syncthreads();

    const int r0 = tid >> 1, half = tid & 1;
    const float* src = sC + r0 * 132 + half * 64;
    const int grow = bx * 128 + r0;
    float bias = g_mb[bz * Cc + grow];
    size_t base = ((size_t)bz * Cc + grow) * (size_t)Nn + by * 128 + half * 64;
#pragma unroll
    for (int j = 0; j < 64; j += 4) {
        float4 v4 = *(const float4*)(src + j);
        *(float4*)(out + base + j) = make_float4(v4.x + bias, v4.y + bias,
                                                 v4.z + bias, v4.w + bias);
    }
}

// ---------------------------------------------------------------------------
// attention + fold: M = (A+I)W3 + I (full identity folded in), mb = (A+I)b3
// ---------------------------------------------------------------------------
__global__ void __launch_bounds__(256) k_attn_fold(
    const float* __restrict__ w1, const float* __restrict__ b1,
    const float* __restrict__ w2, const float* __restrict__ b2,
    const float* __restrict__ w3, const float* __restrict__ b3,
    const float* __restrict__ temp)
{
    const int h = blockIdx.x, b = blockIdx.y;
    const int tid = threadIdx.x;
    const int warp = tid >> 5, lane = tid & 31;

    __shared__ float sU[CH * 65];
    __shared__ float sW[CH * 65];
    __shared__ float sAa[CH * 49];
    __shared__ float sNq[CH], sNk[CH], sP1[CH], sP2[CH];
    __shared__ float sB1[CH], sB2[CH], sB3[CH];

    const float* U1  = &g_U1[(size_t)b * Cc * Cc + (size_t)h * CH * Cc];
    const float* U2  = &g_U2[(size_t)b * Cc * Cc + (size_t)h * CH * Cc];
    const float* w1h = w1 + (size_t)h * CH * Cc;
    const float* w2h = w2 + (size_t)h * CH * Cc;
    const float* w3h = w3 + (size_t)h * CH * Cc;
    const float* sx  = &g_sx[b * Cc];

    if (tid < CH) {
        sB1[tid] = b1[h * CH + tid];
        sB2[tid] = b2[h * CH + tid];
        sB3[tid] = b3[h * CH + tid];
    }

    float acc[9];
#pragma unroll
    for (int e = 0; e < 9; e++) acc[e] = 0.f;

    for (int k0 = 0; k0 < Cc; k0 += 64) {
        __syncthreads();
        for (int i = tid; i < CH * 64; i += 256) {
            int c = i >> 6, kk = i & 63;
            sU[c * 65 + kk] = U1[c * Cc + k0 + kk];
            sW[c * 65 + kk] = w2h[c * Cc + k0 + kk];
        }
        __syncthreads();
#pragma unroll
        for (int e = 0; e < 9; e++) {
            int idx = tid + 256 * e;
            int c = idx / CH, d = idx - c * CH;
            float s = 0.f;
#pragma unroll 16
            for (int kk = 0; kk < 64; kk++)
                s += sU[c * 65 + kk] * sW[d * 65 + kk];
            acc[e] += s;
        }
    }

    __syncthreads();
    for (int c = warp * 6; c < warp * 6 + 6; c++) {
        float aq = 0.f, ak = 0.f, p1 = 0.f, p2 = 0.f;
        for (int k = lane; k < Cc; k += 32) {
            float w1v = w1h[c * Cc + k];
            float w2v = w2h[c * Cc + k];
            aq += U1[c * Cc + k] * w1v;
            ak += U2[c * Cc + k] * w2v;
            float sv = sx[k];
            p1 += w1v * sv;
            p2 += w2v * sv;
        }
#pragma unroll
        for (int o = 16; o; o >>= 1) {
            aq += __shfl_xor_sync(0xffffffffu, aq, o);
            ak += __shfl_xor_sync(0xffffffffu, ak, o);
            p1 += __shfl_xor_sync(0xffffffffu, p1, o);
            p2 += __shfl_xor_sync(0xffffffffu, p2, o);
        }
        if (lane == 0) { sNq[c] = aq; sNk[c] = ak; sP1[c] = p1; sP2[c] = p2; }
    }
    __syncthreads();

    const float tH = temp[h];
#pragma unroll
    for (int e = 0; e < 9; e++) {
        int idx = tid + 256 * e;
        int c = idx / CH, d = idx - c * CH;
        float b1c = sB1[c], b2d = sB2[d];
        float nq = sqrtf(fmaxf(sNq[c] + 2.f * b1c * sP1[c] + 4096.f * b1c * b1c, 0.f));
        float nk = sqrtf(fmaxf(sNk[d] + 2.f * b2d * sP2[d] + 4096.f * b2d * b2d, 0.f));
        float g  = acc[e] + b1c * sP2[d] + b2d * sP1[c] + 4096.f * b1c * b2d;
        sAa[c * 49 + d] = g / (fmaxf(nq, 1e-12f) * fmaxf(nk, 1e-12f)) * tH;
    }
    __syncthreads();

    for (int c = warp * 6; c < warp * 6 + 6; c++) {
        float a0 = sAa[c * 49 + lane];
        float a1 = (lane < 16) ? sAa[c * 49 + 32 + lane] : -3.402823466e38f;
        float m = fmaxf(a0, a1);
#pragma unroll
        for (int o = 16; o; o >>= 1) m = fmaxf(m, __shfl_xor_sync(0xffffffffu, m, o));
        float e0 = __expf(a0 - m);
        float e1 = (lane < 16) ? __expf(a1 - m) : 0.f;
        float s = e0 + e1;
#pragma unroll
        for (int o = 16; o; o >>= 1) s += __shfl_xor_sync(0xffffffffu, s, o);
        float inv = 1.f / s;
        sAa[c * 49 + lane] = e0 * inv;
        if (lane < 16) sAa[c * 49 + 32 + lane] = e1 * inv;
    }
    __syncthreads();

    if (tid < CH) {
        float s = sB3[tid];
#pragma unroll 8
        for (int d = 0; d < CH; d++) s += sAa[tid * 49 + d] * sB3[d];
        g_mb[b * Cc + h * CH + tid] = s;
    }

    for (int k0 = 0; k0 < Cc; k0 += 64) {
        __syncthreads();
        for (int i = tid; i < CH * 64; i += 256) {
            int d = i >> 6, kk = i & 63;
            sW[d * 65 + kk] = w3h[d * Cc + k0 + kk];
        }
        __syncthreads();
        for (int i = tid; i < CH * 64; i += 256) {
            int c = i >> 6, kk = i & 63;
            float s = sW[c * 65 + kk];
#pragma unroll 8
            for (int d = 0; d < CH; d++) s += sAa[c * 49 + d] * sW[d * 65 + kk];
            if (h * CH + c == k0 + kk) s += 1.f;      // fold the +x residual in
            size_t idx = (size_t)b * Cc * Cc + (size_t)(h * CH + c) * Cc + k0 + kk;
            __nv_bfloat16 hv = __float2bfloat16(s);
            g_Mh[idx] = hv;
            g_Ml[idx] = __float2bfloat16(s - __bfloat162float(hv));
        }
    }
}

// ---------------------------------------------------------------------------
extern "C" void kernel_launch(void* const* d_in, const int* in_sizes, int n_in,
                              void* d_out, int out_size)
{
    (void)in_sizes; (void)n_in; (void)out_size;
    const float* x    = (const float*)d_in[0];
    const float* w1   = (const float*)d_in[1];
    const float* b1   = (const float*)d_in[2];
    const float* w2   = (const float*)d_in[3];
    const float* b2   = (const float*)d_in[4];
    const float* w3   = (const float*)d_in[5];
    const float* b3   = (const float*)d_in[6];
    const float* temp = (const float*)d_in[7];
    float* out = (float*)d_out;

    cudaFuncSetAttribute(gemm_S,   cudaFuncAttributeMaxDynamicSharedMemorySize, DSMEM_NT);
    cudaFuncSetAttribute(gemm_U,   cudaFuncAttributeMaxDynamicSharedMemorySize, DSMEM_NT);
    cudaFuncSetAttribute(gemm_out, cudaFuncAttributeMaxDynamicSharedMemorySize, DSMEM_TR);

    void *pW1h, *pW1l, *pW2h, *pW2l, *pU1, *pU2;
    cudaGetSymbolAddress(&pW1h, g_W1h); cudaGetSymbolAddress(&pW1l, g_W1l);
    cudaGetSymbolAddress(&pW2h, g_W2h); cudaGetSymbolAddress(&pW2l, g_W2l);
    cudaGetSymbolAddress(&pU1,  g_U1);  cudaGetSymbolAddress(&pU2,  g_U2);

    k_rowsum<<<Bb * Cc, 256>>>(x);
    k_split<<<(WSZ + 255) / 256, 256>>>(w1, (__nv_bfloat16*)pW1h, (__nv_bfloat16*)pW1l, WSZ);
    k_split<<<(WSZ + 255) / 256, 256>>>(w2, (__nv_bfloat16*)pW2h, (__nv_bfloat16*)pW2l, WSZ);

    gemm_S<<<dim3(3, 3, Bb), 256, DSMEM_NT>>>(x);

    gemm_U<<<dim3(3, 3, Bb), 256, DSMEM_NT>>>(
        (const __nv_bfloat16*)pW1h, (const __nv_bfloat16*)pW1l, (float*)pU1);
    gemm_U<<<dim3(3, 3, Bb), 256, DSMEM_NT>>>(
        (const __nv_bfloat16*)pW2h, (const __nv_bfloat16*)pW2l, (float*)pU2);

    k_attn_fold<<<dim3(HEADS, Bb), 256>>>(w1, b1, w2, b2, w3, b3, temp);

    gemm_out<<<dim3(3, 32, Bb), 256, DSMEM_TR>>>(x, out);
}

// round 5
// speedup vs baseline: 1.9054x; 1.0427x over previous
#include <cuda_runtime.h>
#include <cuda_bf16.h>
#include <math.h>
#include <stdint.h>

#define Bb 16
#define Cc 384
#define Nn 4096
#define HEADS 8
#define CH 48
#define SSZ (Bb*Cc*Cc)
#define WSZ (Cc*Cc)

// ---------------- scratch (device globals; allocation-free) ----------------
__device__ __nv_bfloat16 g_Sh[SSZ], g_Sl[SSZ];     // S bf16 split
__device__ __nv_bfloat16 g_Mh[SSZ], g_Ml[SSZ];     // folded (A+I)W3 + I, split
__device__ __nv_bfloat16 g_W1h[WSZ], g_W1l[WSZ], g_W2h[WSZ], g_W2l[WSZ];
__device__ float g_U1[SSZ], g_U2[SSZ];
__device__ float g_Sp[3*Bb*6*16384];               // split-K partial S tiles
__device__ float g_sxp[3*Bb*Cc];                   // split-K partial row sums
__device__ float g_mb[Bb*Cc];

// ---------------- PTX helpers (sm_80-class only; no 'a'-gated features) ----
__device__ __forceinline__ uint32_t smem_u32(const void* p) {
    uint32_t a;
    asm("{ .reg .u64 t; cvta.to.shared.u64 t, %1; cvt.u32.u64 %0, t; }"
        : "=r"(a) : "l"(p));
    return a;
}
__device__ __forceinline__ void ldsm4(uint32_t* r, uint32_t addr) {
    asm volatile("ldmatrix.sync.aligned.m8n8.x4.shared.b16 {%0,%1,%2,%3}, [%4];"
                 : "=r"(r[0]), "=r"(r[1]), "=r"(r[2]), "=r"(r[3]) : "r"(addr));
}
__device__ __forceinline__ void ldsm4t(uint32_t* r, uint32_t addr) {
    asm volatile("ldmatrix.sync.aligned.m8n8.x4.trans.shared.b16 {%0,%1,%2,%3}, [%4];"
                 : "=r"(r[0]), "=r"(r[1]), "=r"(r[2]), "=r"(r[3]) : "r"(addr));
}
__device__ __forceinline__ void mma16816(float* c, const uint32_t* a, const uint32_t* b) {
    asm volatile(
        "mma.sync.aligned.m16n8k16.row.col.f32.bf16.bf16.f32 "
        "{%0,%1,%2,%3}, {%4,%5,%6,%7}, {%8,%9}, {%0,%1,%2,%3};"
        : "+f"(c[0]), "+f"(c[1]), "+f"(c[2]), "+f"(c[3])
        : "r"(a[0]), "r"(a[1]), "r"(a[2]), "r"(a[3]), "r"(b[0]), "r"(b[1]));
}

// smem geometry
#define SROW80   80
#define ATILE    10240     // 128 * 80
#define STAGE_NT 40960     // Ah,Al,Bh,Bl
#define BPITCH   272       // trans B-tile row pitch bytes
#define BTILE    8704      // 32 * 272
#define STAGE_TR 37888
#define DSMEM_NT 81920
#define DSMEM_TR 75776

// ---------------------------------------------------------------------------
// compute bodies (warp tile 32x64; acc[2][8][4])
// ---------------------------------------------------------------------------
__device__ __forceinline__ void compute_nt(uint32_t smb, int wm, int wn, int lane,
                                           float acc[2][8][4]) {
    const int grp = lane >> 3, lr = lane & 7;
#pragma unroll
    for (int ks = 0; ks < 2; ks++) {
        const int kc = ks * 16;
        uint32_t ah[2][4], al[2][4];
#pragma unroll
        for (int ti = 0; ti < 2; ti++) {
            int row = wm * 32 + ti * 16 + lr + (grp & 1) * 8;
            int col = kc + (grp >> 1) * 8;
            uint32_t addr = smb + row * SROW80 + col * 2;
            ldsm4(ah[ti], addr);
            ldsm4(al[ti], addr + ATILE);
        }
#pragma unroll
        for (int half = 0; half < 2; half++) {
            uint32_t bhf[4][2], blf[4][2];
#pragma unroll
            for (int p = 0; p < 2; p++) {
                int nrow = wn * 64 + half * 32 + p * 16 + (grp >> 1) * 8 + lr;
                int col = kc + (grp & 1) * 8;
                uint32_t addr = smb + 2 * ATILE + nrow * SROW80 + col * 2;
                uint32_t r4[4];
                ldsm4(r4, addr);
                bhf[2*p][0] = r4[0]; bhf[2*p][1] = r4[1];
                bhf[2*p+1][0] = r4[2]; bhf[2*p+1][1] = r4[3];
                ldsm4(r4, addr + ATILE);
                blf[2*p][0] = r4[0]; blf[2*p][1] = r4[1];
                blf[2*p+1][0] = r4[2]; blf[2*p+1][1] = r4[3];
            }
#pragma unroll
            for (int ti = 0; ti < 2; ti++)
#pragma unroll
                for (int tj = 0; tj < 4; tj++) {
                    float* c = acc[ti][half * 4 + tj];
                    mma16816(c, ah[ti], bhf[tj]);
                    mma16816(c, ah[ti], blf[tj]);
                    mma16816(c, al[ti], bhf[tj]);
                }
        }
    }
}

__device__ __forceinline__ void compute_tr(uint32_t smbA, uint32_t smbB,
                                           int wm, int wn, int lane,
                                           float acc[2][8][4]) {
    const int grp = lane >> 3, lr = lane & 7;
#pragma unroll
    for (int ks = 0; ks < 2; ks++) {
        const int kc = ks * 16;
        uint32_t ah[2][4], al[2][4];
#pragma unroll
        for (int ti = 0; ti < 2; ti++) {
            int row = wm * 32 + ti * 16 + lr + (grp & 1) * 8;
            int col = kc + (grp >> 1) * 8;
            uint32_t addr = smbA + row * SROW80 + col * 2;
            ldsm4(ah[ti], addr);
            ldsm4(al[ti], addr + ATILE);
        }
#pragma unroll
        for (int half = 0; half < 2; half++) {
            uint32_t bhf[4][2], blf[4][2];
#pragma unroll
            for (int p = 0; p < 2; p++) {
                int krow = kc + ((lane >> 3) & 1) * 8 + (lane & 7);
                int ncol = wn * 64 + half * 32 + p * 16 + (lane >> 4) * 8;
                uint32_t addr = smbB + krow * BPITCH + ncol * 2;
                uint32_t r4[4];
                ldsm4t(r4, addr);
                bhf[2*p][0] = r4[0]; bhf[2*p][1] = r4[1];
                bhf[2*p+1][0] = r4[2]; bhf[2*p+1][1] = r4[3];
                ldsm4t(r4, addr + BTILE);
                blf[2*p][0] = r4[0]; blf[2*p][1] = r4[1];
                blf[2*p+1][0] = r4[2]; blf[2*p+1][1] = r4[3];
            }
#pragma unroll
            for (int ti = 0; ti < 2; ti++)
#pragma unroll
                for (int tj = 0; tj < 4; tj++) {
                    float* c = acc[ti][half * 4 + tj];
                    mma16816(c, ah[ti], bhf[tj]);
                    mma16816(c, ah[ti], blf[tj]);
                    mma16816(c, al[ti], bhf[tj]);
                }
        }
    }
}

__device__ __forceinline__ void sts_split4(char* ph, char* pl, float4 f) {
    __nv_bfloat162 h01 = __floats2bfloat162_rn(f.x, f.y);
    __nv_bfloat162 h23 = __floats2bfloat162_rn(f.z, f.w);
    __nv_bfloat162 l01 = __floats2bfloat162_rn(f.x - __bfloat162float(h01.x),
                                               f.y - __bfloat162float(h01.y));
    __nv_bfloat162 l23 = __floats2bfloat162_rn(f.z - __bfloat162float(h23.x),
                                               f.w - __bfloat162float(h23.y));
    uint2 hh, ll;
    hh.x = *(uint32_t*)&h01; hh.y = *(uint32_t*)&h23;
    ll.x = *(uint32_t*)&l01; ll.y = *(uint32_t*)&l23;
    *(uint2*)ph = hh;
    *(uint2*)pl = ll;
}

// elementwise hi/lo split (weights)
__global__ void __launch_bounds__(256) k_split(const float* __restrict__ s,
                                               __nv_bfloat16* __restrict__ h,
                                               __nv_bfloat16* __restrict__ l, int n) {
    int i = blockIdx.x * 256 + threadIdx.x;
    if (i < n) {
        float v = s[i];
        __nv_bfloat16 hv = __float2bfloat16(v);
        h[i] = hv;
        l[i] = __float2bfloat16(v - __bfloat162float(hv));
    }
}

// ---------------------------------------------------------------------------
// S GEMM, triangle + split-K=3: partial S tile -> g_Sp[kz][bz][pair].
// Diagonal pairs also accumulate partial row sums of x -> g_sxp.
// grid (6 pairs, 3 kz, 16 batch)
// ---------------------------------------------------------------------------
__global__ void __launch_bounds__(256) gemm_S(const float* __restrict__ x) {
    extern __shared__ char dsm[];
    const int pxl[6] = {0,0,0,1,1,2}, pyl[6] = {0,1,2,1,2,2};
    const int tid = threadIdx.x, lane = tid & 31, wid = tid >> 5;
    const int wm = wid & 3, wn = wid >> 2;
    const int pair = blockIdx.x, kz = blockIdx.y, bz = blockIdx.z;
    const int bx = pxl[pair], by = pyl[pair];
    const bool diag = (bx == by);
    const int c0 = (kz == 0) ? 0 : (kz == 1 ? 43 : 86);
    const int c1 = (kz == 0) ? 43 : (kz == 1 ? 86 : 128);
    const int nch = c1 - c0;
    const uint32_t smb = smem_u32(dsm);

    const float* Ax = x + ((size_t)bz * Cc + bx * 128) * Nn + c0 * 32;
    const float* Bx = x + ((size_t)bz * Cc + by * 128) * Nn + c0 * 32;

    int rw[4], qq[4];
#pragma unroll
    for (int j = 0; j < 4; j++) { int u = tid + 256 * j; rw[j] = u >> 3; qq[j] = u & 7; }

    float acc[2][8][4];
#pragma unroll
    for (int i = 0; i < 2; i++)
#pragma unroll
        for (int j = 0; j < 8; j++)
#pragma unroll
            for (int q = 0; q < 4; q++) acc[i][j][q] = 0.f;

    float rsum[4] = {0.f, 0.f, 0.f, 0.f};

    float4 vA[4], vB[4];
#pragma unroll
    for (int j = 0; j < 4; j++) {
        vA[j] = *(const float4*)(Ax + (size_t)rw[j] * Nn + qq[j] * 4);
        vB[j] = *(const float4*)(Bx + (size_t)rw[j] * Nn + qq[j] * 4);
        if (diag) rsum[j] += (vA[j].x + vA[j].y) + (vA[j].z + vA[j].w);
    }
    {
        char* base = dsm;
#pragma unroll
        for (int j = 0; j < 4; j++) {
            int off = rw[j] * SROW80 + qq[j] * 8;
            sts_split4(base + off, base + ATILE + off, vA[j]);
            sts_split4(base + 2 * ATILE + off, base + 3 * ATILE + off, vB[j]);
        }
    }
#pragma unroll
    for (int j = 0; j < 4; j++) {
        vA[j] = *(const float4*)(Ax + (size_t)rw[j] * Nn + 32 + qq[j] * 4);
        vB[j] = *(const float4*)(Bx + (size_t)rw[j] * Nn + 32 + qq[j] * 4);
        if (diag) rsum[j] += (vA[j].x + vA[j].y) + (vA[j].z + vA[j].w);
    }
    __syncthreads();

    for (int i = 0; i < nch; i++) {
        if (i + 1 < nch) {
            char* base = dsm + ((i + 1) & 1) * STAGE_NT;
#pragma unroll
            for (int j = 0; j < 4; j++) {
                int off = rw[j] * SROW80 + qq[j] * 8;
                sts_split4(base + off, base + ATILE + off, vA[j]);
                sts_split4(base + 2 * ATILE + off, base + 3 * ATILE + off, vB[j]);
            }
        }
        if (i + 2 < nch) {
            int k0 = (i + 2) * 32;
#pragma unroll
            for (int j = 0; j < 4; j++) {
                vA[j] = *(const float4*)(Ax + (size_t)rw[j] * Nn + k0 + qq[j] * 4);
                vB[j] = *(const float4*)(Bx + (size_t)rw[j] * Nn + k0 + qq[j] * 4);
                if (diag) rsum[j] += (vA[j].x + vA[j].y) + (vA[j].z + vA[j].w);
            }
        }
        compute_nt(smb + (i & 1) * STAGE_NT, wm, wn, lane, acc);
        __syncthreads();
    }

    // row-sum partials (diagonal pairs cover all rows across bx)
    if (diag) {
#pragma unroll
        for (int j = 0; j < 4; j++) {
            float s = rsum[j];
            s += __shfl_xor_sync(0xffffffffu, s, 1);
            s += __shfl_xor_sync(0xffffffffu, s, 2);
            s += __shfl_xor_sync(0xffffffffu, s, 4);
            if (qq[j] == 0)
                g_sxp[((size_t)kz * Bb + bz) * Cc + bx * 128 + rw[j]] = s;
        }
    }

    // epilogue: acc -> smem fp32 -> partial tile (fp32)
    float* sC = (float*)dsm;
#pragma unroll
    for (int ti = 0; ti < 2; ti++)
#pragma unroll
        for (int j = 0; j < 8; j++) {
            int row0 = wm * 32 + ti * 16 + (lane >> 2);
            int col  = wn * 64 + j * 8 + (lane & 3) * 2;
            *(float2*)(sC + row0 * 132 + col)       = make_float2(acc[ti][j][0], acc[ti][j][1]);
            *(float2*)(sC + (row0 + 8) * 132 + col) = make_float2(acc[ti][j][2], acc[ti][j][3]);
        }
    __syncthreads();

    float* outp = g_Sp + (((size_t)kz * Bb + bz) * 6 + pair) * 16384;
    const int r0 = tid >> 1, half = tid & 1;
    const float* src = sC + r0 * 132 + half * 64;
#pragma unroll
    for (int j = 0; j < 64; j += 4)
        *(float4*)(outp + r0 * 128 + half * 64 + j) = *(const float4*)(src + j);
}

// ---------------------------------------------------------------------------
// S reduce: sum 3 partials, bf16 split, write tile and (off-diag) transpose.
// grid (16 subtiles, 6 pairs, 16 batch), 256 threads.
// ---------------------------------------------------------------------------
__global__ void __launch_bounds__(256) k_Sreduce() {
    __shared__ float t[32][33];
    const int pxl[6] = {0,0,0,1,1,2}, pyl[6] = {0,1,2,1,2,2};
    const int sub = blockIdx.x, pair = blockIdx.y, bz = blockIdx.z;
    const int px = pxl[pair], py = pyl[pair];
    const int si = sub >> 2, sj = sub & 3;
    const int cc = threadIdx.x & 31, rb = threadIdx.x >> 5;

    const size_t stride = (size_t)Bb * 6 * 16384;
    const float* p0 = g_Sp + ((size_t)bz * 6 + pair) * 16384;
    const float* p1 = p0 + stride;
    const float* p2 = p0 + 2 * stride;
    const size_t gb = (size_t)bz * Cc * Cc;

#pragma unroll
    for (int r = 0; r < 4; r++) {
        int rr = rb + r * 8;
        int li = (si * 32 + rr) * 128 + sj * 32 + cc;
        float s = p0[li] + p1[li] + p2[li];
        t[rr][cc] = s;
        __nv_bfloat16 hv = __float2bfloat16(s);
        size_t o = gb + (size_t)(px * 128 + si * 32 + rr) * Cc + py * 128 + sj * 32 + cc;
        g_Sh[o] = hv;
        g_Sl[o] = __float2bfloat16(s - __bfloat162float(hv));
    }
    if (px == py) return;
    __syncthreads();
#pragma unroll
    for (int r = 0; r < 4; r++) {
        int rr = rb + r * 8;
        float s = t[cc][rr];
        __nv_bfloat16 hv = __float2bfloat16(s);
        size_t o = gb + (size_t)(py * 128 + sj * 32 + rr) * Cc + px * 128 + si * 32 + cc;
        g_Sh[o] = hv;
        g_Sl[o] = __float2bfloat16(s - __bfloat162float(hv));
    }
}

// ---------------------------------------------------------------------------
// U GEMM (fused U1+U2): U = W @ S (NT, S symmetric). grid (6,3,16).
// ---------------------------------------------------------------------------
__global__ void __launch_bounds__(256) gemm_U() {
    extern __shared__ char dsm[];
    const int tid = threadIdx.x, lane = tid & 31, wid = tid >> 5;
    const int wm = wid & 3, wn = wid >> 2;
    const int sel = blockIdx.x >= 3;
    const int bx = blockIdx.x - (sel ? 3 : 0);
    const int by = blockIdx.y, bz = blockIdx.z;
    const uint32_t smb = smem_u32(dsm);

    const __nv_bfloat16* ptr[4];
    ptr[0] = (sel ? g_W2h : g_W1h) + (size_t)bx * 128 * Cc;
    ptr[1] = (sel ? g_W2l : g_W1l) + (size_t)bx * 128 * Cc;
    ptr[2] = g_Sh + (size_t)bz * Cc * Cc + (size_t)by * 128 * Cc;
    ptr[3] = g_Sl + (size_t)bz * Cc * Cc + (size_t)by * 128 * Cc;
    float* Cf = sel ? g_U2 : g_U1;

    int frow[2], fq[2];
#pragma unroll
    for (int j = 0; j < 2; j++) { int u = tid + 256 * j; frow[j] = u >> 2; fq[j] = u & 3; }

    float acc[2][8][4];
#pragma unroll
    for (int i = 0; i < 2; i++)
#pragma unroll
        for (int j = 0; j < 8; j++)
#pragma unroll
            for (int q = 0; q < 4; q++) acc[i][j][q] = 0.f;

    uint4 v[4][2];
#pragma unroll
    for (int m = 0; m < 4; m++)
#pragma unroll
        for (int j = 0; j < 2; j++)
            v[m][j] = *(const uint4*)(ptr[m] + (size_t)frow[j] * Cc + fq[j] * 8);
    {
#pragma unroll
        for (int m = 0; m < 4; m++)
#pragma unroll
            for (int j = 0; j < 2; j++)
                *(uint4*)(dsm + m * ATILE + frow[j] * SROW80 + fq[j] * 16) = v[m][j];
    }
#pragma unroll
    for (int m = 0; m < 4; m++)
#pragma unroll
        for (int j = 0; j < 2; j++)
            v[m][j] = *(const uint4*)(ptr[m] + (size_t)frow[j] * Cc + 32 + fq[j] * 8);
    __syncthreads();

    const int nch = Cc / 32;
    for (int i = 0; i < nch; i++) {
        if (i + 1 < nch) {
            char* base = dsm + ((i + 1) & 1) * STAGE_NT;
#pragma unroll
            for (int m = 0; m < 4; m++)
#pragma unroll
                for (int j = 0; j < 2; j++)
                    *(uint4*)(base + m * ATILE + frow[j] * SROW80 + fq[j] * 16) = v[m][j];
        }
        if (i + 2 < nch) {
            int k0 = (i + 2) * 32;
#pragma unroll
            for (int m = 0; m < 4; m++)
#pragma unroll
                for (int j = 0; j < 2; j++)
                    v[m][j] = *(const uint4*)(ptr[m] + (size_t)frow[j] * Cc + k0 + fq[j] * 8);
        }
        compute_nt(smb + (i & 1) * STAGE_NT, wm, wn, lane, acc);
        __syncthreads();
    }

    float* sC = (float*)dsm;
#pragma unroll
    for (int ti = 0; ti < 2; ti++)
#pragma unroll
        for (int j = 0; j < 8; j++) {
            int row0 = wm * 32 + ti * 16 + (lane >> 2);
            int col  = wn * 64 + j * 8 + (lane & 3) * 2;
            *(float2*)(sC + row0 * 132 + col)       = make_float2(acc[ti][j][0], acc[ti][j][1]);
            *(float2*)(sC + (row0 + 8) * 132 + col) = make_float2(acc[ti][j][2], acc[ti][j][3]);
        }
    __syncthreads();

    const int r0 = tid >> 1, half = tid & 1;
    const float* src = sC + r0 * 132 + half * 64;
    size_t base = ((size_t)bz * Cc + bx * 128 + r0) * Cc + by * 128 + half * 64;
#pragma unroll
    for (int j = 0; j < 64; j += 4)
        *(float4*)(Cf + base + j) = *(const float4*)(src + j);
}

// ---------------------------------------------------------------------------
// out GEMM: out = (M+I) X + mb. grid (3,32,16).
// ---------------------------------------------------------------------------
__global__ void __launch_bounds__(256) gemm_out(const float* __restrict__ x,
                                                float* __restrict__ out)
{
    extern __shared__ char dsm[];
    const int tid = threadIdx.x, lane = tid & 31, wid = tid >> 5;
    const int wm = wid & 3, wn = wid >> 2;
    const int bx = blockIdx.x, by = blockIdx.y, bz = blockIdx.z;
    const uint32_t smb = smem_u32(dsm);

    const __nv_bfloat16* pA[2];
    pA[0] = g_Mh + (size_t)bz * Cc * Cc + (size_t)bx * 128 * Cc;
    pA[1] = g_Ml + (size_t)bz * Cc * Cc + (size_t)bx * 128 * Cc;
    const float* Bx = x + (size_t)bz * Cc * Nn + by * 128;

    int frow[2], fq[2];
#pragma unroll
    for (int j = 0; j < 2; j++) { int u = tid + 256 * j; frow[j] = u >> 2; fq[j] = u & 3; }
    int brw[4], bq[4];
#pragma unroll
    for (int j = 0; j < 4; j++) { int u = tid + 256 * j; brw[j] = u >> 5; bq[j] = u & 31; }

    float acc[2][8][4];
#pragma unroll
    for (int i = 0; i < 2; i++)
#pragma unroll
        for (int j = 0; j < 8; j++)
#pragma unroll
            for (int q = 0; q < 4; q++) acc[i][j][q] = 0.f;

    uint4 vA[2][2];
    float4 vB[4];
#pragma unroll
    for (int m = 0; m < 2; m++)
#pragma unroll
        for (int j = 0; j < 2; j++)
            vA[m][j] = *(const uint4*)(pA[m] + (size_t)frow[j] * Cc + fq[j] * 8);
#pragma unroll
    for (int j = 0; j < 4; j++)
        vB[j] = *(const float4*)(Bx + (size_t)brw[j] * Nn + bq[j] * 4);
    {
        char* base = dsm;
#pragma unroll
        for (int m = 0; m < 2; m++)
#pragma unroll
            for (int j = 0; j < 2; j++)
                *(uint4*)(base + m * ATILE + frow[j] * SROW80 + fq[j] * 16) = vA[m][j];
#pragma unroll
        for (int j = 0; j < 4; j++) {
            int off = brw[j] * BPITCH + bq[j] * 8;
            sts_split4(base + 2 * ATILE + off, base + 2 * ATILE + BTILE + off, vB[j]);
        }
    }
#pragma unroll
    for (int m = 0; m < 2; m++)
#pragma unroll
        for (int j = 0; j < 2; j++)
            vA[m][j] = *(const uint4*)(pA[m] + (size_t)frow[j] * Cc + 32 + fq[j] * 8);
#pragma unroll
    for (int j = 0; j < 4; j++)
        vB[j] = *(const float4*)(Bx + (size_t)(32 + brw[j]) * Nn + bq[j] * 4);
    __syncthreads();

    const int nch = Cc / 32;
    for (int i = 0; i < nch; i++) {
        if (i + 1 < nch) {
            char* base = dsm + ((i + 1) & 1) * STAGE_TR;
#pragma unroll
            for (int m = 0; m < 2; m++)
#pragma unroll
                for (int j = 0; j < 2; j++)
                    *(uint4*)(base + m * ATILE + frow[j] * SROW80 + fq[j] * 16) = vA[m][j];
#pragma unroll
            for (int j = 0; j < 4; j++) {
                int off = brw[j] * BPITCH + bq[j] * 8;
                sts_split4(base + 2 * ATILE + off, base + 2 * ATILE + BTILE + off, vB[j]);
            }
        }
        if (i + 2 < nch) {
            int k0 = (i + 2) * 32;
#pragma unroll
            for (int m = 0; m < 2; m++)
#pragma unroll
                for (int j = 0; j < 2; j++)
                    vA[m][j] = *(const uint4*)(pA[m] + (size_t)frow[j] * Cc + k0 + fq[j] * 8);
#pragma unroll
            for (int j = 0; j < 4; j++)
                vB[j] = *(const float4*)(Bx + (size_t)(k0 + brw[j]) * Nn + bq[j] * 4);
        }
        uint32_t st = smb + (i & 1) * STAGE_TR;
        compute_tr(st, st + 2 * ATILE, wm, wn, lane, acc);
        __syncthreads();
    }

    float* sC = (float*)dsm;
#pragma unroll
    for (int ti = 0; ti < 2; ti++)
#pragma unroll
        for (int j = 0; j < 8; j++) {
            int row0 = wm * 32 + ti * 16 + (lane >> 2);
            int col  = wn * 64 + j * 8 + (lane & 3) * 2;
            *(float2*)(sC + row0 * 132 + col)       = make_float2(acc[ti][j][0], acc[ti][j][1]);
            *(float2*)(sC + (row0 + 8) * 132 + col) = make_float2(acc[ti][j][2], acc[ti][j][3]);
        }
    __syncthreads();

    const int r0 = tid >> 1, half = tid & 1;
    const float* src = sC + r0 * 132 + half * 64;
    const int grow = bx * 128 + r0;
    float bias = g_mb[bz * Cc + grow];
    size_t base = ((size_t)bz * Cc + grow) * (size_t)Nn + by * 128 + half * 64;
#pragma unroll
    for (int j = 0; j < 64; j += 4) {
        float4 v4 = *(const float4*)(src + j);
        *(float4*)(out + base + j) = make_float4(v4.x + bias, v4.y + bias,
                                                 v4.z + bias, v4.w + bias);
    }
}

// ---------------------------------------------------------------------------
// attention + fold: M = (A+I)W3 + I, mb = (A+I)b3
// ---------------------------------------------------------------------------
__global__ void __launch_bounds__(256) k_attn_fold(
    const float* __restrict__ w1, const float* __restrict__ b1,
    const float* __restrict__ w2, const float* __restrict__ b2,
    const float* __restrict__ w3, const float* __restrict__ b3,
    const float* __restrict__ temp)
{
    const int h = blockIdx.x, b = blockIdx.y;
    const int tid = threadIdx.x;
    const int warp = tid >> 5, lane = tid & 31;

    __shared__ float sU[CH * 65];
    __shared__ float sW[CH * 65];
    __shared__ float sAa[CH * 49];
    __shared__ float sNq[CH], sNk[CH], sP1[CH], sP2[CH];
    __shared__ float sB1[CH], sB2[CH], sB3[CH];
    __shared__ float sSx[Cc];

    const float* U1  = &g_U1[(size_t)b * Cc * Cc + (size_t)h * CH * Cc];
    const float* U2  = &g_U2[(size_t)b * Cc * Cc + (size_t)h * CH * Cc];
    const float* w1h = w1 + (size_t)h * CH * Cc;
    const float* w2h = w2 + (size_t)h * CH * Cc;
    const float* w3h = w3 + (size_t)h * CH * Cc;

    if (tid < CH) {
        sB1[tid] = b1[h * CH + tid];
        sB2[tid] = b2[h * CH + tid];
        sB3[tid] = b3[h * CH + tid];
    }
    for (int i = tid; i < Cc; i += 256)
        sSx[i] = g_sxp[(size_t)b * Cc + i]
               + g_sxp[((size_t)Bb + b) * Cc + i]
               + g_sxp[((size_t)2 * Bb + b) * Cc + i];

    float acc[9];
#pragma unroll
    for (int e = 0; e < 9; e++) acc[e] = 0.f;

    for (int k0 = 0; k0 < Cc; k0 += 64) {
        __syncthreads();
        for (int i = tid; i < CH * 64; i += 256) {
            int c = i >> 6, kk = i & 63;
            sU[c * 65 + kk] = U1[c * Cc + k0 + kk];
            sW[c * 65 + kk] = w2h[c * Cc + k0 + kk];
        }
        __syncthreads();
#pragma unroll
        for (int e = 0; e < 9; e++) {
            int idx = tid + 256 * e;
            int c = idx / CH, d = idx - c * CH;
            float s = 0.f;
#pragma unroll 16
            for (int kk = 0; kk < 64; kk++)
                s += sU[c * 65 + kk] * sW[d * 65 + kk];
            acc[e] += s;
        }
    }

    __syncthreads();
    for (int c = warp * 6; c < warp * 6 + 6; c++) {
        float aq = 0.f, ak = 0.f, p1 = 0.f, p2 = 0.f;
        for (int k = lane; k < Cc; k += 32) {
            float w1v = w1h[c * Cc + k];
            float w2v = w2h[c * Cc + k];
            aq += U1[c * Cc + k] * w1v;
            ak += U2[c * Cc + k] * w2v;
            float sv = sSx[k];
            p1 += w1v * sv;
            p2 += w2v * sv;
        }
#pragma unroll
        for (int o = 16; o; o >>= 1) {
            aq += __shfl_xor_sync(0xffffffffu, aq, o);
            ak += __shfl_xor_sync(0xffffffffu, ak, o);
            p1 += __shfl_xor_sync(0xffffffffu, p1, o);
            p2 += __shfl_xor_sync(0xffffffffu, p2, o);
        }
        if (lane == 0) { sNq[c] = aq; sNk[c] = ak; sP1[c] = p1; sP2[c] = p2; }
    }
    __syncthreads();

    const float tH = temp[h];
#pragma unroll
    for (int e = 0; e < 9; e++) {
        int idx = tid + 256 * e;
        int c = idx / CH, d = idx - c * CH;
        float b1c = sB1[c], b2d = sB2[d];
        float nq = sqrtf(fmaxf(sNq[c] + 2.f * b1c * sP1[c] + 4096.f * b1c * b1c, 0.f));
        float nk = sqrtf(fmaxf(sNk[d] + 2.f * b2d * sP2[d] + 4096.f * b2d * b2d, 0.f));
        float g  = acc[e] + b1c * sP2[d] + b2d * sP1[c] + 4096.f * b1c * b2d;
        sAa[c * 49 + d] = g / (fmaxf(nq, 1e-12f) * fmaxf(nk, 1e-12f)) * tH;
    }
    __syncthreads();

    for (int c = warp * 6; c < warp * 6 + 6; c++) {
        float a0 = sAa[c * 49 + lane];
        float a1 = (lane < 16) ? sAa[c * 49 + 32 + lane] : -3.402823466e38f;
        float m = fmaxf(a0, a1);
#pragma unroll
        for (int o = 16; o; o >>= 1) m = fmaxf(m, __shfl_xor_sync(0xffffffffu, m, o));
        float e0 = __expf(a0 - m);
        float e1 = (lane < 16) ? __expf(a1 - m) : 0.f;
        float s = e0 + e1;
#pragma unroll
        for (int o = 16; o; o >>= 1) s += __shfl_xor_sync(0xffffffffu, s, o);
        float inv = 1.f / s;
        sAa[c * 49 + lane] = e0 * inv;
        if (lane < 16) sAa[c * 49 + 32 + lane] = e1 * inv;
    }
    __syncthreads();

    if (tid < CH) {
        float s = sB3[tid];
#pragma unroll 8
        for (int d = 0; d < CH; d++) s += sAa[tid * 49 + d] * sB3[d];
        g_mb[b * Cc + h * CH + tid] = s;
    }

    for (int k0 = 0; k0 < Cc; k0 += 64) {
        __syncthreads();
        for (int i = tid; i < CH * 64; i += 256) {
            int d = i >> 6, kk = i & 63;
            sW[d * 65 + kk] = w3h[d * Cc + k0 + kk];
        }
        __syncthreads();
        for (int i = tid; i < CH * 64; i += 256) {
            int c = i >> 6, kk = i & 63;
            float s = sW[c * 65 + kk];
#pragma unroll 8
            for (int d = 0; d < CH; d++) s += sAa[c * 49 + d] * sW[d * 65 + kk];
            if (h * CH + c == k0 + kk) s += 1.f;      // residual folded in
            size_t idx = (size_t)b * Cc * Cc + (size_t)(h * CH + c) * Cc + k0 + kk;
            __nv_bfloat16 hv = __float2bfloat16(s);
            g_Mh[idx] = hv;
            g_Ml[idx] = __float2bfloat16(s - __bfloat162float(hv));
        }
    }
}

// ---------------------------------------------------------------------------
extern "C" void kernel_launch(void* const* d_in, const int* in_sizes, int n_in,
                              void* d_out, int out_size)
{
    (void)in_sizes; (void)n_in; (void)out_size;
    const float* x    = (const float*)d_in[0];
    const float* w1   = (const float*)d_in[1];
    const float* b1   = (const float*)d_in[2];
    const float* w2   = (const float*)d_in[3];
    const float* b2   = (const float*)d_in[4];
    const float* w3   = (const float*)d_in[5];
    const float* b3   = (const float*)d_in[6];
    const float* temp = (const float*)d_in[7];
    float* out = (float*)d_out;

    cudaFuncSetAttribute(gemm_S,   cudaFuncAttributeMaxDynamicSharedMemorySize, DSMEM_NT);
    cudaFuncSetAttribute(gemm_U,   cudaFuncAttributeMaxDynamicSharedMemorySize, DSMEM_NT);
    cudaFuncSetAttribute(gemm_out, cudaFuncAttributeMaxDynamicSharedMemorySize, DSMEM_TR);

    void *pW1h, *pW1l, *pW2h, *pW2l;
    cudaGetSymbolAddress(&pW1h, g_W1h); cudaGetSymbolAddress(&pW1l, g_W1l);
    cudaGetSymbolAddress(&pW2h, g_W2h); cudaGetSymbolAddress(&pW2l, g_W2l);

    k_split<<<(WSZ + 255) / 256, 256>>>(w1, (__nv_bfloat16*)pW1h, (__nv_bfloat16*)pW1l, WSZ);
    k_split<<<(WSZ + 255) / 256, 256>>>(w2, (__nv_bfloat16*)pW2h, (__nv_bfloat16*)pW2l, WSZ);

    gemm_S<<<dim3(6, 3, Bb), 256, DSMEM_NT>>>(x);
    k_Sreduce<<<dim3(16, 6, Bb), 256>>>();

    gemm_U<<<dim3(6, 3, Bb), 256, DSMEM_NT>>>();

    k_attn_fold<<<dim3(HEADS, Bb), 256>>>(w1, b1, w2, b2, w3, b3, temp);

    gemm_out<<<dim3(3, 32, Bb), 256, DSMEM_TR>>>(x, out);
}

// round 6
// speedup vs baseline: 2.2291x; 1.1699x over previous
#include <cuda_runtime.h>
#include <cuda_fp16.h>
#include <math.h>
#include <stdint.h>

#define Bb 16
#define Cc 384
#define Nn 4096
#define HEADS 8
#define CH 48
#define SSZ (Bb*Cc*Cc)
#define WSZ (Cc*Cc)

// ---------------- scratch (device globals; allocation-free) ----------------
__device__ __half g_Sh[SSZ], g_Sl[SSZ];     // S fp16 split
__device__ __half g_Mh[SSZ], g_Ml[SSZ];     // folded (A+I)W3 + I, fp16 split
__device__ __half g_W1h[WSZ], g_W1l[WSZ], g_W2h[WSZ], g_W2l[WSZ];
__device__ float g_U1[SSZ], g_U2[SSZ];
__device__ float g_Sp[3*Bb*6*16384];        // split-K partial S tiles
__device__ float g_sxp[3*Bb*Cc];            // split-K partial row sums
__device__ float g_mb[Bb*Cc];

// ---------------- PTX helpers (sm_80-class; no 'a'-gated features) ---------
__device__ __forceinline__ uint32_t smem_u32(const void* p) {
    uint32_t a;
    asm("{ .reg .u64 t; cvta.to.shared.u64 t, %1; cvt.u32.u64 %0, t; }"
        : "=r"(a) : "l"(p));
    return a;
}
__device__ __forceinline__ void ldsm4(uint32_t* r, uint32_t addr) {
    asm volatile("ldmatrix.sync.aligned.m8n8.x4.shared.b16 {%0,%1,%2,%3}, [%4];"
                 : "=r"(r[0]), "=r"(r[1]), "=r"(r[2]), "=r"(r[3]) : "r"(addr));
}
__device__ __forceinline__ void ldsm4t(uint32_t* r, uint32_t addr) {
    asm volatile("ldmatrix.sync.aligned.m8n8.x4.trans.shared.b16 {%0,%1,%2,%3}, [%4];"
                 : "=r"(r[0]), "=r"(r[1]), "=r"(r[2]), "=r"(r[3]) : "r"(addr));
}
__device__ __forceinline__ void mma16816(float* c, const uint32_t* a, const uint32_t* b) {
    asm volatile(
        "mma.sync.aligned.m16n8k16.row.col.f32.f16.f16.f32 "
        "{%0,%1,%2,%3}, {%4,%5,%6,%7}, {%8,%9}, {%0,%1,%2,%3};"
        : "+f"(c[0]), "+f"(c[1]), "+f"(c[2]), "+f"(c[3])
        : "r"(a[0]), "r"(a[1]), "r"(a[2]), "r"(a[3]), "r"(b[0]), "r"(b[1]));
}

// smem geometry
#define SROW80    80
#define ATILE     10240     // 128 rows * 80 B
#define STAGE_NT2 30720     // Ah, Al, Bh              (2-pass NT)
#define STAGE_NT3 40960     // Ah, Al, Bh, Bl          (3-pass NT, U gemm)
#define BPITCH    272
#define BTILE     8704      // 32 * 272
#define STAGE_TR2 29184     // Mh, Ml, Bh(trans)
#define DSMEM_S   69632
#define DSMEM_U   81920
#define DSMEM_O   69632

// ---------------------------------------------------------------------------
// compute bodies (warp tile 32x64; acc[2][8][4])
// ---------------------------------------------------------------------------
// 2-pass NT: D += (Ah+Al) Bh^T
__device__ __forceinline__ void compute_nt2(uint32_t smb, int wm, int wn, int lane,
                                            float acc[2][8][4]) {
    const int grp = lane >> 3, lr = lane & 7;
#pragma unroll
    for (int ks = 0; ks < 2; ks++) {
        const int kc = ks * 16;
        uint32_t ah[2][4], al[2][4];
#pragma unroll
        for (int ti = 0; ti < 2; ti++) {
            int row = wm * 32 + ti * 16 + lr + (grp & 1) * 8;
            int col = kc + (grp >> 1) * 8;
            uint32_t addr = smb + row * SROW80 + col * 2;
            ldsm4(ah[ti], addr);
            ldsm4(al[ti], addr + ATILE);
        }
#pragma unroll
        for (int half = 0; half < 2; half++) {
            uint32_t bhf[4][2];
#pragma unroll
            for (int p = 0; p < 2; p++) {
                int nrow = wn * 64 + half * 32 + p * 16 + (grp >> 1) * 8 + lr;
                int col = kc + (grp & 1) * 8;
                uint32_t r4[4];
                ldsm4(r4, smb + 2 * ATILE + nrow * SROW80 + col * 2);
                bhf[2*p][0] = r4[0]; bhf[2*p][1] = r4[1];
                bhf[2*p+1][0] = r4[2]; bhf[2*p+1][1] = r4[3];
            }
#pragma unroll
            for (int ti = 0; ti < 2; ti++)
#pragma unroll
                for (int tj = 0; tj < 4; tj++) {
                    float* c = acc[ti][half * 4 + tj];
                    mma16816(c, ah[ti], bhf[tj]);
                    mma16816(c, al[ti], bhf[tj]);
                }
        }
    }
}

// 3-pass NT: D += Ah Bh^T + Ah Bl^T + Al Bh^T
__device__ __forceinline__ void compute_nt3(uint32_t smb, int wm, int wn, int lane,
                                            float acc[2][8][4]) {
    const int grp = lane >> 3, lr = lane & 7;
#pragma unroll
    for (int ks = 0; ks < 2; ks++) {
        const int kc = ks * 16;
        uint32_t ah[2][4], al[2][4];
#pragma unroll
        for (int ti = 0; ti < 2; ti++) {
            int row = wm * 32 + ti * 16 + lr + (grp & 1) * 8;
            int col = kc + (grp >> 1) * 8;
            uint32_t addr = smb + row * SROW80 + col * 2;
            ldsm4(ah[ti], addr);
            ldsm4(al[ti], addr + ATILE);
        }
#pragma unroll
        for (int half = 0; half < 2; half++) {
            uint32_t bhf[4][2], blf[4][2];
#pragma unroll
            for (int p = 0; p < 2; p++) {
                int nrow = wn * 64 + half * 32 + p * 16 + (grp >> 1) * 8 + lr;
                int col = kc + (grp & 1) * 8;
                uint32_t addr = smb + 2 * ATILE + nrow * SROW80 + col * 2;
                uint32_t r4[4];
                ldsm4(r4, addr);
                bhf[2*p][0] = r4[0]; bhf[2*p][1] = r4[1];
                bhf[2*p+1][0] = r4[2]; bhf[2*p+1][1] = r4[3];
                ldsm4(r4, addr + ATILE);
                blf[2*p][0] = r4[0]; blf[2*p][1] = r4[1];
                blf[2*p+1][0] = r4[2]; blf[2*p+1][1] = r4[3];
            }
#pragma unroll
            for (int ti = 0; ti < 2; ti++)
#pragma unroll
                for (int tj = 0; tj < 4; tj++) {
                    float* c = acc[ti][half * 4 + tj];
                    mma16816(c, ah[ti], bhf[tj]);
                    mma16816(c, ah[ti], blf[tj]);
                    mma16816(c, al[ti], bhf[tj]);
                }
        }
    }
}

// 2-pass trans-B: D += (Mh+Ml) Xh, B consumed via ldmatrix.trans
__device__ __forceinline__ void compute_tr2(uint32_t smbA, uint32_t smbB,
                                            int wm, int wn, int lane,
                                            float acc[2][8][4]) {
    const int grp = lane >> 3, lr = lane & 7;
#pragma unroll
    for (int ks = 0; ks < 2; ks++) {
        const int kc = ks * 16;
        uint32_t ah[2][4], al[2][4];
#pragma unroll
        for (int ti = 0; ti < 2; ti++) {
            int row = wm * 32 + ti * 16 + lr + (grp & 1) * 8;
            int col = kc + (grp >> 1) * 8;
            uint32_t addr = smbA + row * SROW80 + col * 2;
            ldsm4(ah[ti], addr);
            ldsm4(al[ti], addr + ATILE);
        }
#pragma unroll
        for (int half = 0; half < 2; half++) {
            uint32_t bhf[4][2];
#pragma unroll
            for (int p = 0; p < 2; p++) {
                int krow = kc + ((lane >> 3) & 1) * 8 + (lane & 7);
                int ncol = wn * 64 + half * 32 + p * 16 + (lane >> 4) * 8;
                uint32_t r4[4];
                ldsm4t(r4, smbB + krow * BPITCH + ncol * 2);
                bhf[2*p][0] = r4[0]; bhf[2*p][1] = r4[1];
                bhf[2*p+1][0] = r4[2]; bhf[2*p+1][1] = r4[3];
            }
#pragma unroll
            for (int ti = 0; ti < 2; ti++)
#pragma unroll
                for (int tj = 0; tj < 4; tj++) {
                    float* c = acc[ti][half * 4 + tj];
                    mma16816(c, ah[ti], bhf[tj]);
                    mma16816(c, al[ti], bhf[tj]);
                }
        }
    }
}

// fp16 split/convert stores
__device__ __forceinline__ void sts_split4(char* ph, char* pl, float4 f) {
    __half2 h01 = __floats2half2_rn(f.x, f.y);
    __half2 h23 = __floats2half2_rn(f.z, f.w);
    __half2 l01 = __floats2half2_rn(f.x - __half2float(__low2half(h01)),
                                    f.y - __half2float(__high2half(h01)));
    __half2 l23 = __floats2half2_rn(f.z - __half2float(__low2half(h23)),
                                    f.w - __half2float(__high2half(h23)));
    uint2 hh, ll;
    hh.x = *(uint32_t*)&h01; hh.y = *(uint32_t*)&h23;
    ll.x = *(uint32_t*)&l01; ll.y = *(uint32_t*)&l23;
    *(uint2*)ph = hh;
    *(uint2*)pl = ll;
}
__device__ __forceinline__ void sts_cvt4(char* p, float4 f) {
    __half2 h01 = __floats2half2_rn(f.x, f.y);
    __half2 h23 = __floats2half2_rn(f.z, f.w);
    uint2 hh;
    hh.x = *(uint32_t*)&h01; hh.y = *(uint32_t*)&h23;
    *(uint2*)p = hh;
}

// elementwise hi/lo split (weights)
__global__ void __launch_bounds__(256) k_split(const float* __restrict__ s,
                                               __half* __restrict__ h,
                                               __half* __restrict__ l, int n) {
    int i = blockIdx.x * 256 + threadIdx.x;
    if (i < n) {
        float v = s[i];
        __half hv = __float2half_rn(v);
        h[i] = hv;
        l[i] = __float2half_rn(v - __half2float(hv));
    }
}

// ---------------------------------------------------------------------------
// S GEMM, triangle + split-K=3, 2-pass: partial tiles -> g_Sp.
// Diagonal pairs also accumulate partial row sums -> g_sxp.
// grid (6 pairs, 3 kz, 16 batch)
// ---------------------------------------------------------------------------
__global__ void __launch_bounds__(256) gemm_S(const float* __restrict__ x) {
    extern __shared__ char dsm[];
    const int pxl[6] = {0,0,0,1,1,2}, pyl[6] = {0,1,2,1,2,2};
    const int tid = threadIdx.x, lane = tid & 31, wid = tid >> 5;
    const int wm = wid & 3, wn = wid >> 2;
    const int pair = blockIdx.x, kz = blockIdx.y, bz = blockIdx.z;
    const int bx = pxl[pair], by = pyl[pair];
    const bool diag = (bx == by);
    const int c0 = (kz == 0) ? 0 : (kz == 1 ? 43 : 86);
    const int c1 = (kz == 0) ? 43 : (kz == 1 ? 86 : 128);
    const int nch = c1 - c0;
    const uint32_t smb = smem_u32(dsm);

    const float* Ax = x + ((size_t)bz * Cc + bx * 128) * Nn + c0 * 32;
    const float* Bx = x + ((size_t)bz * Cc + by * 128) * Nn + c0 * 32;

    int rw[4], qq[4];
#pragma unroll
    for (int j = 0; j < 4; j++) { int u = tid + 256 * j; rw[j] = u >> 3; qq[j] = u & 7; }

    float acc[2][8][4];
#pragma unroll
    for (int i = 0; i < 2; i++)
#pragma unroll
        for (int j = 0; j < 8; j++)
#pragma unroll
            for (int q = 0; q < 4; q++) acc[i][j][q] = 0.f;

    float rsum[4] = {0.f, 0.f, 0.f, 0.f};

    float4 vA[4], vB[4];
#pragma unroll
    for (int j = 0; j < 4; j++) {
        vA[j] = *(const float4*)(Ax + (size_t)rw[j] * Nn + qq[j] * 4);
        vB[j] = *(const float4*)(Bx + (size_t)rw[j] * Nn + qq[j] * 4);
        if (diag) rsum[j] += (vA[j].x + vA[j].y) + (vA[j].z + vA[j].w);
    }
    {
        char* base = dsm;
#pragma unroll
        for (int j = 0; j < 4; j++) {
            int off = rw[j] * SROW80 + qq[j] * 8;
            sts_split4(base + off, base + ATILE + off, vA[j]);
            sts_cvt4(base + 2 * ATILE + off, vB[j]);
        }
    }
#pragma unroll
    for (int j = 0; j < 4; j++) {
        vA[j] = *(const float4*)(Ax + (size_t)rw[j] * Nn + 32 + qq[j] * 4);
        vB[j] = *(const float4*)(Bx + (size_t)rw[j] * Nn + 32 + qq[j] * 4);
        if (diag) rsum[j] += (vA[j].x + vA[j].y) + (vA[j].z + vA[j].w);
    }
    __syncthreads();

    for (int i = 0; i < nch; i++) {
        if (i + 1 < nch) {
            char* base = dsm + ((i + 1) & 1) * STAGE_NT2;
#pragma unroll
            for (int j = 0; j < 4; j++) {
                int off = rw[j] * SROW80 + qq[j] * 8;
                sts_split4(base + off, base + ATILE + off, vA[j]);
                sts_cvt4(base + 2 * ATILE + off, vB[j]);
            }
        }
        if (i + 2 < nch) {
            int k0 = (i + 2) * 32;
#pragma unroll
            for (int j = 0; j < 4; j++) {
                vA[j] = *(const float4*)(Ax + (size_t)rw[j] * Nn + k0 + qq[j] * 4);
                vB[j] = *(const float4*)(Bx + (size_t)rw[j] * Nn + k0 + qq[j] * 4);
                if (diag) rsum[j] += (vA[j].x + vA[j].y) + (vA[j].z + vA[j].w);
            }
        }
        compute_nt2(smb + (i & 1) * STAGE_NT2, wm, wn, lane, acc);
        __syncthreads();
    }

    if (diag) {
#pragma unroll
        for (int j = 0; j < 4; j++) {
            float s = rsum[j];
            s += __shfl_xor_sync(0xffffffffu, s, 1);
            s += __shfl_xor_sync(0xffffffffu, s, 2);
            s += __shfl_xor_sync(0xffffffffu, s, 4);
            if (qq[j] == 0)
                g_sxp[((size_t)kz * Bb + bz) * Cc + bx * 128 + rw[j]] = s;
        }
    }

    float* sC = (float*)dsm;
#pragma unroll
    for (int ti = 0; ti < 2; ti++)
#pragma unroll
        for (int j = 0; j < 8; j++) {
            int row0 = wm * 32 + ti * 16 + (lane >> 2);
            int col  = wn * 64 + j * 8 + (lane & 3) * 2;
            *(float2*)(sC + row0 * 132 + col)       = make_float2(acc[ti][j][0], acc[ti][j][1]);
            *(float2*)(sC + (row0 + 8) * 132 + col) = make_float2(acc[ti][j][2], acc[ti][j][3]);
        }
    __syncthreads();

    float* outp = g_Sp + (((size_t)kz * Bb + bz) * 6 + pair) * 16384;
    const int r0 = tid >> 1, half = tid & 1;
    const float* src = sC + r0 * 132 + half * 64;
#pragma unroll
    for (int j = 0; j < 64; j += 4)
        *(float4*)(outp + r0 * 128 + half * 64 + j) = *(const float4*)(src + j);
}

// ---------------------------------------------------------------------------
// S reduce: sum 3 partials, fp16 split, write tile + (off-diag) transpose.
// grid (16 subtiles, 6 pairs, 16 batch)
// ---------------------------------------------------------------------------
__global__ void __launch_bounds__(256) k_Sreduce() {
    __shared__ float t[32][33];
    const int pxl[6] = {0,0,0,1,1,2}, pyl[6] = {0,1,2,1,2,2};
    const int sub = blockIdx.x, pair = blockIdx.y, bz = blockIdx.z;
    const int px = pxl[pair], py = pyl[pair];
    const int si = sub >> 2, sj = sub & 3;
    const int cc = threadIdx.x & 31, rb = threadIdx.x >> 5;

    const size_t stride = (size_t)Bb * 6 * 16384;
    const float* p0 = g_Sp + ((size_t)bz * 6 + pair) * 16384;
    const float* p1 = p0 + stride;
    const float* p2 = p0 + 2 * stride;
    const size_t gb = (size_t)bz * Cc * Cc;

#pragma unroll
    for (int r = 0; r < 4; r++) {
        int rr = rb + r * 8;
        int li = (si * 32 + rr) * 128 + sj * 32 + cc;
        float s = p0[li] + p1[li] + p2[li];
        t[rr][cc] = s;
        __half hv = __float2half_rn(s);
        size_t o = gb + (size_t)(px * 128 + si * 32 + rr) * Cc + py * 128 + sj * 32 + cc;
        g_Sh[o] = hv;
        g_Sl[o] = __float2half_rn(s - __half2float(hv));
    }
    if (px == py) return;
    __syncthreads();
#pragma unroll
    for (int r = 0; r < 4; r++) {
        int rr = rb + r * 8;
        float s = t[cc][rr];
        __half hv = __float2half_rn(s);
        size_t o = gb + (size_t)(py * 128 + sj * 32 + rr) * Cc + px * 128 + si * 32 + cc;
        g_Sh[o] = hv;
        g_Sl[o] = __float2half_rn(s - __half2float(hv));
    }
}

// ---------------------------------------------------------------------------
// U GEMM (fused U1+U2), 3-pass: U = W @ S (NT, S symmetric). grid (6,3,16).
// ---------------------------------------------------------------------------
__global__ void __launch_bounds__(256) gemm_U() {
    extern __shared__ char dsm[];
    const int tid = threadIdx.x, lane = tid & 31, wid = tid >> 5;
    const int wm = wid & 3, wn = wid >> 2;
    const int sel = blockIdx.x >= 3;
    const int bx = blockIdx.x - (sel ? 3 : 0);
    const int by = blockIdx.y, bz = blockIdx.z;
    const uint32_t smb = smem_u32(dsm);

    const __half* ptr[4];
    ptr[0] = (sel ? g_W2h : g_W1h) + (size_t)bx * 128 * Cc;
    ptr[1] = (sel ? g_W2l : g_W1l) + (size_t)bx * 128 * Cc;
    ptr[2] = g_Sh + (size_t)bz * Cc * Cc + (size_t)by * 128 * Cc;
    ptr[3] = g_Sl + (size_t)bz * Cc * Cc + (size_t)by * 128 * Cc;
    float* Cf = sel ? g_U2 : g_U1;

    int frow[2], fq[2];
#pragma unroll
    for (int j = 0; j < 2; j++) { int u = tid + 256 * j; frow[j] = u >> 2; fq[j] = u & 3; }

    float acc[2][8][4];
#pragma unroll
    for (int i = 0; i < 2; i++)
#pragma unroll
        for (int j = 0; j < 8; j++)
#pragma unroll
            for (int q = 0; q < 4; q++) acc[i][j][q] = 0.f;

    uint4 v[4][2];
#pragma unroll
    for (int m = 0; m < 4; m++)
#pragma unroll
        for (int j = 0; j < 2; j++)
            v[m][j] = *(const uint4*)(ptr[m] + (size_t)frow[j] * Cc + fq[j] * 8);
    {
#pragma unroll
        for (int m = 0; m < 4; m++)
#pragma unroll
            for (int j = 0; j < 2; j++)
                *(uint4*)(dsm + m * ATILE + frow[j] * SROW80 + fq[j] * 16) = v[m][j];
    }
#pragma unroll
    for (int m = 0; m < 4; m++)
#pragma unroll
        for (int j = 0; j < 2; j++)
            v[m][j] = *(const uint4*)(ptr[m] + (size_t)frow[j] * Cc + 32 + fq[j] * 8);
    __syncthreads();

    const int nch = Cc / 32;
    for (int i = 0; i < nch; i++) {
        if (i + 1 < nch) {
            char* base = dsm + ((i + 1) & 1) * STAGE_NT3;
#pragma unroll
            for (int m = 0; m < 4; m++)
#pragma unroll
                for (int j = 0; j < 2; j++)
                    *(uint4*)(base + m * ATILE + frow[j] * SROW80 + fq[j] * 16) = v[m][j];
        }
        if (i + 2 < nch) {
            int k0 = (i + 2) * 32;
#pragma unroll
            for (int m = 0; m < 4; m++)
#pragma unroll
                for (int j = 0; j < 2; j++)
                    v[m][j] = *(const uint4*)(ptr[m] + (size_t)frow[j] * Cc + k0 + fq[j] * 8);
        }
        compute_nt3(smb + (i & 1) * STAGE_NT3, wm, wn, lane, acc);
        __syncthreads();
    }

    float* sC = (float*)dsm;
#pragma unroll
    for (int ti = 0; ti < 2; ti++)
#pragma unroll
        for (int j = 0; j < 8; j++) {
            int row0 = wm * 32 + ti * 16 + (lane >> 2);
            int col  = wn * 64 + j * 8 + (lane & 3) * 2;
            *(float2*)(sC + row0 * 132 + col)       = make_float2(acc[ti][j][0], acc[ti][j][1]);
            *(float2*)(sC + (row0 + 8) * 132 + col) = make_float2(acc[ti][j][2], acc[ti][j][3]);
        }
    __syncthreads();

    const int r0 = tid >> 1, half = tid & 1;
    const float* src = sC + r0 * 132 + half * 64;
    size_t base = ((size_t)bz * Cc + bx * 128 + r0) * Cc + by * 128 + half * 64;
#pragma unroll
    for (int j = 0; j < 64; j += 4)
        *(float4*)(Cf + base + j) = *(const float4*)(src + j);
}

// ---------------------------------------------------------------------------
// out GEMM, 2-pass: out = (Mh+Ml) Xh + mb. grid (3,32,16).
// ---------------------------------------------------------------------------
__global__ void __launch_bounds__(256) gemm_out(const float* __restrict__ x,
                                                float* __restrict__ out)
{
    extern __shared__ char dsm[];
    const int tid = threadIdx.x, lane = tid & 31, wid = tid >> 5;
    const int wm = wid & 3, wn = wid >> 2;
    const int bx = blockIdx.x, by = blockIdx.y, bz = blockIdx.z;
    const uint32_t smb = smem_u32(dsm);

    const __half* pA[2];
    pA[0] = g_Mh + (size_t)bz * Cc * Cc + (size_t)bx * 128 * Cc;
    pA[1] = g_Ml + (size_t)bz * Cc * Cc + (size_t)bx * 128 * Cc;
    const float* Bx = x + (size_t)bz * Cc * Nn + by * 128;

    int frow[2], fq[2];
#pragma unroll
    for (int j = 0; j < 2; j++) { int u = tid + 256 * j; frow[j] = u >> 2; fq[j] = u & 3; }
    int brw[4], bq[4];
#pragma unroll
    for (int j = 0; j < 4; j++) { int u = tid + 256 * j; brw[j] = u >> 5; bq[j] = u & 31; }

    float acc[2][8][4];
#pragma unroll
    for (int i = 0; i < 2; i++)
#pragma unroll
        for (int j = 0; j < 8; j++)
#pragma unroll
            for (int q = 0; q < 4; q++) acc[i][j][q] = 0.f;

    uint4 vA[2][2];
    float4 vB[4];
#pragma unroll
    for (int m = 0; m < 2; m++)
#pragma unroll
        for (int j = 0; j < 2; j++)
            vA[m][j] = *(const uint4*)(pA[m] + (size_t)frow[j] * Cc + fq[j] * 8);
#pragma unroll
    for (int j = 0; j < 4; j++)
        vB[j] = *(const float4*)(Bx + (size_t)brw[j] * Nn + bq[j] * 4);
    {
        char* base = dsm;
#pragma unroll
        for (int m = 0; m < 2; m++)
#pragma unroll
            for (int j = 0; j < 2; j++)
                *(uint4*)(base + m * ATILE + frow[j] * SROW80 + fq[j] * 16) = vA[m][j];
#pragma unroll
        for (int j = 0; j < 4; j++)
            sts_cvt4(base + 2 * ATILE + brw[j] * BPITCH + bq[j] * 8, vB[j]);
    }
#pragma unroll
    for (int m = 0; m < 2; m++)
#pragma unroll
        for (int j = 0; j < 2; j++)
            vA[m][j] = *(const uint4*)(pA[m] + (size_t)frow[j] * Cc + 32 + fq[j] * 8);
#pragma unroll
    for (int j = 0; j < 4; j++)
        vB[j] = *(const float4*)(Bx + (size_t)(32 + brw[j]) * Nn + bq[j] * 4);
    __syncthreads();

    const int nch = Cc / 32;
    for (int i = 0; i < nch; i++) {
        if (i + 1 < nch) {
            char* base = dsm + ((i + 1) & 1) * STAGE_TR2;
#pragma unroll
            for (int m = 0; m < 2; m++)
#pragma unroll
                for (int j = 0; j < 2; j++)
                    *(uint4*)(base + m * ATILE + frow[j] * SROW80 + fq[j] * 16) = vA[m][j];
#pragma unroll
            for (int j = 0; j < 4; j++)
                sts_cvt4(base + 2 * ATILE + brw[j] * BPITCH + bq[j] * 8, vB[j]);
        }
        if (i + 2 < nch) {
            int k0 = (i + 2) * 32;
#pragma unroll
            for (int m = 0; m < 2; m++)
#pragma unroll
                for (int j = 0; j < 2; j++)
                    vA[m][j] = *(const uint4*)(pA[m] + (size_t)frow[j] * Cc + k0 + fq[j] * 8);
#pragma unroll
            for (int j = 0; j < 4; j++)
                vB[j] = *(const float4*)(Bx + (size_t)(k0 + brw[j]) * Nn + bq[j] * 4);
        }
        uint32_t st = smb + (i & 1) * STAGE_TR2;
        compute_tr2(st, st + 2 * ATILE, wm, wn, lane, acc);
        __syncthreads();
    }

    float* sC = (float*)dsm;
#pragma unroll
    for (int ti = 0; ti < 2; ti++)
#pragma unroll
        for (int j = 0; j < 8; j++) {
            int row0 = wm * 32 + ti * 16 + (lane >> 2);
            int col  = wn * 64 + j * 8 + (lane & 3) * 2;
            *(float2*)(sC + row0 * 132 + col)       = make_float2(acc[ti][j][0], acc[ti][j][1]);
            *(float2*)(sC + (row0 + 8) * 132 + col) = make_float2(acc[ti][j][2], acc[ti][j][3]);
        }
    __syncthreads();

    const int r0 = tid >> 1, half = tid & 1;
    const float* src = sC + r0 * 132 + half * 64;
    const int grow = bx * 128 + r0;
    float bias = g_mb[bz * Cc + grow];
    size_t base = ((size_t)bz * Cc + grow) * (size_t)Nn + by * 128 + half * 64;
#pragma unroll
    for (int j = 0; j < 64; j += 4) {
        float4 v4 = *(const float4*)(src + j);
        *(float4*)(out + base + j) = make_float4(v4.x + bias, v4.y + bias,
                                                 v4.z + bias, v4.w + bias);
    }
}

// ---------------------------------------------------------------------------
// attention + fold: M = (A+I)W3 + I, mb = (A+I)b3, fp16 split M
// ---------------------------------------------------------------------------
__global__ void __launch_bounds__(256) k_attn_fold(
    const float* __restrict__ w1, const float* __restrict__ b1,
    const float* __restrict__ w2, const float* __restrict__ b2,
    const float* __restrict__ w3, const float* __restrict__ b3,
    const float* __restrict__ temp)
{
    const int h = blockIdx.x, b = blockIdx.y;
    const int tid = threadIdx.x;
    const int warp = tid >> 5, lane = tid & 31;

    __shared__ float sU[CH * 65];
    __shared__ float sW[CH * 65];
    __shared__ float sAa[CH * 49];
    __shared__ float sNq[CH], sNk[CH], sP1[CH], sP2[CH];
    __shared__ float sB1[CH], sB2[CH], sB3[CH];
    __shared__ float sSx[Cc];

    const float* U1  = &g_U1[(size_t)b * Cc * Cc + (size_t)h * CH * Cc];
    const float* U2  = &g_U2[(size_t)b * Cc * Cc + (size_t)h * CH * Cc];
    const float* w1h = w1 + (size_t)h * CH * Cc;
    const float* w2h = w2 + (size_t)h * CH * Cc;
    const float* w3h = w3 + (size_t)h * CH * Cc;

    if (tid < CH) {
        sB1[tid] = b1[h * CH + tid];
        sB2[tid] = b2[h * CH + tid];
        sB3[tid] = b3[h * CH + tid];
    }
    for (int i = tid; i < Cc; i += 256)
        sSx[i] = g_sxp[(size_t)b * Cc + i]
               + g_sxp[((size_t)Bb + b) * Cc + i]
               + g_sxp[((size_t)2 * Bb + b) * Cc + i];

    float acc[9];
#pragma unroll
    for (int e = 0; e < 9; e++) acc[e] = 0.f;

    for (int k0 = 0; k0 < Cc; k0 += 64) {
        __syncthreads();
        for (int i = tid; i < CH * 64; i += 256) {
            int c = i >> 6, kk = i & 63;
            sU[c * 65 + kk] = U1[c * Cc + k0 + kk];
            sW[c * 65 + kk] = w2h[c * Cc + k0 + kk];
        }
        __syncthreads();
#pragma unroll
        for (int e = 0; e < 9; e++) {
            int idx = tid + 256 * e;
            int c = idx / CH, d = idx - c * CH;
            float s = 0.f;
#pragma unroll 16
            for (int kk = 0; kk < 64; kk++)
                s += sU[c * 65 + kk] * sW[d * 65 + kk];
            acc[e] += s;
        }
    }

    __syncthreads();
    for (int c = warp * 6; c < warp * 6 + 6; c++) {
        float aq = 0.f, ak = 0.f, p1 = 0.f, p2 = 0.f;
        for (int k = lane; k < Cc; k += 32) {
            float w1v = w1h[c * Cc + k];
            float w2v = w2h[c * Cc + k];
            aq += U1[c * Cc + k] * w1v;
            ak += U2[c * Cc + k] * w2v;
            float sv = sSx[k];
            p1 += w1v * sv;
            p2 += w2v * sv;
        }
#pragma unroll
        for (int o = 16; o; o >>= 1) {
            aq += __shfl_xor_sync(0xffffffffu, aq, o);
            ak += __shfl_xor_sync(0xffffffffu, ak, o);
            p1 += __shfl_xor_sync(0xffffffffu, p1, o);
            p2 += __shfl_xor_sync(0xffffffffu, p2, o);
        }
        if (lane == 0) { sNq[c] = aq; sNk[c] = ak; sP1[c] = p1; sP2[c] = p2; }
    }
    __syncthreads();

    const float tH = temp[h];
#pragma unroll
    for (int e = 0; e < 9; e++) {
        int idx = tid + 256 * e;
        int c = idx / CH, d = idx - c * CH;
        float b1c = sB1[c], b2d = sB2[d];
        float nq = sqrtf(fmaxf(sNq[c] + 2.f * b1c * sP1[c] + 4096.f * b1c * b1c, 0.f));
        float nk = sqrtf(fmaxf(sNk[d] + 2.f * b2d * sP2[d] + 4096.f * b2d * b2d, 0.f));
        float g  = acc[e] + b1c * sP2[d] + b2d * sP1[c] + 4096.f * b1c * b2d;
        sAa[c * 49 + d] = g / (fmaxf(nq, 1e-12f) * fmaxf(nk, 1e-12f)) * tH;
    }
    __syncthreads();

    for (int c = warp * 6; c < warp * 6 + 6; c++) {
        float a0 = sAa[c * 49 + lane];
        float a1 = (lane < 16) ? sAa[c * 49 + 32 + lane] : -3.402823466e38f;
        float m = fmaxf(a0, a1);
#pragma unroll
        for (int o = 16; o; o >>= 1) m = fmaxf(m, __shfl_xor_sync(0xffffffffu, m, o));
        float e0 = __expf(a0 - m);
        float e1 = (lane < 16) ? __expf(a1 - m) : 0.f;
        float s = e0 + e1;
#pragma unroll
        for (int o = 16; o; o >>= 1) s += __shfl_xor_sync(0xffffffffu, s, o);
        float inv = 1.f / s;
        sAa[c * 49 + lane] = e0 * inv;
        if (lane < 16) sAa[c * 49 + 32 + lane] = e1 * inv;
    }
    __syncthreads();

    if (tid < CH) {
        float s = sB3[tid];
#pragma unroll 8
        for (int d = 0; d < CH; d++) s += sAa[tid * 49 + d] * sB3[d];
        g_mb[b * Cc + h * CH + tid] = s;
    }

    for (int k0 = 0; k0 < Cc; k0 += 64) {
        __syncthreads();
        for (int i = tid; i < CH * 64; i += 256) {
            int d = i >> 6, kk = i & 63;
            sW[d * 65 + kk] = w3h[d * Cc + k0 + kk];
        }
        __syncthreads();
        for (int i = tid; i < CH * 64; i += 256) {
            int c = i >> 6, kk = i & 63;
            float s = sW[c * 65 + kk];
#pragma unroll 8
            for (int d = 0; d < CH; d++) s += sAa[c * 49 + d] * sW[d * 65 + kk];
            if (h * CH + c == k0 + kk) s += 1.f;      // residual folded in
            size_t idx = (size_t)b * Cc * Cc + (size_t)(h * CH + c) * Cc + k0 + kk;
            __half hv = __float2half_rn(s);
            g_Mh[idx] = hv;
            g_Ml[idx] = __float2half_rn(s - __half2float(hv));
        }
    }
}

// ---------------------------------------------------------------------------
extern "C" void kernel_launch(void* const* d_in, const int* in_sizes, int n_in,
                              void* d_out, int out_size)
{
    (void)in_sizes; (void)n_in; (void)out_size;
    const float* x    = (const float*)d_in[0];
    const float* w1   = (const float*)d_in[1];
    const float* b1   = (const float*)d_in[2];
    const float* w2   = (const float*)d_in[3];
    const float* b2   = (const float*)d_in[4];
    const float* w3   = (const float*)d_in[5];
    const float* b3   = (const float*)d_in[6];
    const float* temp = (const float*)d_in[7];
    float* out = (float*)d_out;

    cudaFuncSetAttribute(gemm_S,   cudaFuncAttributeMaxDynamicSharedMemorySize, DSMEM_S);
    cudaFuncSetAttribute(gemm_U,   cudaFuncAttributeMaxDynamicSharedMemorySize, DSMEM_U);
    cudaFuncSetAttribute(gemm_out, cudaFuncAttributeMaxDynamicSharedMemorySize, DSMEM_O);

    void *pW1h, *pW1l, *pW2h, *pW2l;
    cudaGetSymbolAddress(&pW1h, g_W1h); cudaGetSymbolAddress(&pW1l, g_W1l);
    cudaGetSymbolAddress(&pW2h, g_W2h); cudaGetSymbolAddress(&pW2l, g_W2l);

    k_split<<<(WSZ + 255) / 256, 256>>>(w1, (__half*)pW1h, (__half*)pW1l, WSZ);
    k_split<<<(WSZ + 255) / 256, 256>>>(w2, (__half*)pW2h, (__half*)pW2l, WSZ);

    gemm_S<<<dim3(6, 3, Bb), 256, DSMEM_S>>>(x);
    k_Sreduce<<<dim3(16, 6, Bb), 256>>>();

    gemm_U<<<dim3(6, 3, Bb), 256, DSMEM_U>>>();

    k_attn_fold<<<dim3(HEADS, Bb), 256>>>(w1, b1, w2, b2, w3, b3, temp);

    gemm_out<<<dim3(3, 32, Bb), 256, DSMEM_O>>>(x, out);
}

// round 7
// speedup vs baseline: 2.6237x; 1.1770x over previous
#include <cuda_runtime.h>
#include <cuda_fp16.h>
#include <math.h>
#include <stdint.h>

#define Bb 16
#define Cc 384
#define Nn 4096
#define HEADS 8
#define CH 48
#define SSZ (Bb*Cc*Cc)
#define WSZ (Cc*Cc)

// ---------------- scratch (device globals; allocation-free) ----------------
__device__ __half g_Sh[SSZ], g_Sl[SSZ];     // S fp16 split
__device__ __half g_Mh[SSZ];                // folded (A+I)W3 + I (fp16 hi only)
__device__ float g_U1[SSZ], g_U2[SSZ];
__device__ float g_Sp[3*Bb*6*16384];        // split-K partial S tiles
__device__ float g_sxp[3*Bb*Cc];            // split-K partial row sums
__device__ float g_mb[Bb*Cc];

// ---------------- PTX helpers (sm_80-class; no 'a'-gated features) ---------
__device__ __forceinline__ uint32_t smem_u32(const void* p) {
    uint32_t a;
    asm("{ .reg .u64 t; cvta.to.shared.u64 t, %1; cvt.u32.u64 %0, t; }"
        : "=r"(a) : "l"(p));
    return a;
}
__device__ __forceinline__ void ldsm4(uint32_t* r, uint32_t addr) {
    asm volatile("ldmatrix.sync.aligned.m8n8.x4.shared.b16 {%0,%1,%2,%3}, [%4];"
                 : "=r"(r[0]), "=r"(r[1]), "=r"(r[2]), "=r"(r[3]) : "r"(addr));
}
__device__ __forceinline__ void ldsm4t(uint32_t* r, uint32_t addr) {
    asm volatile("ldmatrix.sync.aligned.m8n8.x4.trans.shared.b16 {%0,%1,%2,%3}, [%4];"
                 : "=r"(r[0]), "=r"(r[1]), "=r"(r[2]), "=r"(r[3]) : "r"(addr));
}
__device__ __forceinline__ void mma16816(float* c, const uint32_t* a, const uint32_t* b) {
    asm volatile(
        "mma.sync.aligned.m16n8k16.row.col.f32.f16.f16.f32 "
        "{%0,%1,%2,%3}, {%4,%5,%6,%7}, {%8,%9}, {%0,%1,%2,%3};"
        : "+f"(c[0]), "+f"(c[1]), "+f"(c[2]), "+f"(c[3])
        : "r"(a[0]), "r"(a[1]), "r"(a[2]), "r"(a[3]), "r"(b[0]), "r"(b[1]));
}

// smem geometry
#define SROW80    80
#define ATILE     10240     // 128 rows * 80 B   (BK=32 fp16 tile)
#define STAGE_NT2 30720     // Ah, Al, Bh              (S gemm, 2-pass)
#define STAGE_NT3 40960     // Ah, Al, Bh, Bl          (U gemm, 3-pass)
#define DSMEM_S   69632
#define DSMEM_U   81920
// out gemm (BK=64, 1-pass)
#define AROW144   144
#define ATILE_O   18432     // 128 * 144
#define BPITCH    272
#define BTILE_O   17408     // 64 * 272
#define STAGE_O   35840
#define DSMEM_O   71680

// ---------------------------------------------------------------------------
// compute bodies (warp tile 32x64; acc[2][8][4])
// ---------------------------------------------------------------------------
// 2-pass NT: D += (Ah+Al) Bh^T   (BK=32)
__device__ __forceinline__ void compute_nt2(uint32_t smb, int wm, int wn, int lane,
                                            float acc[2][8][4]) {
    const int grp = lane >> 3, lr = lane & 7;
#pragma unroll
    for (int ks = 0; ks < 2; ks++) {
        const int kc = ks * 16;
        uint32_t ah[2][4], al[2][4];
#pragma unroll
        for (int ti = 0; ti < 2; ti++) {
            int row = wm * 32 + ti * 16 + lr + (grp & 1) * 8;
            int col = kc + (grp >> 1) * 8;
            uint32_t addr = smb + row * SROW80 + col * 2;
            ldsm4(ah[ti], addr);
            ldsm4(al[ti], addr + ATILE);
        }
#pragma unroll
        for (int half = 0; half < 2; half++) {
            uint32_t bhf[4][2];
#pragma unroll
            for (int p = 0; p < 2; p++) {
                int nrow = wn * 64 + half * 32 + p * 16 + (grp >> 1) * 8 + lr;
                int col = kc + (grp & 1) * 8;
                uint32_t r4[4];
                ldsm4(r4, smb + 2 * ATILE + nrow * SROW80 + col * 2);
                bhf[2*p][0] = r4[0]; bhf[2*p][1] = r4[1];
                bhf[2*p+1][0] = r4[2]; bhf[2*p+1][1] = r4[3];
            }
#pragma unroll
            for (int ti = 0; ti < 2; ti++)
#pragma unroll
                for (int tj = 0; tj < 4; tj++) {
                    float* c = acc[ti][half * 4 + tj];
                    mma16816(c, ah[ti], bhf[tj]);
                    mma16816(c, al[ti], bhf[tj]);
                }
        }
    }
}

// 3-pass NT: D += Ah Bh^T + Ah Bl^T + Al Bh^T   (BK=32)
__device__ __forceinline__ void compute_nt3(uint32_t smb, int wm, int wn, int lane,
                                            float acc[2][8][4]) {
    const int grp = lane >> 3, lr = lane & 7;
#pragma unroll
    for (int ks = 0; ks < 2; ks++) {
        const int kc = ks * 16;
        uint32_t ah[2][4], al[2][4];
#pragma unroll
        for (int ti = 0; ti < 2; ti++) {
            int row = wm * 32 + ti * 16 + lr + (grp & 1) * 8;
            int col = kc + (grp >> 1) * 8;
            uint32_t addr = smb + row * SROW80 + col * 2;
            ldsm4(ah[ti], addr);
            ldsm4(al[ti], addr + ATILE);
        }
#pragma unroll
        for (int half = 0; half < 2; half++) {
            uint32_t bhf[4][2], blf[4][2];
#pragma unroll
            for (int p = 0; p < 2; p++) {
                int nrow = wn * 64 + half * 32 + p * 16 + (grp >> 1) * 8 + lr;
                int col = kc + (grp & 1) * 8;
                uint32_t addr = smb + 2 * ATILE + nrow * SROW80 + col * 2;
                uint32_t r4[4];
                ldsm4(r4, addr);
                bhf[2*p][0] = r4[0]; bhf[2*p][1] = r4[1];
                bhf[2*p+1][0] = r4[2]; bhf[2*p+1][1] = r4[3];
                ldsm4(r4, addr + ATILE);
                blf[2*p][0] = r4[0]; blf[2*p][1] = r4[1];
                blf[2*p+1][0] = r4[2]; blf[2*p+1][1] = r4[3];
            }
#pragma unroll
            for (int ti = 0; ti < 2; ti++)
#pragma unroll
                for (int tj = 0; tj < 4; tj++) {
                    float* c = acc[ti][half * 4 + tj];
                    mma16816(c, ah[ti], bhf[tj]);
                    mma16816(c, ah[ti], blf[tj]);
                    mma16816(c, al[ti], bhf[tj]);
                }
        }
    }
}

// 1-pass trans-B, BK=64: D += Mh Xh (B via ldmatrix.trans)
__device__ __forceinline__ void compute_o(uint32_t smbA, uint32_t smbB,
                                          int wm, int wn, int lane,
                                          float acc[2][8][4]) {
    const int grp = lane >> 3, lr = lane & 7;
#pragma unroll
    for (int ks = 0; ks < 4; ks++) {
        const int kc = ks * 16;
        uint32_t ah[2][4];
#pragma unroll
        for (int ti = 0; ti < 2; ti++) {
            int row = wm * 32 + ti * 16 + lr + (grp & 1) * 8;
            int col = kc + (grp >> 1) * 8;
            ldsm4(ah[ti], smbA + row * AROW144 + col * 2);
        }
#pragma unroll
        for (int half = 0; half < 2; half++) {
            uint32_t bhf[4][2];
#pragma unroll
            for (int p = 0; p < 2; p++) {
                int krow = kc + ((lane >> 3) & 1) * 8 + (lane & 7);
                int ncol = wn * 64 + half * 32 + p * 16 + (lane >> 4) * 8;
                uint32_t r4[4];
                ldsm4t(r4, smbB + krow * BPITCH + ncol * 2);
                bhf[2*p][0] = r4[0]; bhf[2*p][1] = r4[1];
                bhf[2*p+1][0] = r4[2]; bhf[2*p+1][1] = r4[3];
            }
#pragma unroll
            for (int ti = 0; ti < 2; ti++)
#pragma unroll
                for (int tj = 0; tj < 4; tj++)
                    mma16816(acc[ti][half * 4 + tj], ah[ti], bhf[tj]);
        }
    }
}

// fp16 split/convert stores
__device__ __forceinline__ void sts_split4(char* ph, char* pl, float4 f) {
    __half2 h01 = __floats2half2_rn(f.x, f.y);
    __half2 h23 = __floats2half2_rn(f.z, f.w);
    __half2 l01 = __floats2half2_rn(f.x - __half2float(__low2half(h01)),
                                    f.y - __half2float(__high2half(h01)));
    __half2 l23 = __floats2half2_rn(f.z - __half2float(__low2half(h23)),
                                    f.w - __half2float(__high2half(h23)));
    uint2 hh, ll;
    hh.x = *(uint32_t*)&h01; hh.y = *(uint32_t*)&h23;
    ll.x = *(uint32_t*)&l01; ll.y = *(uint32_t*)&l23;
    *(uint2*)ph = hh;
    *(uint2*)pl = ll;
}
__device__ __forceinline__ void sts_cvt4(char* p, float4 f) {
    __half2 h01 = __floats2half2_rn(f.x, f.y);
    __half2 h23 = __floats2half2_rn(f.z, f.w);
    uint2 hh;
    hh.x = *(uint32_t*)&h01; hh.y = *(uint32_t*)&h23;
    *(uint2*)p = hh;
}

// ---------------------------------------------------------------------------
// S GEMM, triangle + split-K=3, 2-pass. grid (6 pairs, 3 kz, 16 batch)
// ---------------------------------------------------------------------------
__global__ void __launch_bounds__(256) gemm_S(const float* __restrict__ x) {
    extern __shared__ char dsm[];
    const int pxl[6] = {0,0,0,1,1,2}, pyl[6] = {0,1,2,1,2,2};
    const int tid = threadIdx.x, lane = tid & 31, wid = tid >> 5;
    const int wm = wid & 3, wn = wid >> 2;
    const int pair = blockIdx.x, kz = blockIdx.y, bz = blockIdx.z;
    const int bx = pxl[pair], by = pyl[pair];
    const bool diag = (bx == by);
    const int c0 = (kz == 0) ? 0 : (kz == 1 ? 43 : 86);
    const int c1 = (kz == 0) ? 43 : (kz == 1 ? 86 : 128);
    const int nch = c1 - c0;
    const uint32_t smb = smem_u32(dsm);

    const float* Ax = x + ((size_t)bz * Cc + bx * 128) * Nn + c0 * 32;
    const float* Bx = x + ((size_t)bz * Cc + by * 128) * Nn + c0 * 32;

    int rw[4], qq[4];
#pragma unroll
    for (int j = 0; j < 4; j++) { int u = tid + 256 * j; rw[j] = u >> 3; qq[j] = u & 7; }

    float acc[2][8][4];
#pragma unroll
    for (int i = 0; i < 2; i++)
#pragma unroll
        for (int j = 0; j < 8; j++)
#pragma unroll
            for (int q = 0; q < 4; q++) acc[i][j][q] = 0.f;

    float rsum[4] = {0.f, 0.f, 0.f, 0.f};

    float4 vA[4], vB[4];
#pragma unroll
    for (int j = 0; j < 4; j++) {
        vA[j] = *(const float4*)(Ax + (size_t)rw[j] * Nn + qq[j] * 4);
        vB[j] = *(const float4*)(Bx + (size_t)rw[j] * Nn + qq[j] * 4);
        if (diag) rsum[j] += (vA[j].x + vA[j].y) + (vA[j].z + vA[j].w);
    }
    {
        char* base = dsm;
#pragma unroll
        for (int j = 0; j < 4; j++) {
            int off = rw[j] * SROW80 + qq[j] * 8;
            sts_split4(base + off, base + ATILE + off, vA[j]);
            sts_cvt4(base + 2 * ATILE + off, vB[j]);
        }
    }
#pragma unroll
    for (int j = 0; j < 4; j++) {
        vA[j] = *(const float4*)(Ax + (size_t)rw[j] * Nn + 32 + qq[j] * 4);
        vB[j] = *(const float4*)(Bx + (size_t)rw[j] * Nn + 32 + qq[j] * 4);
        if (diag) rsum[j] += (vA[j].x + vA[j].y) + (vA[j].z + vA[j].w);
    }
    __syncthreads();

    for (int i = 0; i < nch; i++) {
        if (i + 1 < nch) {
            char* base = dsm + ((i + 1) & 1) * STAGE_NT2;
#pragma unroll
            for (int j = 0; j < 4; j++) {
                int off = rw[j] * SROW80 + qq[j] * 8;
                sts_split4(base + off, base + ATILE + off, vA[j]);
                sts_cvt4(base + 2 * ATILE + off, vB[j]);
            }
        }
        if (i + 2 < nch) {
            int k0 = (i + 2) * 32;
#pragma unroll
            for (int j = 0; j < 4; j++) {
                vA[j] = *(const float4*)(Ax + (size_t)rw[j] * Nn + k0 + qq[j] * 4);
                vB[j] = *(const float4*)(Bx + (size_t)rw[j] * Nn + k0 + qq[j] * 4);
                if (diag) rsum[j] += (vA[j].x + vA[j].y) + (vA[j].z + vA[j].w);
            }
        }
        compute_nt2(smb + (i & 1) * STAGE_NT2, wm, wn, lane, acc);
        __syncthreads();
    }

    if (diag) {
#pragma unroll
        for (int j = 0; j < 4; j++) {
            float s = rsum[j];
            s += __shfl_xor_sync(0xffffffffu, s, 1);
            s += __shfl_xor_sync(0xffffffffu, s, 2);
            s += __shfl_xor_sync(0xffffffffu, s, 4);
            if (qq[j] == 0)
                g_sxp[((size_t)kz * Bb + bz) * Cc + bx * 128 + rw[j]] = s;
        }
    }

    float* sC = (float*)dsm;
#pragma unroll
    for (int ti = 0; ti < 2; ti++)
#pragma unroll
        for (int j = 0; j < 8; j++) {
            int row0 = wm * 32 + ti * 16 + (lane >> 2);
            int col  = wn * 64 + j * 8 + (lane & 3) * 2;
            *(float2*)(sC + row0 * 132 + col)       = make_float2(acc[ti][j][0], acc[ti][j][1]);
            *(float2*)(sC + (row0 + 8) * 132 + col) = make_float2(acc[ti][j][2], acc[ti][j][3]);
        }
    __syncthreads();

    float* outp = g_Sp + (((size_t)kz * Bb + bz) * 6 + pair) * 16384;
    const int r0 = tid >> 1, half = tid & 1;
    const float* src = sC + r0 * 132 + half * 64;
#pragma unroll
    for (int j = 0; j < 64; j += 4)
        *(float4*)(outp + r0 * 128 + half * 64 + j) = *(const float4*)(src + j);
}

// ---------------------------------------------------------------------------
// S reduce: sum 3 partials, fp16 split, write tile + (off-diag) transpose.
// grid (16 subtiles, 6 pairs, 16 batch)
// ---------------------------------------------------------------------------
__global__ void __launch_bounds__(256) k_Sreduce() {
    __shared__ float t[32][33];
    const int pxl[6] = {0,0,0,1,1,2}, pyl[6] = {0,1,2,1,2,2};
    const int sub = blockIdx.x, pair = blockIdx.y, bz = blockIdx.z;
    const int px = pxl[pair], py = pyl[pair];
    const int si = sub >> 2, sj = sub & 3;
    const int cc = threadIdx.x & 31, rb = threadIdx.x >> 5;

    const size_t stride = (size_t)Bb * 6 * 16384;
    const float* p0 = g_Sp + ((size_t)bz * 6 + pair) * 16384;
    const float* p1 = p0 + stride;
    const float* p2 = p0 + 2 * stride;
    const size_t gb = (size_t)bz * Cc * Cc;

#pragma unroll
    for (int r = 0; r < 4; r++) {
        int rr = rb + r * 8;
        int li = (si * 32 + rr) * 128 + sj * 32 + cc;
        float s = p0[li] + p1[li] + p2[li];
        t[rr][cc] = s;
        __half hv = __float2half_rn(s);
        size_t o = gb + (size_t)(px * 128 + si * 32 + rr) * Cc + py * 128 + sj * 32 + cc;
        g_Sh[o] = hv;
        g_Sl[o] = __float2half_rn(s - __half2float(hv));
    }
    if (px == py) return;
    __syncthreads();
#pragma unroll
    for (int r = 0; r < 4; r++) {
        int rr = rb + r * 8;
        float s = t[cc][rr];
        __half hv = __float2half_rn(s);
        size_t o = gb + (size_t)(py * 128 + sj * 32 + rr) * Cc + px * 128 + si * 32 + cc;
        g_Sh[o] = hv;
        g_Sl[o] = __float2half_rn(s - __half2float(hv));
    }
}

// ---------------------------------------------------------------------------
// U GEMM (fused U1+U2), 3-pass, W read fp32 + split inline. grid (6,3,16).
// ---------------------------------------------------------------------------
__global__ void __launch_bounds__(256) gemm_U(const float* __restrict__ w1,
                                              const float* __restrict__ w2) {
    extern __shared__ char dsm[];
    const int tid = threadIdx.x, lane = tid & 31, wid = tid >> 5;
    const int wm = wid & 3, wn = wid >> 2;
    const int sel = blockIdx.x >= 3;
    const int bx = blockIdx.x - (sel ? 3 : 0);
    const int by = blockIdx.y, bz = blockIdx.z;
    const uint32_t smb = smem_u32(dsm);

    const float* Aw = (sel ? w2 : w1) + (size_t)bx * 128 * Cc;
    const __half* pBh = g_Sh + (size_t)bz * Cc * Cc + (size_t)by * 128 * Cc;
    const __half* pBl = g_Sl + (size_t)bz * Cc * Cc + (size_t)by * 128 * Cc;
    float* Cf = sel ? g_U2 : g_U1;

    int rw[4], qq[4];
#pragma unroll
    for (int j = 0; j < 4; j++) { int u = tid + 256 * j; rw[j] = u >> 3; qq[j] = u & 7; }
    int frow[2], fq[2];
#pragma unroll
    for (int j = 0; j < 2; j++) { int u = tid + 256 * j; frow[j] = u >> 2; fq[j] = u & 3; }

    float acc[2][8][4];
#pragma unroll
    for (int i = 0; i < 2; i++)
#pragma unroll
        for (int j = 0; j < 8; j++)
#pragma unroll
            for (int q = 0; q < 4; q++) acc[i][j][q] = 0.f;

    float4 vA[4];
    uint4 vBh[2], vBl[2];
#pragma unroll
    for (int j = 0; j < 4; j++)
        vA[j] = *(const float4*)(Aw + (size_t)rw[j] * Cc + qq[j] * 4);
#pragma unroll
    for (int j = 0; j < 2; j++) {
        vBh[j] = *(const uint4*)(pBh + (size_t)frow[j] * Cc + fq[j] * 8);
        vBl[j] = *(const uint4*)(pBl + (size_t)frow[j] * Cc + fq[j] * 8);
    }
    {
        char* base = dsm;
#pragma unroll
        for (int j = 0; j < 4; j++) {
            int off = rw[j] * SROW80 + qq[j] * 8;
            sts_split4(base + off, base + ATILE + off, vA[j]);
        }
#pragma unroll
        for (int j = 0; j < 2; j++) {
            int off = frow[j] * SROW80 + fq[j] * 16;
            *(uint4*)(base + 2 * ATILE + off) = vBh[j];
            *(uint4*)(base + 3 * ATILE + off) = vBl[j];
        }
    }
#pragma unroll
    for (int j = 0; j < 4; j++)
        vA[j] = *(const float4*)(Aw + (size_t)rw[j] * Cc + 32 + qq[j] * 4);
#pragma unroll
    for (int j = 0; j < 2; j++) {
        vBh[j] = *(const uint4*)(pBh + (size_t)frow[j] * Cc + 32 + fq[j] * 8);
        vBl[j] = *(const uint4*)(pBl + (size_t)frow[j] * Cc + 32 + fq[j] * 8);
    }
    __syncthreads();

    const int nch = Cc / 32;
    for (int i = 0; i < nch; i++) {
        if (i + 1 < nch) {
            char* base = dsm + ((i + 1) & 1) * STAGE_NT3;
#pragma unroll
            for (int j = 0; j < 4; j++) {
                int off = rw[j] * SROW80 + qq[j] * 8;
                sts_split4(base + off, base + ATILE + off, vA[j]);
            }
#pragma unroll
            for (int j = 0; j < 2; j++) {
                int off = frow[j] * SROW80 + fq[j] * 16;
                *(uint4*)(base + 2 * ATILE + off) = vBh[j];
                *(uint4*)(base + 3 * ATILE + off) = vBl[j];
            }
        }
        if (i + 2 < nch) {
            int k0 = (i + 2) * 32;
#pragma unroll
            for (int j = 0; j < 4; j++)
                vA[j] = *(const float4*)(Aw + (size_t)rw[j] * Cc + k0 + qq[j] * 4);
#pragma unroll
            for (int j = 0; j < 2; j++) {
                vBh[j] = *(const uint4*)(pBh + (size_t)frow[j] * Cc + k0 + fq[j] * 8);
                vBl[j] = *(const uint4*)(pBl + (size_t)frow[j] * Cc + k0 + fq[j] * 8);
            }
        }
        compute_nt3(smb + (i & 1) * STAGE_NT3, wm, wn, lane, acc);
        __syncthreads();
    }

    float* sC = (float*)dsm;
#pragma unroll
    for (int ti = 0; ti < 2; ti++)
#pragma unroll
        for (int j = 0; j < 8; j++) {
            int row0 = wm * 32 + ti * 16 + (lane >> 2);
            int col  = wn * 64 + j * 8 + (lane & 3) * 2;
            *(float2*)(sC + row0 * 132 + col)       = make_float2(acc[ti][j][0], acc[ti][j][1]);
            *(float2*)(sC + (row0 + 8) * 132 + col) = make_float2(acc[ti][j][2], acc[ti][j][3]);
        }
    __syncthreads();

    const int r0 = tid >> 1, half = tid & 1;
    const float* src = sC + r0 * 132 + half * 64;
    size_t base = ((size_t)bz * Cc + bx * 128 + r0) * Cc + by * 128 + half * 64;
#pragma unroll
    for (int j = 0; j < 64; j += 4)
        *(float4*)(Cf + base + j) = *(const float4*)(src + j);
}

// ---------------------------------------------------------------------------
// out GEMM, 1-pass, BK=64: out = Mh Xh + mb. grid (3,32,16).
// ---------------------------------------------------------------------------
__global__ void __launch_bounds__(256) gemm_out(const float* __restrict__ x,
                                                float* __restrict__ out)
{
    extern __shared__ char dsm[];
    const int tid = threadIdx.x, lane = tid & 31, wid = tid >> 5;
    const int wm = wid & 3, wn = wid >> 2;
    const int bx = blockIdx.x, by = blockIdx.y, bz = blockIdx.z;
    const uint32_t smb = smem_u32(dsm);

    const __half* pA = g_Mh + (size_t)bz * Cc * Cc + (size_t)bx * 128 * Cc;
    const float* Bx = x + (size_t)bz * Cc * Nn + by * 128;

    // A loader: 128 rows x 64 fp16 = 1024 uint4 -> 4/thread
    int arw[4], aq[4];
#pragma unroll
    for (int j = 0; j < 4; j++) { int u = tid + 256 * j; arw[j] = u >> 3; aq[j] = u & 7; }
    // B loader: 64 k-rows x 128 n fp32 -> 8 float4/thread
    int brw[8], bq[8];
#pragma unroll
    for (int j = 0; j < 8; j++) { int u = tid + 256 * j; brw[j] = u >> 5; bq[j] = u & 31; }

    float acc[2][8][4];
#pragma unroll
    for (int i = 0; i < 2; i++)
#pragma unroll
        for (int j = 0; j < 8; j++)
#pragma unroll
            for (int q = 0; q < 4; q++) acc[i][j][q] = 0.f;

    uint4 vA[4];
    float4 vB[8];
#pragma unroll
    for (int j = 0; j < 4; j++)
        vA[j] = *(const uint4*)(pA + (size_t)arw[j] * Cc + aq[j] * 8);
#pragma unroll
    for (int j = 0; j < 8; j++)
        vB[j] = *(const float4*)(Bx + (size_t)brw[j] * Nn + bq[j] * 4);
    {
        char* base = dsm;
#pragma unroll
        for (int j = 0; j < 4; j++)
            *(uint4*)(base + arw[j] * AROW144 + aq[j] * 16) = vA[j];
#pragma unroll
        for (int j = 0; j < 8; j++)
            sts_cvt4(base + ATILE_O + brw[j] * BPITCH + bq[j] * 8, vB[j]);
    }
#pragma unroll
    for (int j = 0; j < 4; j++)
        vA[j] = *(const uint4*)(pA + (size_t)arw[j] * Cc + 64 + aq[j] * 8);
#pragma unroll
    for (int j = 0; j < 8; j++)
        vB[j] = *(const float4*)(Bx + (size_t)(64 + brw[j]) * Nn + bq[j] * 4);
    __syncthreads();

    const int nch = Cc / 64;   // 6
    for (int i = 0; i < nch; i++) {
        if (i + 1 < nch) {
            char* base = dsm + ((i + 1) & 1) * STAGE_O;
#pragma unroll
            for (int j = 0; j < 4; j++)
                *(uint4*)(base + arw[j] * AROW144 + aq[j] * 16) = vA[j];
#pragma unroll
            for (int j = 0; j < 8; j++)
                sts_cvt4(base + ATILE_O + brw[j] * BPITCH + bq[j] * 8, vB[j]);
        }
        if (i + 2 < nch) {
            int k0 = (i + 2) * 64;
#pragma unroll
            for (int j = 0; j < 4; j++)
                vA[j] = *(const uint4*)(pA + (size_t)arw[j] * Cc + k0 + aq[j] * 8);
#pragma unroll
            for (int j = 0; j < 8; j++)
                vB[j] = *(const float4*)(Bx + (size_t)(k0 + brw[j]) * Nn + bq[j] * 4);
        }
        uint32_t st = smb + (i & 1) * STAGE_O;
        compute_o(st, st + ATILE_O, wm, wn, lane, acc);
        __syncthreads();
    }

    float* sC = (float*)dsm;
#pragma unroll
    for (int ti = 0; ti < 2; ti++)
#pragma unroll
        for (int j = 0; j < 8; j++) {
            int row0 = wm * 32 + ti * 16 + (lane >> 2);
            int col  = wn * 64 + j * 8 + (lane & 3) * 2;
            *(float2*)(sC + row0 * 132 + col)       = make_float2(acc[ti][j][0], acc[ti][j][1]);
            *(float2*)(sC + (row0 + 8) * 132 + col) = make_float2(acc[ti][j][2], acc[ti][j][3]);
        }
    __syncthreads();

    const int r0 = tid >> 1, half = tid & 1;
    const float* src = sC + r0 * 132 + half * 64;
    const int grow = bx * 128 + r0;
    float bias = g_mb[bz * Cc + grow];
    size_t base = ((size_t)bz * Cc + grow) * (size_t)Nn + by * 128 + half * 64;
#pragma unroll
    for (int j = 0; j < 64; j += 4) {
        float4 v4 = *(const float4*)(src + j);
        *(float4*)(out + base + j) = make_float4(v4.x + bias, v4.y + bias,
                                                 v4.z + bias, v4.w + bias);
    }
}

// ---------------------------------------------------------------------------
// attention + fold: M = (A+I)W3 + I, mb = (A+I)b3, fp16 hi M only
// ---------------------------------------------------------------------------
__global__ void __launch_bounds__(256) k_attn_fold(
    const float* __restrict__ w1, const float* __restrict__ b1,
    const float* __restrict__ w2, const float* __restrict__ b2,
    const float* __restrict__ w3, const float* __restrict__ b3,
    const float* __restrict__ temp)
{
    const int h = blockIdx.x, b = blockIdx.y;
    const int tid = threadIdx.x;
    const int warp = tid >> 5, lane = tid & 31;

    __shared__ float sU[CH * 65];
    __shared__ float sW[CH * 65];
    __shared__ float sAa[CH * 49];
    __shared__ float sNq[CH], sNk[CH], sP1[CH], sP2[CH];
    __shared__ float sB1[CH], sB2[CH], sB3[CH];
    __shared__ float sSx[Cc];

    const float* U1  = &g_U1[(size_t)b * Cc * Cc + (size_t)h * CH * Cc];
    const float* U2  = &g_U2[(size_t)b * Cc * Cc + (size_t)h * CH * Cc];
    const float* w1h = w1 + (size_t)h * CH * Cc;
    const float* w2h = w2 + (size_t)h * CH * Cc;
    const float* w3h = w3 + (size_t)h * CH * Cc;

    if (tid < CH) {
        sB1[tid] = b1[h * CH + tid];
        sB2[tid] = b2[h * CH + tid];
        sB3[tid] = b3[h * CH + tid];
    }
    for (int i = tid; i < Cc; i += 256)
        sSx[i] = g_sxp[(size_t)b * Cc + i]
               + g_sxp[((size_t)Bb + b) * Cc + i]
               + g_sxp[((size_t)2 * Bb + b) * Cc + i];

    float acc[9];
#pragma unroll
    for (int e = 0; e < 9; e++) acc[e] = 0.f;

    for (int k0 = 0; k0 < Cc; k0 += 64) {
        __syncthreads();
        for (int i = tid; i < CH * 64; i += 256) {
            int c = i >> 6, kk = i & 63;
            sU[c * 65 + kk] = U1[c * Cc + k0 + kk];
            sW[c * 65 + kk] = w2h[c * Cc + k0 + kk];
        }
        __syncthreads();
#pragma unroll
        for (int e = 0; e < 9; e++) {
            int idx = tid + 256 * e;
            int c = idx / CH, d = idx - c * CH;
            float s = 0.f;
#pragma unroll 16
            for (int kk = 0; kk < 64; kk++)
                s += sU[c * 65 + kk] * sW[d * 65 + kk];
            acc[e] += s;
        }
    }

    __syncthreads();
    for (int c = warp * 6; c < warp * 6 + 6; c++) {
        float aq = 0.f, ak = 0.f, p1 = 0.f, p2 = 0.f;
        for (int k = lane; k < Cc; k += 32) {
            float w1v = w1h[c * Cc + k];
            float w2v = w2h[c * Cc + k];
            aq += U1[c * Cc + k] * w1v;
            ak += U2[c * Cc + k] * w2v;
            float sv = sSx[k];
            p1 += w1v * sv;
            p2 += w2v * sv;
        }
#pragma unroll
        for (int o = 16; o; o >>= 1) {
            aq += __shfl_xor_sync(0xffffffffu, aq, o);
            ak += __shfl_xor_sync(0xffffffffu, ak, o);
            p1 += __shfl_xor_sync(0xffffffffu, p1, o);
            p2 += __shfl_xor_sync(0xffffffffu, p2, o);
        }
        if (lane == 0) { sNq[c] = aq; sNk[c] = ak; sP1[c] = p1; sP2[c] = p2; }
    }
    __syncthreads();

    const float tH = temp[h];
#pragma unroll
    for (int e = 0; e < 9; e++) {
        int idx = tid + 256 * e;
        int c = idx / CH, d = idx - c * CH;
        float b1c = sB1[c], b2d = sB2[d];
        float nq = sqrtf(fmaxf(sNq[c] + 2.f * b1c * sP1[c] + 4096.f * b1c * b1c, 0.f));
        float nk = sqrtf(fmaxf(sNk[d] + 2.f * b2d * sP2[d] + 4096.f * b2d * b2d, 0.f));
        float g  = acc[e] + b1c * sP2[d] + b2d * sP1[c] + 4096.f * b1c * b2d;
        sAa[c * 49 + d] = g / (fmaxf(nq, 1e-12f) * fmaxf(nk, 1e-12f)) * tH;
    }
    __syncthreads();

    for (int c = warp * 6; c < warp * 6 + 6; c++) {
        float a0 = sAa[c * 49 + lane];
        float a1 = (lane < 16) ? sAa[c * 49 + 32 + lane] : -3.402823466e38f;
        float m = fmaxf(a0, a1);
#pragma unroll
        for (int o = 16; o; o >>= 1) m = fmaxf(m, __shfl_xor_sync(0xffffffffu, m, o));
        float e0 = __expf(a0 - m);
        float e1 = (lane < 16) ? __expf(a1 - m) : 0.f;
        float s = e0 + e1;
#pragma unroll
        for (int o = 16; o; o >>= 1) s += __shfl_xor_sync(0xffffffffu, s, o);
        float inv = 1.f / s;
        sAa[c * 49 + lane] = e0 * inv;
        if (lane < 16) sAa[c * 49 + 32 + lane] = e1 * inv;
    }
    __syncthreads();

    if (tid < CH) {
        float s = sB3[tid];
#pragma unroll 8
        for (int d = 0; d < CH; d++) s += sAa[tid * 49 + d] * sB3[d];
        g_mb[b * Cc + h * CH + tid] = s;
    }

    for (int k0 = 0; k0 < Cc; k0 += 64) {
        __syncthreads();
        for (int i = tid; i < CH * 64; i += 256) {
            int d = i >> 6, kk = i & 63;
            sW[d * 65 + kk] = w3h[d * Cc + k0 + kk];
        }
        __syncthreads();
        for (int i = tid; i < CH * 64; i += 256) {
            int c = i >> 6, kk = i & 63;
            float s = sW[c * 65 + kk];
#pragma unroll 8
            for (int d = 0; d < CH; d++) s += sAa[c * 49 + d] * sW[d * 65 + kk];
            if (h * CH + c == k0 + kk) s += 1.f;      // residual folded in
            g_Mh[(size_t)b * Cc * Cc + (size_t)(h * CH + c) * Cc + k0 + kk] =
                __float2half_rn(s);
        }
    }
}

// ---------------------------------------------------------------------------
extern "C" void kernel_launch(void* const* d_in, const int* in_sizes, int n_in,
                              void* d_out, int out_size)
{
    (void)in_sizes; (void)n_in; (void)out_size;
    const float* x    = (const float*)d_in[0];
    const float* w1   = (const float*)d_in[1];
    const float* b1   = (const float*)d_in[2];
    const float* w2   = (const float*)d_in[3];
    const float* b2   = (const float*)d_in[4];
    const float* w3   = (const float*)d_in[5];
    const float* b3   = (const float*)d_in[6];
    const float* temp = (const float*)d_in[7];
    float* out = (float*)d_out;

    cudaFuncSetAttribute(gemm_S,   cudaFuncAttributeMaxDynamicSharedMemorySize, DSMEM_S);
    cudaFuncSetAttribute(gemm_U,   cudaFuncAttributeMaxDynamicSharedMemorySize, DSMEM_U);
    cudaFuncSetAttribute(gemm_out, cudaFuncAttributeMaxDynamicSharedMemorySize, DSMEM_O);

    gemm_S<<<dim3(6, 3, Bb), 256, DSMEM_S>>>(x);
    k_Sreduce<<<dim3(16, 6, Bb), 256>>>();

    gemm_U<<<dim3(6, 3, Bb), 256, DSMEM_U>>>(w1, w2);

    k_attn_fold<<<dim3(HEADS, Bb), 256>>>(w1, b1, w2, b2, w3, b3, temp);

    gemm_out<<<dim3(3, 32, Bb), 256, DSMEM_O>>>(x, out);
}

// round 8
// speedup vs baseline: 2.8841x; 1.0993x over previous
#include <cuda_runtime.h>
#include <cuda_fp16.h>
#include <math.h>
#include <stdint.h>

#define Bb 16
#define Cc 384
#define Nn 4096
#define HEADS 8
#define CH 48
#define SSZ (Bb*Cc*Cc)

// ---------------- scratch (device globals; allocation-free) ----------------
__device__ __half g_Sh[SSZ], g_Sl[SSZ];     // S fp16 split
__device__ __half g_Mh[SSZ];                // folded (A+I)W3 + I (fp16 hi only)
__device__ float g_U1[SSZ], g_U2[SSZ];
__device__ float g_Sp[3*Bb*6*16384];        // split-K partial S tiles
__device__ float g_sxp[3*Bb*Cc];            // split-K partial row sums
__device__ float g_mb[Bb*Cc];
__device__ float g_A[Bb*HEADS*CH*CH];       // softmaxed attention matrices

// ---------------- PTX helpers (sm_80-class; no 'a'-gated features) ---------
__device__ __forceinline__ uint32_t smem_u32(const void* p) {
    uint32_t a;
    asm("{ .reg .u64 t; cvta.to.shared.u64 t, %1; cvt.u32.u64 %0, t; }"
        : "=r"(a) : "l"(p));
    return a;
}
__device__ __forceinline__ void ldsm4(uint32_t* r, uint32_t addr) {
    asm volatile("ldmatrix.sync.aligned.m8n8.x4.shared.b16 {%0,%1,%2,%3}, [%4];"
                 : "=r"(r[0]), "=r"(r[1]), "=r"(r[2]), "=r"(r[3]) : "r"(addr));
}
__device__ __forceinline__ void ldsm4t(uint32_t* r, uint32_t addr) {
    asm volatile("ldmatrix.sync.aligned.m8n8.x4.trans.shared.b16 {%0,%1,%2,%3}, [%4];"
                 : "=r"(r[0]), "=r"(r[1]), "=r"(r[2]), "=r"(r[3]) : "r"(addr));
}
__device__ __forceinline__ void mma16816(float* c, const uint32_t* a, const uint32_t* b) {
    asm volatile(
        "mma.sync.aligned.m16n8k16.row.col.f32.f16.f16.f32 "
        "{%0,%1,%2,%3}, {%4,%5,%6,%7}, {%8,%9}, {%0,%1,%2,%3};"
        : "+f"(c[0]), "+f"(c[1]), "+f"(c[2]), "+f"(c[3])
        : "r"(a[0]), "r"(a[1]), "r"(a[2]), "r"(a[3]), "r"(b[0]), "r"(b[1]));
}

// smem geometry
#define SROW80    80
#define ATILE     10240
#define STAGE_NT2 30720
#define STAGE_NT3 40960
#define DSMEM_S   69632
#define DSMEM_U   81920
#define AROW144   144
#define ATILE_O   18432
#define BPITCH    272
#define STAGE_O   35840
#define DSMEM_O   71680

// ---------------------------------------------------------------------------
// compute bodies (warp tile 32x64; acc[2][8][4])
// ---------------------------------------------------------------------------
__device__ __forceinline__ void compute_nt2(uint32_t smb, int wm, int wn, int lane,
                                            float acc[2][8][4]) {
    const int grp = lane >> 3, lr = lane & 7;
#pragma unroll
    for (int ks = 0; ks < 2; ks++) {
        const int kc = ks * 16;
        uint32_t ah[2][4], al[2][4];
#pragma unroll
        for (int ti = 0; ti < 2; ti++) {
            int row = wm * 32 + ti * 16 + lr + (grp & 1) * 8;
            int col = kc + (grp >> 1) * 8;
            uint32_t addr = smb + row * SROW80 + col * 2;
            ldsm4(ah[ti], addr);
            ldsm4(al[ti], addr + ATILE);
        }
#pragma unroll
        for (int half = 0; half < 2; half++) {
            uint32_t bhf[4][2];
#pragma unroll
            for (int p = 0; p < 2; p++) {
                int nrow = wn * 64 + half * 32 + p * 16 + (grp >> 1) * 8 + lr;
                int col = kc + (grp & 1) * 8;
                uint32_t r4[4];
                ldsm4(r4, smb + 2 * ATILE + nrow * SROW80 + col * 2);
                bhf[2*p][0] = r4[0]; bhf[2*p][1] = r4[1];
                bhf[2*p+1][0] = r4[2]; bhf[2*p+1][1] = r4[3];
            }
#pragma unroll
            for (int ti = 0; ti < 2; ti++)
#pragma unroll
                for (int tj = 0; tj < 4; tj++) {
                    float* c = acc[ti][half * 4 + tj];
                    mma16816(c, ah[ti], bhf[tj]);
                    mma16816(c, al[ti], bhf[tj]);
                }
        }
    }
}

__device__ __forceinline__ void compute_nt3(uint32_t smb, int wm, int wn, int lane,
                                            float acc[2][8][4]) {
    const int grp = lane >> 3, lr = lane & 7;
#pragma unroll
    for (int ks = 0; ks < 2; ks++) {
        const int kc = ks * 16;
        uint32_t ah[2][4], al[2][4];
#pragma unroll
        for (int ti = 0; ti < 2; ti++) {
            int row = wm * 32 + ti * 16 + lr + (grp & 1) * 8;
            int col = kc + (grp >> 1) * 8;
            uint32_t addr = smb + row * SROW80 + col * 2;
            ldsm4(ah[ti], addr);
            ldsm4(al[ti], addr + ATILE);
        }
#pragma unroll
        for (int half = 0; half < 2; half++) {
            uint32_t bhf[4][2], blf[4][2];
#pragma unroll
            for (int p = 0; p < 2; p++) {
                int nrow = wn * 64 + half * 32 + p * 16 + (grp >> 1) * 8 + lr;
                int col = kc + (grp & 1) * 8;
                uint32_t addr = smb + 2 * ATILE + nrow * SROW80 + col * 2;
                uint32_t r4[4];
                ldsm4(r4, addr);
                bhf[2*p][0] = r4[0]; bhf[2*p][1] = r4[1];
                bhf[2*p+1][0] = r4[2]; bhf[2*p+1][1] = r4[3];
                ldsm4(r4, addr + ATILE);
                blf[2*p][0] = r4[0]; blf[2*p][1] = r4[1];
                blf[2*p+1][0] = r4[2]; blf[2*p+1][1] = r4[3];
            }
#pragma unroll
            for (int ti = 0; ti < 2; ti++)
#pragma unroll
                for (int tj = 0; tj < 4; tj++) {
                    float* c = acc[ti][half * 4 + tj];
                    mma16816(c, ah[ti], bhf[tj]);
                    mma16816(c, ah[ti], blf[tj]);
                    mma16816(c, al[ti], bhf[tj]);
                }
        }
    }
}

__device__ __forceinline__ void compute_o(uint32_t smbA, uint32_t smbB,
                                          int wm, int wn, int lane,
                                          float acc[2][8][4]) {
    const int grp = lane >> 3, lr = lane & 7;
#pragma unroll
    for (int ks = 0; ks < 4; ks++) {
        const int kc = ks * 16;
        uint32_t ah[2][4];
#pragma unroll
        for (int ti = 0; ti < 2; ti++) {
            int row = wm * 32 + ti * 16 + lr + (grp & 1) * 8;
            int col = kc + (grp >> 1) * 8;
            ldsm4(ah[ti], smbA + row * AROW144 + col * 2);
        }
#pragma unroll
        for (int half = 0; half < 2; half++) {
            uint32_t bhf[4][2];
#pragma unroll
            for (int p = 0; p < 2; p++) {
                int krow = kc + ((lane >> 3) & 1) * 8 + (lane & 7);
                int ncol = wn * 64 + half * 32 + p * 16 + (lane >> 4) * 8;
                uint32_t r4[4];
                ldsm4t(r4, smbB + krow * BPITCH + ncol * 2);
                bhf[2*p][0] = r4[0]; bhf[2*p][1] = r4[1];
                bhf[2*p+1][0] = r4[2]; bhf[2*p+1][1] = r4[3];
            }
#pragma unroll
            for (int ti = 0; ti < 2; ti++)
#pragma unroll
                for (int tj = 0; tj < 4; tj++)
                    mma16816(acc[ti][half * 4 + tj], ah[ti], bhf[tj]);
        }
    }
}

__device__ __forceinline__ void sts_split4(char* ph, char* pl, float4 f) {
    __half2 h01 = __floats2half2_rn(f.x, f.y);
    __half2 h23 = __floats2half2_rn(f.z, f.w);
    __half2 l01 = __floats2half2_rn(f.x - __half2float(__low2half(h01)),
                                    f.y - __half2float(__high2half(h01)));
    __half2 l23 = __floats2half2_rn(f.z - __half2float(__low2half(h23)),
                                    f.w - __half2float(__high2half(h23)));
    uint2 hh, ll;
    hh.x = *(uint32_t*)&h01; hh.y = *(uint32_t*)&h23;
    ll.x = *(uint32_t*)&l01; ll.y = *(uint32_t*)&l23;
    *(uint2*)ph = hh;
    *(uint2*)pl = ll;
}
__device__ __forceinline__ void sts_cvt4(char* p, float4 f) {
    __half2 h01 = __floats2half2_rn(f.x, f.y);
    __half2 h23 = __floats2half2_rn(f.z, f.w);
    uint2 hh;
    hh.x = *(uint32_t*)&h01; hh.y = *(uint32_t*)&h23;
    *(uint2*)p = hh;
}

// ---------------------------------------------------------------------------
// S GEMM, triangle + split-K=3, 2-pass. grid (6 pairs, 3 kz, 16 batch)
// ---------------------------------------------------------------------------
__global__ void __launch_bounds__(256) gemm_S(const float* __restrict__ x) {
    extern __shared__ char dsm[];
    const int pxl[6] = {0,0,0,1,1,2}, pyl[6] = {0,1,2,1,2,2};
    const int tid = threadIdx.x, lane = tid & 31, wid = tid >> 5;
    const int wm = wid & 3, wn = wid >> 2;
    const int pair = blockIdx.x, kz = blockIdx.y, bz = blockIdx.z;
    const int bx = pxl[pair], by = pyl[pair];
    const bool diag = (bx == by);
    const int c0 = (kz == 0) ? 0 : (kz == 1 ? 43 : 86);
    const int c1 = (kz == 0) ? 43 : (kz == 1 ? 86 : 128);
    const int nch = c1 - c0;
    const uint32_t smb = smem_u32(dsm);

    const float* Ax = x + ((size_t)bz * Cc + bx * 128) * Nn + c0 * 32;
    const float* Bx = x + ((size_t)bz * Cc + by * 128) * Nn + c0 * 32;

    int rw[4], qq[4];
#pragma unroll
    for (int j = 0; j < 4; j++) { int u = tid + 256 * j; rw[j] = u >> 3; qq[j] = u & 7; }

    float acc[2][8][4];
#pragma unroll
    for (int i = 0; i < 2; i++)
#pragma unroll
        for (int j = 0; j < 8; j++)
#pragma unroll
            for (int q = 0; q < 4; q++) acc[i][j][q] = 0.f;

    float rsum[4] = {0.f, 0.f, 0.f, 0.f};

    float4 vA[4], vB[4];
#pragma unroll
    for (int j = 0; j < 4; j++) {
        vA[j] = *(const float4*)(Ax + (size_t)rw[j] * Nn + qq[j] * 4);
        vB[j] = *(const float4*)(Bx + (size_t)rw[j] * Nn + qq[j] * 4);
        if (diag) rsum[j] += (vA[j].x + vA[j].y) + (vA[j].z + vA[j].w);
    }
    {
        char* base = dsm;
#pragma unroll
        for (int j = 0; j < 4; j++) {
            int off = rw[j] * SROW80 + qq[j] * 8;
            sts_split4(base + off, base + ATILE + off, vA[j]);
            sts_cvt4(base + 2 * ATILE + off, vB[j]);
        }
    }
#pragma unroll
    for (int j = 0; j < 4; j++) {
        vA[j] = *(const float4*)(Ax + (size_t)rw[j] * Nn + 32 + qq[j] * 4);
        vB[j] = *(const float4*)(Bx + (size_t)rw[j] * Nn + 32 + qq[j] * 4);
        if (diag) rsum[j] += (vA[j].x + vA[j].y) + (vA[j].z + vA[j].w);
    }
    __syncthreads();

    for (int i = 0; i < nch; i++) {
        if (i + 1 < nch) {
            char* base = dsm + ((i + 1) & 1) * STAGE_NT2;
#pragma unroll
            for (int j = 0; j < 4; j++) {
                int off = rw[j] * SROW80 + qq[j] * 8;
                sts_split4(base + off, base + ATILE + off, vA[j]);
                sts_cvt4(base + 2 * ATILE + off, vB[j]);
            }
        }
        if (i + 2 < nch) {
            int k0 = (i + 2) * 32;
#pragma unroll
            for (int j = 0; j < 4; j++) {
                vA[j] = *(const float4*)(Ax + (size_t)rw[j] * Nn + k0 + qq[j] * 4);
                vB[j] = *(const float4*)(Bx + (size_t)rw[j] * Nn + k0 + qq[j] * 4);
                if (diag) rsum[j] += (vA[j].x + vA[j].y) + (vA[j].z + vA[j].w);
            }
        }
        compute_nt2(smb + (i & 1) * STAGE_NT2, wm, wn, lane, acc);
        __syncthreads();
    }

    if (diag) {
#pragma unroll
        for (int j = 0; j < 4; j++) {
            float s = rsum[j];
            s += __shfl_xor_sync(0xffffffffu, s, 1);
            s += __shfl_xor_sync(0xffffffffu, s, 2);
            s += __shfl_xor_sync(0xffffffffu, s, 4);
            if (qq[j] == 0)
                g_sxp[((size_t)kz * Bb + bz) * Cc + bx * 128 + rw[j]] = s;
        }
    }

    float* sC = (float*)dsm;
#pragma unroll
    for (int ti = 0; ti < 2; ti++)
#pragma unroll
        for (int j = 0; j < 8; j++) {
            int row0 = wm * 32 + ti * 16 + (lane >> 2);
            int col  = wn * 64 + j * 8 + (lane & 3) * 2;
            *(float2*)(sC + row0 * 132 + col)       = make_float2(acc[ti][j][0], acc[ti][j][1]);
            *(float2*)(sC + (row0 + 8) * 132 + col) = make_float2(acc[ti][j][2], acc[ti][j][3]);
        }
    __syncthreads();

    float* outp = g_Sp + (((size_t)kz * Bb + bz) * 6 + pair) * 16384;
    const int r0 = tid >> 1, half = tid & 1;
    const float* src = sC + r0 * 132 + half * 64;
#pragma unroll
    for (int j = 0; j < 64; j += 4)
        *(float4*)(outp + r0 * 128 + half * 64 + j) = *(const float4*)(src + j);
}

// ---------------------------------------------------------------------------
// S reduce. grid (16 subtiles, 6 pairs, 16 batch)
// ---------------------------------------------------------------------------
__global__ void __launch_bounds__(256) k_Sreduce() {
    __shared__ float t[32][33];
    const int pxl[6] = {0,0,0,1,1,2}, pyl[6] = {0,1,2,1,2,2};
    const int sub = blockIdx.x, pair = blockIdx.y, bz = blockIdx.z;
    const int px = pxl[pair], py = pyl[pair];
    const int si = sub >> 2, sj = sub & 3;
    const int cc = threadIdx.x & 31, rb = threadIdx.x >> 5;

    const size_t stride = (size_t)Bb * 6 * 16384;
    const float* p0 = g_Sp + ((size_t)bz * 6 + pair) * 16384;
    const float* p1 = p0 + stride;
    const float* p2 = p0 + 2 * stride;
    const size_t gb = (size_t)bz * Cc * Cc;

#pragma unroll
    for (int r = 0; r < 4; r++) {
        int rr = rb + r * 8;
        int li = (si * 32 + rr) * 128 + sj * 32 + cc;
        float s = p0[li] + p1[li] + p2[li];
        t[rr][cc] = s;
        __half hv = __float2half_rn(s);
        size_t o = gb + (size_t)(px * 128 + si * 32 + rr) * Cc + py * 128 + sj * 32 + cc;
        g_Sh[o] = hv;
        g_Sl[o] = __float2half_rn(s - __half2float(hv));
    }
    if (px == py) return;
    __syncthreads();
#pragma unroll
    for (int r = 0; r < 4; r++) {
        int rr = rb + r * 8;
        float s = t[cc][rr];
        __half hv = __float2half_rn(s);
        size_t o = gb + (size_t)(py * 128 + sj * 32 + rr) * Cc + px * 128 + si * 32 + cc;
        g_Sh[o] = hv;
        g_Sl[o] = __float2half_rn(s - __half2float(hv));
    }
}

// ---------------------------------------------------------------------------
// U GEMM (fused U1+U2), 3-pass, W split inline. grid (6,3,16).
// ---------------------------------------------------------------------------
__global__ void __launch_bounds__(256) gemm_U(const float* __restrict__ w1,
                                              const float* __restrict__ w2) {
    extern __shared__ char dsm[];
    const int tid = threadIdx.x, lane = tid & 31, wid = tid >> 5;
    const int wm = wid & 3, wn = wid >> 2;
    const int sel = blockIdx.x >= 3;
    const int bx = blockIdx.x - (sel ? 3 : 0);
    const int by = blockIdx.y, bz = blockIdx.z;
    const uint32_t smb = smem_u32(dsm);

    const float* Aw = (sel ? w2 : w1) + (size_t)bx * 128 * Cc;
    const __half* pBh = g_Sh + (size_t)bz * Cc * Cc + (size_t)by * 128 * Cc;
    const __half* pBl = g_Sl + (size_t)bz * Cc * Cc + (size_t)by * 128 * Cc;
    float* Cf = sel ? g_U2 : g_U1;

    int rw[4], qq[4];
#pragma unroll
    for (int j = 0; j < 4; j++) { int u = tid + 256 * j; rw[j] = u >> 3; qq[j] = u & 7; }
    int frow[2], fq[2];
#pragma unroll
    for (int j = 0; j < 2; j++) { int u = tid + 256 * j; frow[j] = u >> 2; fq[j] = u & 3; }

    float acc[2][8][4];
#pragma unroll
    for (int i = 0; i < 2; i++)
#pragma unroll
        for (int j = 0; j < 8; j++)
#pragma unroll
            for (int q = 0; q < 4; q++) acc[i][j][q] = 0.f;

    float4 vA[4];
    uint4 vBh[2], vBl[2];
#pragma unroll
    for (int j = 0; j < 4; j++)
        vA[j] = *(const float4*)(Aw + (size_t)rw[j] * Cc + qq[j] * 4);
#pragma unroll
    for (int j = 0; j < 2; j++) {
        vBh[j] = *(const uint4*)(pBh + (size_t)frow[j] * Cc + fq[j] * 8);
        vBl[j] = *(const uint4*)(pBl + (size_t)frow[j] * Cc + fq[j] * 8);
    }
    {
        char* base = dsm;
#pragma unroll
        for (int j = 0; j < 4; j++) {
            int off = rw[j] * SROW80 + qq[j] * 8;
            sts_split4(base + off, base + ATILE + off, vA[j]);
        }
#pragma unroll
        for (int j = 0; j < 2; j++) {
            int off = frow[j] * SROW80 + fq[j] * 16;
            *(uint4*)(base + 2 * ATILE + off) = vBh[j];
            *(uint4*)(base + 3 * ATILE + off) = vBl[j];
        }
    }
#pragma unroll
    for (int j = 0; j < 4; j++)
        vA[j] = *(const float4*)(Aw + (size_t)rw[j] * Cc + 32 + qq[j] * 4);
#pragma unroll
    for (int j = 0; j < 2; j++) {
        vBh[j] = *(const uint4*)(pBh + (size_t)frow[j] * Cc + 32 + fq[j] * 8);
        vBl[j] = *(const uint4*)(pBl + (size_t)frow[j] * Cc + 32 + fq[j] * 8);
    }
    __syncthreads();

    const int nch = Cc / 32;
    for (int i = 0; i < nch; i++) {
        if (i + 1 < nch) {
            char* base = dsm + ((i + 1) & 1) * STAGE_NT3;
#pragma unroll
            for (int j = 0; j < 4; j++) {
                int off = rw[j] * SROW80 + qq[j] * 8;
                sts_split4(base + off, base + ATILE + off, vA[j]);
            }
#pragma unroll
            for (int j = 0; j < 2; j++) {
                int off = frow[j] * SROW80 + fq[j] * 16;
                *(uint4*)(base + 2 * ATILE + off) = vBh[j];
                *(uint4*)(base + 3 * ATILE + off) = vBl[j];
            }
        }
        if (i + 2 < nch) {
            int k0 = (i + 2) * 32;
#pragma unroll
            for (int j = 0; j < 4; j++)
                vA[j] = *(const float4*)(Aw + (size_t)rw[j] * Cc + k0 + qq[j] * 4);
#pragma unroll
            for (int j = 0; j < 2; j++) {
                vBh[j] = *(const uint4*)(pBh + (size_t)frow[j] * Cc + k0 + fq[j] * 8);
                vBl[j] = *(const uint4*)(pBl + (size_t)frow[j] * Cc + k0 + fq[j] * 8);
            }
        }
        compute_nt3(smb + (i & 1) * STAGE_NT3, wm, wn, lane, acc);
        __syncthreads();
    }

    float* sC = (float*)dsm;
#pragma unroll
    for (int ti = 0; ti < 2; ti++)
#pragma unroll
        for (int j = 0; j < 8; j++) {
            int row0 = wm * 32 + ti * 16 + (lane >> 2);
            int col  = wn * 64 + j * 8 + (lane & 3) * 2;
            *(float2*)(sC + row0 * 132 + col)       = make_float2(acc[ti][j][0], acc[ti][j][1]);
            *(float2*)(sC + (row0 + 8) * 132 + col) = make_float2(acc[ti][j][2], acc[ti][j][3]);
        }
    __syncthreads();

    const int r0 = tid >> 1, half = tid & 1;
    const float* src = sC + r0 * 132 + half * 64;
    size_t base = ((size_t)bz * Cc + bx * 128 + r0) * Cc + by * 128 + half * 64;
#pragma unroll
    for (int j = 0; j < 64; j += 4)
        *(float4*)(Cf + base + j) = *(const float4*)(src + j);
}

// ---------------------------------------------------------------------------
// out GEMM, 1-pass, BK=64: out = Mh Xh + mb. grid (3,32,16).
// ---------------------------------------------------------------------------
__global__ void __launch_bounds__(256) gemm_out(const float* __restrict__ x,
                                                float* __restrict__ out)
{
    extern __shared__ char dsm[];
    const int tid = threadIdx.x, lane = tid & 31, wid = tid >> 5;
    const int wm = wid & 3, wn = wid >> 2;
    const int bx = blockIdx.x, by = blockIdx.y, bz = blockIdx.z;
    const uint32_t smb = smem_u32(dsm);

    const __half* pA = g_Mh + (size_t)bz * Cc * Cc + (size_t)bx * 128 * Cc;
    const float* Bx = x + (size_t)bz * Cc * Nn + by * 128;

    int arw[4], aq[4];
#pragma unroll
    for (int j = 0; j < 4; j++) { int u = tid + 256 * j; arw[j] = u >> 3; aq[j] = u & 7; }
    int brw[8], bq[8];
#pragma unroll
    for (int j = 0; j < 8; j++) { int u = tid + 256 * j; brw[j] = u >> 5; bq[j] = u & 31; }

    float acc[2][8][4];
#pragma unroll
    for (int i = 0; i < 2; i++)
#pragma unroll
        for (int j = 0; j < 8; j++)
#pragma unroll
            for (int q = 0; q < 4; q++) acc[i][j][q] = 0.f;

    uint4 vA[4];
    float4 vB[8];
#pragma unroll
    for (int j = 0; j < 4; j++)
        vA[j] = *(const uint4*)(pA + (size_t)arw[j] * Cc + aq[j] * 8);
#pragma unroll
    for (int j = 0; j < 8; j++)
        vB[j] = *(const float4*)(Bx + (size_t)brw[j] * Nn + bq[j] * 4);
    {
        char* base = dsm;
#pragma unroll
        for (int j = 0; j < 4; j++)
            *(uint4*)(base + arw[j] * AROW144 + aq[j] * 16) = vA[j];
#pragma unroll
        for (int j = 0; j < 8; j++)
            sts_cvt4(base + ATILE_O + brw[j] * BPITCH + bq[j] * 8, vB[j]);
    }
#pragma unroll
    for (int j = 0; j < 4; j++)
        vA[j] = *(const uint4*)(pA + (size_t)arw[j] * Cc + 64 + aq[j] * 8);
#pragma unroll
    for (int j = 0; j < 8; j++)
        vB[j] = *(const float4*)(Bx + (size_t)(64 + brw[j]) * Nn + bq[j] * 4);
    __syncthreads();

    const int nch = Cc / 64;
    for (int i = 0; i < nch; i++) {
        if (i + 1 < nch) {
            char* base = dsm + ((i + 1) & 1) * STAGE_O;
#pragma unroll
            for (int j = 0; j < 4; j++)
                *(uint4*)(base + arw[j] * AROW144 + aq[j] * 16) = vA[j];
#pragma unroll
            for (int j = 0; j < 8; j++)
                sts_cvt4(base + ATILE_O + brw[j] * BPITCH + bq[j] * 8, vB[j]);
        }
        if (i + 2 < nch) {
            int k0 = (i + 2) * 64;
#pragma unroll
            for (int j = 0; j < 4; j++)
                vA[j] = *(const uint4*)(pA + (size_t)arw[j] * Cc + k0 + aq[j] * 8);
#pragma unroll
            for (int j = 0; j < 8; j++)
                vB[j] = *(const float4*)(Bx + (size_t)(k0 + brw[j]) * Nn + bq[j] * 4);
        }
        uint32_t st = smb + (i & 1) * STAGE_O;
        compute_o(st, st + ATILE_O, wm, wn, lane, acc);
        __syncthreads();
    }

    float* sC = (float*)dsm;
#pragma unroll
    for (int ti = 0; ti < 2; ti++)
#pragma unroll
        for (int j = 0; j < 8; j++) {
            int row0 = wm * 32 + ti * 16 + (lane >> 2);
            int col  = wn * 64 + j * 8 + (lane & 3) * 2;
            *(float2*)(sC + row0 * 132 + col)       = make_float2(acc[ti][j][0], acc[ti][j][1]);
            *(float2*)(sC + (row0 + 8) * 132 + col) = make_float2(acc[ti][j][2], acc[ti][j][3]);
        }
    __syncthreads();

    const int r0 = tid >> 1, half = tid & 1;
    const float* src = sC + r0 * 132 + half * 64;
    const int grow = bx * 128 + r0;
    float bias = g_mb[bz * Cc + grow];
    size_t base = ((size_t)bz * Cc + grow) * (size_t)Nn + by * 128 + half * 64;
#pragma unroll
    for (int j = 0; j < 64; j += 4) {
        float4 v4 = *(const float4*)(src + j);
        *(float4*)(out + base + j) = make_float4(v4.x + bias, v4.y + bias,
                                                 v4.z + bias, v4.w + bias);
    }
}

// ---------------------------------------------------------------------------
// k_attn: logits (3x3 register-tiled), norms, softmax, mb, A -> g_A.
// grid (HEADS, Bb), 256 threads.
// ---------------------------------------------------------------------------
__global__ void __launch_bounds__(256) k_attn(
    const float* __restrict__ w1, const float* __restrict__ b1,
    const float* __restrict__ w2, const float* __restrict__ b2,
    const float* __restrict__ b3, const float* __restrict__ temp)
{
    const int h = blockIdx.x, b = blockIdx.y;
    const int tid = threadIdx.x;
    const int warp = tid >> 5, lane = tid & 31;

    __shared__ float sU[CH * 65];
    __shared__ float sW[CH * 65];
    __shared__ float sAa[CH * 49];
    __shared__ float sNq[CH], sNk[CH], sP1[CH], sP2[CH];
    __shared__ float sB1[CH], sB2[CH], sB3[CH];
    __shared__ float sSx[Cc];

    const float* U1  = &g_U1[(size_t)b * Cc * Cc + (size_t)h * CH * Cc];
    const float* U2  = &g_U2[(size_t)b * Cc * Cc + (size_t)h * CH * Cc];
    const float* w1h = w1 + (size_t)h * CH * Cc;
    const float* w2h = w2 + (size_t)h * CH * Cc;

    if (tid < CH) {
        sB1[tid] = b1[h * CH + tid];
        sB2[tid] = b2[h * CH + tid];
        sB3[tid] = b3[h * CH + tid];
    }
    for (int i = tid; i < Cc; i += 256)
        sSx[i] = g_sxp[(size_t)b * Cc + i]
               + g_sxp[((size_t)Bb + b) * Cc + i]
               + g_sxp[((size_t)2 * Bb + b) * Cc + i];

    // Phase 1: Gqk via 3x3 register tiles (16x16 thread grid over 48x48)
    const int ci0 = (tid >> 4) * 3, di0 = (tid & 15) * 3;
    float acc[3][3];
#pragma unroll
    for (int i = 0; i < 3; i++)
#pragma unroll
        for (int j = 0; j < 3; j++) acc[i][j] = 0.f;

    for (int k0 = 0; k0 < Cc; k0 += 64) {
        __syncthreads();
        for (int i = tid; i < CH * 64; i += 256) {
            int c = i >> 6, kk = i & 63;
            sU[c * 65 + kk] = U1[c * Cc + k0 + kk];
            sW[c * 65 + kk] = w2h[c * Cc + k0 + kk];
        }
        __syncthreads();
#pragma unroll 8
        for (int kk = 0; kk < 64; kk++) {
            float u[3], w[3];
#pragma unroll
            for (int i = 0; i < 3; i++) u[i] = sU[(ci0 + i) * 65 + kk];
#pragma unroll
            for (int j = 0; j < 3; j++) w[j] = sW[(di0 + j) * 65 + kk];
#pragma unroll
            for (int i = 0; i < 3; i++)
#pragma unroll
                for (int j = 0; j < 3; j++) acc[i][j] += u[i] * w[j];
        }
    }

    // Phase 2: per-row reductions
    __syncthreads();
    for (int c = warp * 6; c < warp * 6 + 6; c++) {
        float aq = 0.f, ak = 0.f, p1 = 0.f, p2 = 0.f;
        for (int k = lane; k < Cc; k += 32) {
            float w1v = w1h[c * Cc + k];
            float w2v = w2h[c * Cc + k];
            aq += U1[c * Cc + k] * w1v;
            ak += U2[c * Cc + k] * w2v;
            float sv = sSx[k];
            p1 += w1v * sv;
            p2 += w2v * sv;
        }
#pragma unroll
        for (int o = 16; o; o >>= 1) {
            aq += __shfl_xor_sync(0xffffffffu, aq, o);
            ak += __shfl_xor_sync(0xffffffffu, ak, o);
            p1 += __shfl_xor_sync(0xffffffffu, p1, o);
            p2 += __shfl_xor_sync(0xffffffffu, p2, o);
        }
        if (lane == 0) { sNq[c] = aq; sNk[c] = ak; sP1[c] = p1; sP2[c] = p2; }
    }
    __syncthreads();

    // Phase 3: normalized logits
    const float tH = temp[h];
#pragma unroll
    for (int i = 0; i < 3; i++) {
        int c = ci0 + i;
        float b1c = sB1[c];
        float nq = sqrtf(fmaxf(sNq[c] + 2.f * b1c * sP1[c] + 4096.f * b1c * b1c, 0.f));
        float invq = tH / fmaxf(nq, 1e-12f);
#pragma unroll
        for (int j = 0; j < 3; j++) {
            int d = di0 + j;
            float b2d = sB2[d];
            float nk = sqrtf(fmaxf(sNk[d] + 2.f * b2d * sP2[d] + 4096.f * b2d * b2d, 0.f));
            float g = acc[i][j] + b1c * sP2[d] + b2d * sP1[c] + 4096.f * b1c * b2d;
            sAa[c * 49 + d] = g / fmaxf(nk, 1e-12f) * invq;
        }
    }
    __syncthreads();

    // Phase 4: row softmax
    for (int c = warp * 6; c < warp * 6 + 6; c++) {
        float a0 = sAa[c * 49 + lane];
        float a1 = (lane < 16) ? sAa[c * 49 + 32 + lane] : -3.402823466e38f;
        float m = fmaxf(a0, a1);
#pragma unroll
        for (int o = 16; o; o >>= 1) m = fmaxf(m, __shfl_xor_sync(0xffffffffu, m, o));
        float e0 = __expf(a0 - m);
        float e1 = (lane < 16) ? __expf(a1 - m) : 0.f;
        float s = e0 + e1;
#pragma unroll
        for (int o = 16; o; o >>= 1) s += __shfl_xor_sync(0xffffffffu, s, o);
        float inv = 1.f / s;
        sAa[c * 49 + lane] = e0 * inv;
        if (lane < 16) sAa[c * 49 + 32 + lane] = e1 * inv;
    }
    __syncthreads();

    // Phase 5: mb = (A+I) b3, and A -> global
    if (tid < CH) {
        float s = sB3[tid];
#pragma unroll 8
        for (int d = 0; d < CH; d++) s += sAa[tid * 49 + d] * sB3[d];
        g_mb[b * Cc + h * CH + tid] = s;
    }
    float* Ag = g_A + ((size_t)b * HEADS + h) * CH * CH;
    for (int i = tid; i < CH * CH; i += 256)
        Ag[i] = sAa[(i / CH) * 49 + (i % CH)];
}

// ---------------------------------------------------------------------------
// k_foldM: M = (A+I)W3 + I -> fp16. grid (3 k-tiles, HEADS, Bb), 256 thr.
// ---------------------------------------------------------------------------
__global__ void __launch_bounds__(256) k_foldM(const float* __restrict__ w3) {
    __shared__ float sA[CH * 49];
    __shared__ float sW[CH * 130];
    const int kt = blockIdx.x, h = blockIdx.y, b = blockIdx.z;
    const int k0 = kt * 128;
    const int tid = threadIdx.x;
    const float* w3h = w3 + (size_t)h * CH * Cc;
    const float* Ag = g_A + ((size_t)b * HEADS + h) * CH * CH;

    for (int i = tid; i < CH * CH; i += 256)
        sA[(i / CH) * 49 + (i % CH)] = Ag[i];
    for (int i = tid; i < CH * 128; i += 256) {
        int d = i >> 7, kk = i & 127;
        sW[d * 130 + kk] = w3h[d * Cc + k0 + kk];
    }
    __syncthreads();

    const int kkl = tid & 127, half = tid >> 7;
    float w[CH];
#pragma unroll 12
    for (int d = 0; d < CH; d++) w[d] = sW[d * 130 + kkl];

    __half* Mrow = g_Mh + (size_t)b * Cc * Cc + (size_t)(h * CH) * Cc + k0 + kkl;
    for (int c = half * 24; c < half * 24 + 24; c++) {
        float s = w[0] * sA[c * 49 + 0] + sW[c * 130 + kkl];   // d=0 term + identity of (A+I)
#pragma unroll 12
        for (int d = 1; d < CH; d++) s += sA[c * 49 + d] * w[d];
        if (h * CH + c == k0 + kkl) s += 1.f;                  // residual fold
        Mrow[(size_t)c * Cc] = __float2half_rn(s);
    }
}

// ---------------------------------------------------------------------------
extern "C" void kernel_launch(void* const* d_in, const int* in_sizes, int n_in,
                              void* d_out, int out_size)
{
    (void)in_sizes; (void)n_in; (void)out_size;
    const float* x    = (const float*)d_in[0];
    const float* w1   = (const float*)d_in[1];
    const float* b1   = (const float*)d_in[2];
    const float* w2   = (const float*)d_in[3];
    const float* b2   = (const float*)d_in[4];
    const float* w3   = (const float*)d_in[5];
    const float* b3   = (const float*)d_in[6];
    const float* temp = (const float*)d_in[7];
    float* out = (float*)d_out;

    cudaFuncSetAttribute(gemm_S,   cudaFuncAttributeMaxDynamicSharedMemorySize, DSMEM_S);
    cudaFuncSetAttribute(gemm_U,   cudaFuncAttributeMaxDynamicSharedMemorySize, DSMEM_U);
    cudaFuncSetAttribute(gemm_out, cudaFuncAttributeMaxDynamicSharedMemorySize, DSMEM_O);

    gemm_S<<<dim3(6, 3, Bb), 256, DSMEM_S>>>(x);
    k_Sreduce<<<dim3(16, 6, Bb), 256>>>();

    gemm_U<<<dim3(6, 3, Bb), 256, DSMEM_U>>>(w1, w2);

    k_attn<<<dim3(HEADS, Bb), 256>>>(w1, b1, w2, b2, b3, temp);
    k_foldM<<<dim3(3, HEADS, Bb), 256>>>(w3);

    gemm_out<<<dim3(3, 32, Bb), 256, DSMEM_O>>>(x, out);
}

// round 9
// speedup vs baseline: 3.0861x; 1.0700x over previous
#include <cuda_runtime.h>
#include <cuda_fp16.h>
#include <math.h>
#include <stdint.h>

#define Bb 16
#define Cc 384
#define Nn 4096
#define HEADS 8
#define CH 48
#define SSZ (Bb*Cc*Cc)

// ---------------- scratch (device globals; allocation-free) ----------------
__device__ __half g_Sh[SSZ];                // S fp16 (hi)
__device__ __half g_Mh[SSZ];                // folded (A+I)W3 + I (fp16 hi)
__device__ __half g_Xh[(size_t)Bb*Cc*Nn];   // x fp16 [b][c][n] (from gemm_S)
__device__ float g_U1[SSZ], g_U2[SSZ];
__device__ float g_Sp[3*Bb*6*16384];        // split-K partial S tiles
__device__ float g_sxp[3*Bb*Cc];            // split-K partial row sums
__device__ float g_mb[Bb*Cc];
__device__ float g_A[Bb*HEADS*CH*CH];       // softmaxed attention matrices
__device__ float g_Gp[3*Bb*HEADS*CH*CH];    // split-K partial Gqk
__device__ float g_rp[3*Bb*HEADS*4*CH];     // split-K partial row reductions

// ---------------- PTX helpers (sm_80-class; no 'a'-gated features) ---------
__device__ __forceinline__ uint32_t smem_u32(const void* p) {
    uint32_t a;
    asm("{ .reg .u64 t; cvta.to.shared.u64 t, %1; cvt.u32.u64 %0, t; }"
        : "=r"(a) : "l"(p));
    return a;
}
__device__ __forceinline__ void ldsm4(uint32_t* r, uint32_t addr) {
    asm volatile("ldmatrix.sync.aligned.m8n8.x4.shared.b16 {%0,%1,%2,%3}, [%4];"
                 : "=r"(r[0]), "=r"(r[1]), "=r"(r[2]), "=r"(r[3]) : "r"(addr));
}
__device__ __forceinline__ void ldsm4t(uint32_t* r, uint32_t addr) {
    asm volatile("ldmatrix.sync.aligned.m8n8.x4.trans.shared.b16 {%0,%1,%2,%3}, [%4];"
                 : "=r"(r[0]), "=r"(r[1]), "=r"(r[2]), "=r"(r[3]) : "r"(addr));
}
__device__ __forceinline__ void mma16816(float* c, const uint32_t* a, const uint32_t* b) {
    asm volatile(
        "mma.sync.aligned.m16n8k16.row.col.f32.f16.f16.f32 "
        "{%0,%1,%2,%3}, {%4,%5,%6,%7}, {%8,%9}, {%0,%1,%2,%3};"
        : "+f"(c[0]), "+f"(c[1]), "+f"(c[2]), "+f"(c[3])
        : "r"(a[0]), "r"(a[1]), "r"(a[2]), "r"(a[3]), "r"(b[0]), "r"(b[1]));
}

// smem geometry
#define SROW80    80
#define ATILE     10240
#define STAGE_NT2 30720     // Ah, Al, Bh (2-pass NT)
#define DSMEM_S   69632
#define AROW144   144
#define ATILE_O   18432
#define BPITCH    272
#define STAGE_O   35840
#define DSMEM_O   71680
#define ATTN1_SM  49920     // 2 * 48 * 130 * 4

// ---------------------------------------------------------------------------
// compute bodies (warp tile 32x64; acc[2][8][4])
// ---------------------------------------------------------------------------
__device__ __forceinline__ void compute_nt2(uint32_t smb, int wm, int wn, int lane,
                                            float acc[2][8][4]) {
    const int grp = lane >> 3, lr = lane & 7;
#pragma unroll
    for (int ks = 0; ks < 2; ks++) {
        const int kc = ks * 16;
        uint32_t ah[2][4], al[2][4];
#pragma unroll
        for (int ti = 0; ti < 2; ti++) {
            int row = wm * 32 + ti * 16 + lr + (grp & 1) * 8;
            int col = kc + (grp >> 1) * 8;
            uint32_t addr = smb + row * SROW80 + col * 2;
            ldsm4(ah[ti], addr);
            ldsm4(al[ti], addr + ATILE);
        }
#pragma unroll
        for (int half = 0; half < 2; half++) {
            uint32_t bhf[4][2];
#pragma unroll
            for (int p = 0; p < 2; p++) {
                int nrow = wn * 64 + half * 32 + p * 16 + (grp >> 1) * 8 + lr;
                int col = kc + (grp & 1) * 8;
                uint32_t r4[4];
                ldsm4(r4, smb + 2 * ATILE + nrow * SROW80 + col * 2);
                bhf[2*p][0] = r4[0]; bhf[2*p][1] = r4[1];
                bhf[2*p+1][0] = r4[2]; bhf[2*p+1][1] = r4[3];
            }
#pragma unroll
            for (int ti = 0; ti < 2; ti++)
#pragma unroll
                for (int tj = 0; tj < 4; tj++) {
                    float* c = acc[ti][half * 4 + tj];
                    mma16816(c, ah[ti], bhf[tj]);
                    mma16816(c, al[ti], bhf[tj]);
                }
        }
    }
}

__device__ __forceinline__ void compute_o(uint32_t smbA, uint32_t smbB,
                                          int wm, int wn, int lane,
                                          float acc[2][8][4]) {
    const int grp = lane >> 3, lr = lane & 7;
#pragma unroll
    for (int ks = 0; ks < 4; ks++) {
        const int kc = ks * 16;
        uint32_t ah[2][4];
#pragma unroll
        for (int ti = 0; ti < 2; ti++) {
            int row = wm * 32 + ti * 16 + lr + (grp & 1) * 8;
            int col = kc + (grp >> 1) * 8;
            ldsm4(ah[ti], smbA + row * AROW144 + col * 2);
        }
#pragma unroll
        for (int half = 0; half < 2; half++) {
            uint32_t bhf[4][2];
#pragma unroll
            for (int p = 0; p < 2; p++) {
                int krow = kc + ((lane >> 3) & 1) * 8 + (lane & 7);
                int ncol = wn * 64 + half * 32 + p * 16 + (lane >> 4) * 8;
                uint32_t r4[4];
                ldsm4t(r4, smbB + krow * BPITCH + ncol * 2);
                bhf[2*p][0] = r4[0]; bhf[2*p][1] = r4[1];
                bhf[2*p+1][0] = r4[2]; bhf[2*p+1][1] = r4[3];
            }
#pragma unroll
            for (int ti = 0; ti < 2; ti++)
#pragma unroll
                for (int tj = 0; tj < 4; tj++)
                    mma16816(acc[ti][half * 4 + tj], ah[ti], bhf[tj]);
        }
    }
}

__device__ __forceinline__ void sts_split4(char* ph, char* pl, float4 f) {
    __half2 h01 = __floats2half2_rn(f.x, f.y);
    __half2 h23 = __floats2half2_rn(f.z, f.w);
    __half2 l01 = __floats2half2_rn(f.x - __half2float(__low2half(h01)),
                                    f.y - __half2float(__high2half(h01)));
    __half2 l23 = __floats2half2_rn(f.z - __half2float(__low2half(h23)),
                                    f.w - __half2float(__high2half(h23)));
    uint2 hh, ll;
    hh.x = *(uint32_t*)&h01; hh.y = *(uint32_t*)&h23;
    ll.x = *(uint32_t*)&l01; ll.y = *(uint32_t*)&l23;
    *(uint2*)ph = hh;
    *(uint2*)pl = ll;
}
// convert fp32x4 -> fp16x4, store to smem, optionally mirror to global
__device__ __forceinline__ void sts_cvt4g(char* p, __half* g, float4 f, bool wr) {
    __half2 h01 = __floats2half2_rn(f.x, f.y);
    __half2 h23 = __floats2half2_rn(f.z, f.w);
    uint2 hh;
    hh.x = *(uint32_t*)&h01; hh.y = *(uint32_t*)&h23;
    *(uint2*)p = hh;
    if (wr) *(uint2*)g = hh;
}

// ---------------------------------------------------------------------------
// S GEMM, triangle + split-K=3, 2-pass. Diag pairs write g_Xh fp16 + rowsums.
// grid (6 pairs, 3 kz, 16 batch)
// ---------------------------------------------------------------------------
__global__ void __launch_bounds__(256) gemm_S(const float* __restrict__ x) {
    extern __shared__ char dsm[];
    const int pxl[6] = {0,0,0,1,1,2}, pyl[6] = {0,1,2,1,2,2};
    const int tid = threadIdx.x, lane = tid & 31, wid = tid >> 5;
    const int wm = wid & 3, wn = wid >> 2;
    const int pair = blockIdx.x, kz = blockIdx.y, bz = blockIdx.z;
    const int bx = pxl[pair], by = pyl[pair];
    const bool diag = (bx == by);
    const int c0 = (kz == 0) ? 0 : (kz == 1 ? 43 : 86);
    const int c1 = (kz == 0) ? 43 : (kz == 1 ? 86 : 128);
    const int nch = c1 - c0;
    const uint32_t smb = smem_u32(dsm);

    const float* Ax = x + ((size_t)bz * Cc + bx * 128) * Nn + c0 * 32;
    const float* Bx = x + ((size_t)bz * Cc + by * 128) * Nn + c0 * 32;
    __half* gXb = g_Xh + ((size_t)bz * Cc + by * 128) * Nn + c0 * 32;

    int rw[4], qq[4];
#pragma unroll
    for (int j = 0; j < 4; j++) { int u = tid + 256 * j; rw[j] = u >> 3; qq[j] = u & 7; }

    float acc[2][8][4];
#pragma unroll
    for (int i = 0; i < 2; i++)
#pragma unroll
        for (int j = 0; j < 8; j++)
#pragma unroll
            for (int q = 0; q < 4; q++) acc[i][j][q] = 0.f;

    float rsum[4] = {0.f, 0.f, 0.f, 0.f};

    float4 vA[4], vB[4];
#pragma unroll
    for (int j = 0; j < 4; j++) {
        vA[j] = *(const float4*)(Ax + (size_t)rw[j] * Nn + qq[j] * 4);
        vB[j] = *(const float4*)(Bx + (size_t)rw[j] * Nn + qq[j] * 4);
        if (diag) rsum[j] += (vA[j].x + vA[j].y) + (vA[j].z + vA[j].w);
    }
    {
        char* base = dsm;
#pragma unroll
        for (int j = 0; j < 4; j++) {
            int off = rw[j] * SROW80 + qq[j] * 8;
            sts_split4(base + off, base + ATILE + off, vA[j]);
            sts_cvt4g(base + 2 * ATILE + off,
                      gXb + (size_t)rw[j] * Nn + qq[j] * 4, vB[j], diag);
        }
    }
#pragma unroll
    for (int j = 0; j < 4; j++) {
        vA[j] = *(const float4*)(Ax + (size_t)rw[j] * Nn + 32 + qq[j] * 4);
        vB[j] = *(const float4*)(Bx + (size_t)rw[j] * Nn + 32 + qq[j] * 4);
        if (diag) rsum[j] += (vA[j].x + vA[j].y) + (vA[j].z + vA[j].w);
    }
    __syncthreads();

    for (int i = 0; i < nch; i++) {
        if (i + 1 < nch) {
            char* base = dsm + ((i + 1) & 1) * STAGE_NT2;
            int k0 = (i + 1) * 32;
#pragma unroll
            for (int j = 0; j < 4; j++) {
                int off = rw[j] * SROW80 + qq[j] * 8;
                sts_split4(base + off, base + ATILE + off, vA[j]);
                sts_cvt4g(base + 2 * ATILE + off,
                          gXb + (size_t)rw[j] * Nn + k0 + qq[j] * 4, vB[j], diag);
            }
        }
        if (i + 2 < nch) {
            int k0 = (i + 2) * 32;
#pragma unroll
            for (int j = 0; j < 4; j++) {
                vA[j] = *(const float4*)(Ax + (size_t)rw[j] * Nn + k0 + qq[j] * 4);
                vB[j] = *(const float4*)(Bx + (size_t)rw[j] * Nn + k0 + qq[j] * 4);
                if (diag) rsum[j] += (vA[j].x + vA[j].y) + (vA[j].z + vA[j].w);
            }
        }
        compute_nt2(smb + (i & 1) * STAGE_NT2, wm, wn, lane, acc);
        __syncthreads();
    }

    if (diag) {
#pragma unroll
        for (int j = 0; j < 4; j++) {
            float s = rsum[j];
            s += __shfl_xor_sync(0xffffffffu, s, 1);
            s += __shfl_xor_sync(0xffffffffu, s, 2);
            s += __shfl_xor_sync(0xffffffffu, s, 4);
            if (qq[j] == 0)
                g_sxp[((size_t)kz * Bb + bz) * Cc + bx * 128 + rw[j]] = s;
        }
    }

    float* sC = (float*)dsm;
#pragma unroll
    for (int ti = 0; ti < 2; ti++)
#pragma unroll
        for (int j = 0; j < 8; j++) {
            int row0 = wm * 32 + ti * 16 + (lane >> 2);
            int col  = wn * 64 + j * 8 + (lane & 3) * 2;
            *(float2*)(sC + row0 * 132 + col)       = make_float2(acc[ti][j][0], acc[ti][j][1]);
            *(float2*)(sC + (row0 + 8) * 132 + col) = make_float2(acc[ti][j][2], acc[ti][j][3]);
        }
    __syncthreads();

    float* outp = g_Sp + (((size_t)kz * Bb + bz) * 6 + pair) * 16384;
    const int r0 = tid >> 1, half = tid & 1;
    const float* src = sC + r0 * 132 + half * 64;
#pragma unroll
    for (int j = 0; j < 64; j += 4)
        *(float4*)(outp + r0 * 128 + half * 64 + j) = *(const float4*)(src + j);
}

// ---------------------------------------------------------------------------
// S reduce: sum 3 partials -> fp16 Sh (tile + transpose).
// grid (16 subtiles, 6 pairs, 16 batch)
// ---------------------------------------------------------------------------
__global__ void __launch_bounds__(256) k_Sreduce() {
    __shared__ float t[32][33];
    const int pxl[6] = {0,0,0,1,1,2}, pyl[6] = {0,1,2,1,2,2};
    const int sub = blockIdx.x, pair = blockIdx.y, bz = blockIdx.z;
    const int px = pxl[pair], py = pyl[pair];
    const int si = sub >> 2, sj = sub & 3;
    const int cc = threadIdx.x & 31, rb = threadIdx.x >> 5;

    const size_t stride = (size_t)Bb * 6 * 16384;
    const float* p0 = g_Sp + ((size_t)bz * 6 + pair) * 16384;
    const float* p1 = p0 + stride;
    const float* p2 = p0 + 2 * stride;
    const size_t gb = (size_t)bz * Cc * Cc;

#pragma unroll
    for (int r = 0; r < 4; r++) {
        int rr = rb + r * 8;
        int li = (si * 32 + rr) * 128 + sj * 32 + cc;
        float s = p0[li] + p1[li] + p2[li];
        t[rr][cc] = s;
        size_t o = gb + (size_t)(px * 128 + si * 32 + rr) * Cc + py * 128 + sj * 32 + cc;
        g_Sh[o] = __float2half_rn(s);
    }
    if (px == py) return;
    __syncthreads();
#pragma unroll
    for (int r = 0; r < 4; r++) {
        int rr = rb + r * 8;
        float s = t[cc][rr];
        size_t o = gb + (size_t)(py * 128 + sj * 32 + rr) * Cc + px * 128 + si * 32 + cc;
        g_Sh[o] = __float2half_rn(s);
    }
}

// ---------------------------------------------------------------------------
// U GEMM (fused U1+U2), 2-pass: U = (Wh+Wl) Sh. grid (6,3,16).
// ---------------------------------------------------------------------------
__global__ void __launch_bounds__(256) gemm_U(const float* __restrict__ w1,
                                              const float* __restrict__ w2) {
    extern __shared__ char dsm[];
    const int tid = threadIdx.x, lane = tid & 31, wid = tid >> 5;
    const int wm = wid & 3, wn = wid >> 2;
    const int sel = blockIdx.x >= 3;
    const int bx = blockIdx.x - (sel ? 3 : 0);
    const int by = blockIdx.y, bz = blockIdx.z;
    const uint32_t smb = smem_u32(dsm);

    const float* Aw = (sel ? w2 : w1) + (size_t)bx * 128 * Cc;
    const __half* pBh = g_Sh + (size_t)bz * Cc * Cc + (size_t)by * 128 * Cc;
    float* Cf = sel ? g_U2 : g_U1;

    int rw[4], qq[4];
#pragma unroll
    for (int j = 0; j < 4; j++) { int u = tid + 256 * j; rw[j] = u >> 3; qq[j] = u & 7; }
    int frow[2], fq[2];
#pragma unroll
    for (int j = 0; j < 2; j++) { int u = tid + 256 * j; frow[j] = u >> 2; fq[j] = u & 3; }

    float acc[2][8][4];
#pragma unroll
    for (int i = 0; i < 2; i++)
#pragma unroll
        for (int j = 0; j < 8; j++)
#pragma unroll
            for (int q = 0; q < 4; q++) acc[i][j][q] = 0.f;

    float4 vA[4];
    uint4 vBh[2];
#pragma unroll
    for (int j = 0; j < 4; j++)
        vA[j] = *(const float4*)(Aw + (size_t)rw[j] * Cc + qq[j] * 4);
#pragma unroll
    for (int j = 0; j < 2; j++)
        vBh[j] = *(const uint4*)(pBh + (size_t)frow[j] * Cc + fq[j] * 8);
    {
        char* base = dsm;
#pragma unroll
        for (int j = 0; j < 4; j++) {
            int off = rw[j] * SROW80 + qq[j] * 8;
            sts_split4(base + off, base + ATILE + off, vA[j]);
        }
#pragma unroll
        for (int j = 0; j < 2; j++)
            *(uint4*)(base + 2 * ATILE + frow[j] * SROW80 + fq[j] * 16) = vBh[j];
    }
#pragma unroll
    for (int j = 0; j < 4; j++)
        vA[j] = *(const float4*)(Aw + (size_t)rw[j] * Cc + 32 + qq[j] * 4);
#pragma unroll
    for (int j = 0; j < 2; j++)
        vBh[j] = *(const uint4*)(pBh + (size_t)frow[j] * Cc + 32 + fq[j] * 8);
    __syncthreads();

    const int nch = Cc / 32;
    for (int i = 0; i < nch; i++) {
        if (i + 1 < nch) {
            char* base = dsm + ((i + 1) & 1) * STAGE_NT2;
#pragma unroll
            for (int j = 0; j < 4; j++) {
                int off = rw[j] * SROW80 + qq[j] * 8;
                sts_split4(base + off, base + ATILE + off, vA[j]);
            }
#pragma unroll
            for (int j = 0; j < 2; j++)
                *(uint4*)(base + 2 * ATILE + frow[j] * SROW80 + fq[j] * 16) = vBh[j];
        }
        if (i + 2 < nch) {
            int k0 = (i + 2) * 32;
#pragma unroll
            for (int j = 0; j < 4; j++)
                vA[j] = *(const float4*)(Aw + (size_t)rw[j] * Cc + k0 + qq[j] * 4);
#pragma unroll
            for (int j = 0; j < 2; j++)
                vBh[j] = *(const uint4*)(pBh + (size_t)frow[j] * Cc + k0 + fq[j] * 8);
        }
        compute_nt2(smb + (i & 1) * STAGE_NT2, wm, wn, lane, acc);
        __syncthreads();
    }

    float* sC = (float*)dsm;
#pragma unroll
    for (int ti = 0; ti < 2; ti++)
#pragma unroll
        for (int j = 0; j < 8; j++) {
            int row0 = wm * 32 + ti * 16 + (lane >> 2);
            int col  = wn * 64 + j * 8 + (lane & 3) * 2;
            *(float2*)(sC + row0 * 132 + col)       = make_float2(acc[ti][j][0], acc[ti][j][1]);
            *(float2*)(sC + (row0 + 8) * 132 + col) = make_float2(acc[ti][j][2], acc[ti][j][3]);
        }
    __syncthreads();

    const int r0 = tid >> 1, half = tid & 1;
    const float* src = sC + r0 * 132 + half * 64;
    size_t base = ((size_t)bz * Cc + bx * 128 + r0) * Cc + by * 128 + half * 64;
#pragma unroll
    for (int j = 0; j < 64; j += 4)
        *(float4*)(Cf + base + j) = *(const float4*)(src + j);
}

// ---------------------------------------------------------------------------
// out GEMM, 1-pass, BK=64, fp16 B from g_Xh: out = Mh Xh + mb. grid (3,32,16).
// ---------------------------------------------------------------------------
__global__ void __launch_bounds__(256) gemm_out(float* __restrict__ out)
{
    extern __shared__ char dsm[];
    const int tid = threadIdx.x, lane = tid & 31, wid = tid >> 5;
    const int wm = wid & 3, wn = wid >> 2;
    const int bx = blockIdx.x, by = blockIdx.y, bz = blockIdx.z;
    const uint32_t smb = smem_u32(dsm);

    const __half* pA = g_Mh + (size_t)bz * Cc * Cc + (size_t)bx * 128 * Cc;
    const __half* pB = g_Xh + (size_t)bz * Cc * Nn + by * 128;

    int arw[4], aq[4];
#pragma unroll
    for (int j = 0; j < 4; j++) { int u = tid + 256 * j; arw[j] = u >> 3; aq[j] = u & 7; }
    // B loader: 64 k-rows x 128 n fp16 -> 1024 uint4 -> 4/thread
    int brw[4], bq[4];
#pragma unroll
    for (int j = 0; j < 4; j++) { int u = tid + 256 * j; brw[j] = u >> 4; bq[j] = u & 15; }

    float acc[2][8][4];
#pragma unroll
    for (int i = 0; i < 2; i++)
#pragma unroll
        for (int j = 0; j < 8; j++)
#pragma unroll
            for (int q = 0; q < 4; q++) acc[i][j][q] = 0.f;

    uint4 vA[4], vB[4];
#pragma unroll
    for (int j = 0; j < 4; j++) {
        vA[j] = *(const uint4*)(pA + (size_t)arw[j] * Cc + aq[j] * 8);
        vB[j] = *(const uint4*)(pB + (size_t)brw[j] * Nn + bq[j] * 8);
    }
    {
        char* base = dsm;
#pragma unroll
        for (int j = 0; j < 4; j++) {
            *(uint4*)(base + arw[j] * AROW144 + aq[j] * 16) = vA[j];
            *(uint4*)(base + ATILE_O + brw[j] * BPITCH + bq[j] * 16) = vB[j];
        }
    }
#pragma unroll
    for (int j = 0; j < 4; j++) {
        vA[j] = *(const uint4*)(pA + (size_t)arw[j] * Cc + 64 + aq[j] * 8);
        vB[j] = *(const uint4*)(pB + (size_t)(64 + brw[j]) * Nn + bq[j] * 8);
    }
    __syncthreads();

    const int nch = Cc / 64;
    for (int i = 0; i < nch; i++) {
        if (i + 1 < nch) {
            char* base = dsm + ((i + 1) & 1) * STAGE_O;
#pragma unroll
            for (int j = 0; j < 4; j++) {
                *(uint4*)(base + arw[j] * AROW144 + aq[j] * 16) = vA[j];
                *(uint4*)(base + ATILE_O + brw[j] * BPITCH + bq[j] * 16) = vB[j];
            }
        }
        if (i + 2 < nch) {
            int k0 = (i + 2) * 64;
#pragma unroll
            for (int j = 0; j < 4; j++) {
                vA[j] = *(const uint4*)(pA + (size_t)arw[j] * Cc + k0 + aq[j] * 8);
                vB[j] = *(const uint4*)(pB + (size_t)(k0 + brw[j]) * Nn + bq[j] * 8);
            }
        }
        uint32_t st = smb + (i & 1) * STAGE_O;
        compute_o(st, st + ATILE_O, wm, wn, lane, acc);
        __syncthreads();
    }

    float* sC = (float*)dsm;
#pragma unroll
    for (int ti = 0; ti < 2; ti++)
#pragma unroll
        for (int j = 0; j < 8; j++) {
            int row0 = wm * 32 + ti * 16 + (lane >> 2);
            int col  = wn * 64 + j * 8 + (lane & 3) * 2;
            *(float2*)(sC + row0 * 132 + col)       = make_float2(acc[ti][j][0], acc[ti][j][1]);
            *(float2*)(sC + (row0 + 8) * 132 + col) = make_float2(acc[ti][j][2], acc[ti][j][3]);
        }
    __syncthreads();

    const int r0 = tid >> 1, half = tid & 1;
    const float* src = sC + r0 * 132 + half * 64;
    const int grow = bx * 128 + r0;
    float bias = g_mb[bz * Cc + grow];
    size_t base = ((size_t)bz * Cc + grow) * (size_t)Nn + by * 128 + half * 64;
#pragma unroll
    for (int j = 0; j < 64; j += 4) {
        float4 v4 = *(const float4*)(src + j);
        *(float4*)(out + base + j) = make_float4(v4.x + bias, v4.y + bias,
                                                 v4.z + bias, v4.w + bias);
    }
}

// ---------------------------------------------------------------------------
// k_attn1: split-K partial Gqk + partial row reductions. grid (3, HEADS, Bb).
// ---------------------------------------------------------------------------
__global__ void __launch_bounds__(256) k_attn1(
    const float* __restrict__ w1, const float* __restrict__ w2)
{
    extern __shared__ float satt[];       // sU[48*130], sW[48*130]
    float* sU = satt;
    float* sW = satt + CH * 130;

    const int kt = blockIdx.x, h = blockIdx.y, b = blockIdx.z;
    const int k0 = kt * 128;
    const int tid = threadIdx.x;
    const int warp = tid >> 5, lane = tid & 31;

    const float* U1  = &g_U1[(size_t)b * Cc * Cc + (size_t)h * CH * Cc];
    const float* U2  = &g_U2[(size_t)b * Cc * Cc + (size_t)h * CH * Cc];
    const float* w1h = w1 + (size_t)h * CH * Cc;
    const float* w2h = w2 + (size_t)h * CH * Cc;

    // stage U1, w2 chunks
    for (int i = tid; i < CH * 128; i += 256) {
        int c = i >> 7, kk = i & 127;
        sU[c * 130 + kk] = U1[c * Cc + k0 + kk];
        sW[c * 130 + kk] = w2h[c * Cc + k0 + kk];
    }
    __syncthreads();

    // partial Gqk: 3x3 register tiles
    const int ci0 = (tid >> 4) * 3, di0 = (tid & 15) * 3;
    float acc[3][3];
#pragma unroll
    for (int i = 0; i < 3; i++)
#pragma unroll
        for (int j = 0; j < 3; j++) acc[i][j] = 0.f;
#pragma unroll 8
    for (int kk = 0; kk < 128; kk++) {
        float u[3], w[3];
#pragma unroll
        for (int i = 0; i < 3; i++) u[i] = sU[(ci0 + i) * 130 + kk];
#pragma unroll
        for (int j = 0; j < 3; j++) w[j] = sW[(di0 + j) * 130 + kk];
#pragma unroll
        for (int i = 0; i < 3; i++)
#pragma unroll
            for (int j = 0; j < 3; j++) acc[i][j] += u[i] * w[j];
    }
    float* Gp = g_Gp + (((size_t)kt * Bb + b) * HEADS + h) * (CH * CH);
#pragma unroll
    for (int i = 0; i < 3; i++)
#pragma unroll
        for (int j = 0; j < 3; j++)
            Gp[(ci0 + i) * CH + di0 + j] = acc[i][j];

    // partial row reductions over this k-slice
    float* rp = g_rp + (((size_t)kt * Bb + b) * HEADS + h) * (4 * CH);
    for (int c = warp * 6; c < warp * 6 + 6; c++) {
        float aq = 0.f, ak = 0.f, p1 = 0.f, p2 = 0.f;
#pragma unroll
        for (int it = 0; it < 4; it++) {
            int k = k0 + lane + it * 32;
            float w1v = w1h[c * Cc + k];
            float w2v = w2h[c * Cc + k];
            aq += U1[c * Cc + k] * w1v;
            ak += U2[c * Cc + k] * w2v;
            float sv = g_sxp[(size_t)b * Cc + k]
                     + g_sxp[((size_t)Bb + b) * Cc + k]
                     + g_sxp[((size_t)2 * Bb + b) * Cc + k];
            p1 += w1v * sv;
            p2 += w2v * sv;
        }
#pragma unroll
        for (int o = 16; o; o >>= 1) {
            aq += __shfl_xor_sync(0xffffffffu, aq, o);
            ak += __shfl_xor_sync(0xffffffffu, ak, o);
            p1 += __shfl_xor_sync(0xffffffffu, p1, o);
            p2 += __shfl_xor_sync(0xffffffffu, p2, o);
        }
        if (lane == 0) {
            rp[0 * CH + c] = aq;
            rp[1 * CH + c] = ak;
            rp[2 * CH + c] = p1;
            rp[3 * CH + c] = p2;
        }
    }
}

// ---------------------------------------------------------------------------
// k_attn2: combine partials, normalize, softmax, mb, A. grid (HEADS, Bb).
// ---------------------------------------------------------------------------
__global__ void __launch_bounds__(256) k_attn2(
    const float* __restrict__ b1, const float* __restrict__ b2,
    const float* __restrict__ b3, const float* __restrict__ temp)
{
    const int h = blockIdx.x, b = blockIdx.y;
    const int tid = threadIdx.x;
    const int warp = tid >> 5, lane = tid & 31;

    __shared__ float sAa[CH * 49];
    __shared__ float sNq[CH], sNk[CH], sP1[CH], sP2[CH];
    __shared__ float sB1[CH], sB2[CH], sB3[CH];

    const size_t gstr = (size_t)Bb * HEADS * CH * CH;
    const size_t rstr = (size_t)Bb * HEADS * 4 * CH;
    const float* Gp = g_Gp + ((size_t)b * HEADS + h) * (CH * CH);
    const float* rp = g_rp + ((size_t)b * HEADS + h) * (4 * CH);

    if (tid < CH) {
        sB1[tid] = b1[h * CH + tid];
        sB2[tid] = b2[h * CH + tid];
        sB3[tid] = b3[h * CH + tid];
        sNq[tid] = rp[0 * CH + tid] + rp[rstr + 0 * CH + tid] + rp[2 * rstr + 0 * CH + tid];
        sNk[tid] = rp[1 * CH + tid] + rp[rstr + 1 * CH + tid] + rp[2 * rstr + 1 * CH + tid];
        sP1[tid] = rp[2 * CH + tid] + rp[rstr + 2 * CH + tid] + rp[2 * rstr + 2 * CH + tid];
        sP2[tid] = rp[3 * CH + tid] + rp[rstr + 3 * CH + tid] + rp[2 * rstr + 3 * CH + tid];
    }
    __syncthreads();

    const float tH = temp[h];
#pragma unroll
    for (int e = 0; e < 9; e++) {
        int idx = tid + 256 * e;
        int c = idx / CH, d = idx - c * CH;
        float g = Gp[idx] + Gp[gstr + idx] + Gp[2 * gstr + idx];
        float b1c = sB1[c], b2d = sB2[d];
        float nq = sqrtf(fmaxf(sNq[c] + 2.f * b1c * sP1[c] + 4096.f * b1c * b1c, 0.f));
        float nk = sqrtf(fmaxf(sNk[d] + 2.f * b2d * sP2[d] + 4096.f * b2d * b2d, 0.f));
        g = g + b1c * sP2[d] + b2d * sP1[c] + 4096.f * b1c * b2d;
        sAa[c * 49 + d] = g / (fmaxf(nq, 1e-12f) * fmaxf(nk, 1e-12f)) * tH;
    }
    __syncthreads();

    for (int c = warp * 6; c < warp * 6 + 6; c++) {
        float a0 = sAa[c * 49 + lane];
        float a1 = (lane < 16) ? sAa[c * 49 + 32 + lane] : -3.402823466e38f;
        float m = fmaxf(a0, a1);
#pragma unroll
        for (int o = 16; o; o >>= 1) m = fmaxf(m, __shfl_xor_sync(0xffffffffu, m, o));
        float e0 = __expf(a0 - m);
        float e1 = (lane < 16) ? __expf(a1 - m) : 0.f;
        float s = e0 + e1;
#pragma unroll
        for (int o = 16; o; o >>= 1) s += __shfl_xor_sync(0xffffffffu, s, o);
        float inv = 1.f / s;
        sAa[c * 49 + lane] = e0 * inv;
        if (lane < 16) sAa[c * 49 + 32 + lane] = e1 * inv;
    }
    __syncthreads();

    if (tid < CH) {
        float s = sB3[tid];
#pragma unroll 8
        for (int d = 0; d < CH; d++) s += sAa[tid * 49 + d] * sB3[d];
        g_mb[b * Cc + h * CH + tid] = s;
    }
    float* Ag = g_A + ((size_t)b * HEADS + h) * CH * CH;
    for (int i = tid; i < CH * CH; i += 256)
        Ag[i] = sAa[(i / CH) * 49 + (i % CH)];
}

// ---------------------------------------------------------------------------
// k_foldM: M = (A+I)W3 + I -> fp16. grid (3, HEADS, Bb).
// ---------------------------------------------------------------------------
__global__ void __launch_bounds__(256) k_foldM(const float* __restrict__ w3) {
    __shared__ float sA[CH * 49];
    __shared__ float sW[CH * 130];
    const int kt = blockIdx.x, h = blockIdx.y, b = blockIdx.z;
    const int k0 = kt * 128;
    const int tid = threadIdx.x;
    const float* w3h = w3 + (size_t)h * CH * Cc;
    const float* Ag = g_A + ((size_t)b * HEADS + h) * CH * CH;

    for (int i = tid; i < CH * CH; i += 256)
        sA[(i / CH) * 49 + (i % CH)] = Ag[i];
    for (int i = tid; i < CH * 128; i += 256) {
        int d = i >> 7, kk = i & 127;
        sW[d * 130 + kk] = w3h[d * Cc + k0 + kk];
    }
    __syncthreads();

    const int kkl = tid & 127, half = tid >> 7;
    float w[CH];
#pragma unroll 12
    for (int d = 0; d < CH; d++) w[d] = sW[d * 130 + kkl];

    __half* Mrow = g_Mh + (size_t)b * Cc * Cc + (size_t)(h * CH) * Cc + k0 + kkl;
    for (int c = half * 24; c < half * 24 + 24; c++) {
        float s = w[0] * sA[c * 49 + 0] + sW[c * 130 + kkl];
#pragma unroll 12
        for (int d = 1; d < CH; d++) s += sA[c * 49 + d] * w[d];
        if (h * CH + c == k0 + kkl) s += 1.f;
        Mrow[(size_t)c * Cc] = __float2half_rn(s);
    }
}

// ---------------------------------------------------------------------------
extern "C" void kernel_launch(void* const* d_in, const int* in_sizes, int n_in,
                              void* d_out, int out_size)
{
    (void)in_sizes; (void)n_in; (void)out_size;
    const float* x    = (const float*)d_in[0];
    const float* w1   = (const float*)d_in[1];
    const float* b1   = (const float*)d_in[2];
    const float* w2   = (const float*)d_in[3];
    const float* b2   = (const float*)d_in[4];
    const float* w3   = (const float*)d_in[5];
    const float* b3   = (const float*)d_in[6];
    const float* temp = (const float*)d_in[7];
    float* out = (float*)d_out;

    cudaFuncSetAttribute(gemm_S,   cudaFuncAttributeMaxDynamicSharedMemorySize, DSMEM_S);
    cudaFuncSetAttribute(gemm_U,   cudaFuncAttributeMaxDynamicSharedMemorySize, DSMEM_S);
    cudaFuncSetAttribute(gemm_out, cudaFuncAttributeMaxDynamicSharedMemorySize, DSMEM_O);
    cudaFuncSetAttribute(k_attn1,  cudaFuncAttributeMaxDynamicSharedMemorySize, ATTN1_SM);

    gemm_S<<<dim3(6, 3, Bb), 256, DSMEM_S>>>(x);
    k_Sreduce<<<dim3(16, 6, Bb), 256>>>();

    gemm_U<<<dim3(6, 3, Bb), 256, DSMEM_S>>>(w1, w2);

    k_attn1<<<dim3(3, HEADS, Bb), 256, ATTN1_SM>>>(w1, w2);
    k_attn2<<<dim3(HEADS, Bb), 256>>>(b1, b2, b3, temp);
    k_foldM<<<dim3(3, HEADS, Bb), 256>>>(w3);

    gemm_out<<<dim3(3, 32, Bb), 256, DSMEM_O>>>(out);
}

// round 10
// speedup vs baseline: 3.4710x; 1.1247x over previous
#include <cuda_runtime.h>
#include <cuda_fp16.h>
#include <math.h>
#include <stdint.h>

#define Bb 16
#define Cc 384
#define Nn 4096
#define HEADS 8
#define CH 48
#define SSZ (Bb*Cc*Cc)

// ---------------- scratch (device globals; allocation-free) ----------------
__device__ __half g_Sh[SSZ];                // S fp16
__device__ __half g_Mh[SSZ];                // folded (A+I)W3 + I (fp16)
__device__ __half g_Xh[(size_t)Bb*Cc*Nn];   // x fp16 [b][c][n] (from gemm_S)
__device__ float g_U1[SSZ], g_U2[SSZ];
__device__ float g_Sp[3*Bb*6*16384];        // split-K partial S tiles
__device__ float g_sxp[3*Bb*Cc];            // split-K partial row sums
__device__ float g_mb[Bb*Cc];
__device__ float g_Gp[3*Bb*HEADS*CH*CH];    // split-K partial Gqk
__device__ float g_rp[3*Bb*HEADS*4*CH];     // split-K partial row reductions

// ---------------- PTX helpers (sm_80-class; no 'a'-gated features) ---------
__device__ __forceinline__ uint32_t smem_u32(const void* p) {
    uint32_t a;
    asm("{ .reg .u64 t; cvta.to.shared.u64 t, %1; cvt.u32.u64 %0, t; }"
        : "=r"(a) : "l"(p));
    return a;
}
__device__ __forceinline__ void ldsm4(uint32_t* r, uint32_t addr) {
    asm volatile("ldmatrix.sync.aligned.m8n8.x4.shared.b16 {%0,%1,%2,%3}, [%4];"
                 : "=r"(r[0]), "=r"(r[1]), "=r"(r[2]), "=r"(r[3]) : "r"(addr));
}
__device__ __forceinline__ void ldsm4t(uint32_t* r, uint32_t addr) {
    asm volatile("ldmatrix.sync.aligned.m8n8.x4.trans.shared.b16 {%0,%1,%2,%3}, [%4];"
                 : "=r"(r[0]), "=r"(r[1]), "=r"(r[2]), "=r"(r[3]) : "r"(addr));
}
__device__ __forceinline__ void mma16816(float* c, const uint32_t* a, const uint32_t* b) {
    asm volatile(
        "mma.sync.aligned.m16n8k16.row.col.f32.f16.f16.f32 "
        "{%0,%1,%2,%3}, {%4,%5,%6,%7}, {%8,%9}, {%0,%1,%2,%3};"
        : "+f"(c[0]), "+f"(c[1]), "+f"(c[2]), "+f"(c[3])
        : "r"(a[0]), "r"(a[1]), "r"(a[2]), "r"(a[3]), "r"(b[0]), "r"(b[1]));
}

// smem geometry
#define SROW80    80
#define ATILE     10240
#define STAGE_S1  20480     // Ah, Bh (1-pass NT)
#define DSMEM_S   69632
#define AROW144   144
#define ATILE_O   18432
#define BPITCH    272
#define STAGE_O   35840
#define DSMEM_O   71680
#define ATTN1_SM  49920     // 2 * 48 * 130 * 4

// ---------------------------------------------------------------------------
// compute bodies (warp tile 32x64; acc[2][8][4])
// ---------------------------------------------------------------------------
// 1-pass NT: D += Ah Bh^T  (BK=32; A at smb, B at smb+ATILE)
__device__ __forceinline__ void compute_nt1(uint32_t smb, int wm, int wn, int lane,
                                            float acc[2][8][4]) {
    const int grp = lane >> 3, lr = lane & 7;
#pragma unroll
    for (int ks = 0; ks < 2; ks++) {
        const int kc = ks * 16;
        uint32_t ah[2][4];
#pragma unroll
        for (int ti = 0; ti < 2; ti++) {
            int row = wm * 32 + ti * 16 + lr + (grp & 1) * 8;
            int col = kc + (grp >> 1) * 8;
            ldsm4(ah[ti], smb + row * SROW80 + col * 2);
        }
#pragma unroll
        for (int half = 0; half < 2; half++) {
            uint32_t bhf[4][2];
#pragma unroll
            for (int p = 0; p < 2; p++) {
                int nrow = wn * 64 + half * 32 + p * 16 + (grp >> 1) * 8 + lr;
                int col = kc + (grp & 1) * 8;
                uint32_t r4[4];
                ldsm4(r4, smb + ATILE + nrow * SROW80 + col * 2);
                bhf[2*p][0] = r4[0]; bhf[2*p][1] = r4[1];
                bhf[2*p+1][0] = r4[2]; bhf[2*p+1][1] = r4[3];
            }
#pragma unroll
            for (int ti = 0; ti < 2; ti++)
#pragma unroll
                for (int tj = 0; tj < 4; tj++)
                    mma16816(acc[ti][half * 4 + tj], ah[ti], bhf[tj]);
        }
    }
}

__device__ __forceinline__ void compute_o(uint32_t smbA, uint32_t smbB,
                                          int wm, int wn, int lane,
                                          float acc[2][8][4]) {
    const int grp = lane >> 3, lr = lane & 7;
#pragma unroll
    for (int ks = 0; ks < 4; ks++) {
        const int kc = ks * 16;
        uint32_t ah[2][4];
#pragma unroll
        for (int ti = 0; ti < 2; ti++) {
            int row = wm * 32 + ti * 16 + lr + (grp & 1) * 8;
            int col = kc + (grp >> 1) * 8;
            ldsm4(ah[ti], smbA + row * AROW144 + col * 2);
        }
#pragma unroll
        for (int half = 0; half < 2; half++) {
            uint32_t bhf[4][2];
#pragma unroll
            for (int p = 0; p < 2; p++) {
                int krow = kc + ((lane >> 3) & 1) * 8 + (lane & 7);
                int ncol = wn * 64 + half * 32 + p * 16 + (lane >> 4) * 8;
                uint32_t r4[4];
                ldsm4t(r4, smbB + krow * BPITCH + ncol * 2);
                bhf[2*p][0] = r4[0]; bhf[2*p][1] = r4[1];
                bhf[2*p+1][0] = r4[2]; bhf[2*p+1][1] = r4[3];
            }
#pragma unroll
            for (int ti = 0; ti < 2; ti++)
#pragma unroll
                for (int tj = 0; tj < 4; tj++)
                    mma16816(acc[ti][half * 4 + tj], ah[ti], bhf[tj]);
        }
    }
}

__device__ __forceinline__ void sts_cvt4(char* p, float4 f) {
    __half2 h01 = __floats2half2_rn(f.x, f.y);
    __half2 h23 = __floats2half2_rn(f.z, f.w);
    uint2 hh;
    hh.x = *(uint32_t*)&h01; hh.y = *(uint32_t*)&h23;
    *(uint2*)p = hh;
}
__device__ __forceinline__ void sts_cvt4g(char* p, __half* g, float4 f, bool wr) {
    __half2 h01 = __floats2half2_rn(f.x, f.y);
    __half2 h23 = __floats2half2_rn(f.z, f.w);
    uint2 hh;
    hh.x = *(uint32_t*)&h01; hh.y = *(uint32_t*)&h23;
    *(uint2*)p = hh;
    if (wr) *(uint2*)g = hh;
}

// ---------------------------------------------------------------------------
// S GEMM, triangle + split-K=3, 1-pass. Diag pairs write g_Xh fp16 + rowsums.
// grid (6 pairs, 3 kz, 16 batch)
// ---------------------------------------------------------------------------
__global__ void __launch_bounds__(256) gemm_S(const float* __restrict__ x) {
    extern __shared__ char dsm[];
    const int pxl[6] = {0,0,0,1,1,2}, pyl[6] = {0,1,2,1,2,2};
    const int tid = threadIdx.x, lane = tid & 31, wid = tid >> 5;
    const int wm = wid & 3, wn = wid >> 2;
    const int pair = blockIdx.x, kz = blockIdx.y, bz = blockIdx.z;
    const int bx = pxl[pair], by = pyl[pair];
    const bool diag = (bx == by);
    const int c0 = (kz == 0) ? 0 : (kz == 1 ? 43 : 86);
    const int c1 = (kz == 0) ? 43 : (kz == 1 ? 86 : 128);
    const int nch = c1 - c0;
    const uint32_t smb = smem_u32(dsm);

    const float* Ax = x + ((size_t)bz * Cc + bx * 128) * Nn + c0 * 32;
    const float* Bx = x + ((size_t)bz * Cc + by * 128) * Nn + c0 * 32;
    __half* gXb = g_Xh + ((size_t)bz * Cc + by * 128) * Nn + c0 * 32;

    int rw[4], qq[4];
#pragma unroll
    for (int j = 0; j < 4; j++) { int u = tid + 256 * j; rw[j] = u >> 3; qq[j] = u & 7; }

    float acc[2][8][4];
#pragma unroll
    for (int i = 0; i < 2; i++)
#pragma unroll
        for (int j = 0; j < 8; j++)
#pragma unroll
            for (int q = 0; q < 4; q++) acc[i][j][q] = 0.f;

    float rsum[4] = {0.f, 0.f, 0.f, 0.f};

    float4 vA[4], vB[4];
#pragma unroll
    for (int j = 0; j < 4; j++) {
        vA[j] = *(const float4*)(Ax + (size_t)rw[j] * Nn + qq[j] * 4);
        vB[j] = *(const float4*)(Bx + (size_t)rw[j] * Nn + qq[j] * 4);
        if (diag) rsum[j] += (vA[j].x + vA[j].y) + (vA[j].z + vA[j].w);
    }
    {
        char* base = dsm;
#pragma unroll
        for (int j = 0; j < 4; j++) {
            int off = rw[j] * SROW80 + qq[j] * 8;
            sts_cvt4(base + off, vA[j]);
            sts_cvt4g(base + ATILE + off,
                      gXb + (size_t)rw[j] * Nn + qq[j] * 4, vB[j], diag);
        }
    }
#pragma unroll
    for (int j = 0; j < 4; j++) {
        vA[j] = *(const float4*)(Ax + (size_t)rw[j] * Nn + 32 + qq[j] * 4);
        vB[j] = *(const float4*)(Bx + (size_t)rw[j] * Nn + 32 + qq[j] * 4);
        if (diag) rsum[j] += (vA[j].x + vA[j].y) + (vA[j].z + vA[j].w);
    }
    __syncthreads();

    for (int i = 0; i < nch; i++) {
        if (i + 1 < nch) {
            char* base = dsm + ((i + 1) & 1) * STAGE_S1;
            int k0 = (i + 1) * 32;
#pragma unroll
            for (int j = 0; j < 4; j++) {
                int off = rw[j] * SROW80 + qq[j] * 8;
                sts_cvt4(base + off, vA[j]);
                sts_cvt4g(base + ATILE + off,
                          gXb + (size_t)rw[j] * Nn + k0 + qq[j] * 4, vB[j], diag);
            }
        }
        if (i + 2 < nch) {
            int k0 = (i + 2) * 32;
#pragma unroll
            for (int j = 0; j < 4; j++) {
                vA[j] = *(const float4*)(Ax + (size_t)rw[j] * Nn + k0 + qq[j] * 4);
                vB[j] = *(const float4*)(Bx + (size_t)rw[j] * Nn + k0 + qq[j] * 4);
                if (diag) rsum[j] += (vA[j].x + vA[j].y) + (vA[j].z + vA[j].w);
            }
        }
        compute_nt1(smb + (i & 1) * STAGE_S1, wm, wn, lane, acc);
        __syncthreads();
    }

    if (diag) {
#pragma unroll
        for (int j = 0; j < 4; j++) {
            float s = rsum[j];
            s += __shfl_xor_sync(0xffffffffu, s, 1);
            s += __shfl_xor_sync(0xffffffffu, s, 2);
            s += __shfl_xor_sync(0xffffffffu, s, 4);
            if (qq[j] == 0)
                g_sxp[((size_t)kz * Bb + bz) * Cc + bx * 128 + rw[j]] = s;
        }
    }

    float* sC = (float*)dsm;
#pragma unroll
    for (int ti = 0; ti < 2; ti++)
#pragma unroll
        for (int j = 0; j < 8; j++) {
            int row0 = wm * 32 + ti * 16 + (lane >> 2);
            int col  = wn * 64 + j * 8 + (lane & 3) * 2;
            *(float2*)(sC + row0 * 132 + col)       = make_float2(acc[ti][j][0], acc[ti][j][1]);
            *(float2*)(sC + (row0 + 8) * 132 + col) = make_float2(acc[ti][j][2], acc[ti][j][3]);
        }
    __syncthreads();

    float* outp = g_Sp + (((size_t)kz * Bb + bz) * 6 + pair) * 16384;
    const int r0 = tid >> 1, half = tid & 1;
    const float* src = sC + r0 * 132 + half * 64;
#pragma unroll
    for (int j = 0; j < 64; j += 4)
        *(float4*)(outp + r0 * 128 + half * 64 + j) = *(const float4*)(src + j);
}

// ---------------------------------------------------------------------------
// S reduce: sum 3 partials -> fp16 Sh (tile + transpose).
// grid (16 subtiles, 6 pairs, 16 batch)
// ---------------------------------------------------------------------------
__global__ void __launch_bounds__(256) k_Sreduce() {
    __shared__ float t[32][33];
    const int pxl[6] = {0,0,0,1,1,2}, pyl[6] = {0,1,2,1,2,2};
    const int sub = blockIdx.x, pair = blockIdx.y, bz = blockIdx.z;
    const int px = pxl[pair], py = pyl[pair];
    const int si = sub >> 2, sj = sub & 3;
    const int cc = threadIdx.x & 31, rb = threadIdx.x >> 5;

    const size_t stride = (size_t)Bb * 6 * 16384;
    const float* p0 = g_Sp + ((size_t)bz * 6 + pair) * 16384;
    const float* p1 = p0 + stride;
    const float* p2 = p0 + 2 * stride;
    const size_t gb = (size_t)bz * Cc * Cc;

#pragma unroll
    for (int r = 0; r < 4; r++) {
        int rr = rb + r * 8;
        int li = (si * 32 + rr) * 128 + sj * 32 + cc;
        float s = p0[li] + p1[li] + p2[li];
        t[rr][cc] = s;
        size_t o = gb + (size_t)(px * 128 + si * 32 + rr) * Cc + py * 128 + sj * 32 + cc;
        g_Sh[o] = __float2half_rn(s);
    }
    if (px == py) return;
    __syncthreads();
#pragma unroll
    for (int r = 0; r < 4; r++) {
        int rr = rb + r * 8;
        float s = t[cc][rr];
        size_t o = gb + (size_t)(py * 128 + sj * 32 + rr) * Cc + px * 128 + si * 32 + cc;
        g_Sh[o] = __float2half_rn(s);
    }
}

// ---------------------------------------------------------------------------
// U GEMM (fused U1+U2), 1-pass: U = Wh Sh. grid (6,3,16).
// ---------------------------------------------------------------------------
__global__ void __launch_bounds__(256) gemm_U(const float* __restrict__ w1,
                                              const float* __restrict__ w2) {
    extern __shared__ char dsm[];
    const int tid = threadIdx.x, lane = tid & 31, wid = tid >> 5;
    const int wm = wid & 3, wn = wid >> 2;
    const int sel = blockIdx.x >= 3;
    const int bx = blockIdx.x - (sel ? 3 : 0);
    const int by = blockIdx.y, bz = blockIdx.z;
    const uint32_t smb = smem_u32(dsm);

    const float* Aw = (sel ? w2 : w1) + (size_t)bx * 128 * Cc;
    const __half* pBh = g_Sh + (size_t)bz * Cc * Cc + (size_t)by * 128 * Cc;
    float* Cf = sel ? g_U2 : g_U1;

    int rw[4], qq[4];
#pragma unroll
    for (int j = 0; j < 4; j++) { int u = tid + 256 * j; rw[j] = u >> 3; qq[j] = u & 7; }
    int frow[2], fq[2];
#pragma unroll
    for (int j = 0; j < 2; j++) { int u = tid + 256 * j; frow[j] = u >> 2; fq[j] = u & 3; }

    float acc[2][8][4];
#pragma unroll
    for (int i = 0; i < 2; i++)
#pragma unroll
        for (int j = 0; j < 8; j++)
#pragma unroll
            for (int q = 0; q < 4; q++) acc[i][j][q] = 0.f;

    float4 vA[4];
    uint4 vBh[2];
#pragma unroll
    for (int j = 0; j < 4; j++)
        vA[j] = *(const float4*)(Aw + (size_t)rw[j] * Cc + qq[j] * 4);
#pragma unroll
    for (int j = 0; j < 2; j++)
        vBh[j] = *(const uint4*)(pBh + (size_t)frow[j] * Cc + fq[j] * 8);
    {
        char* base = dsm;
#pragma unroll
        for (int j = 0; j < 4; j++)
            sts_cvt4(base + rw[j] * SROW80 + qq[j] * 8, vA[j]);
#pragma unroll
        for (int j = 0; j < 2; j++)
            *(uint4*)(base + ATILE + frow[j] * SROW80 + fq[j] * 16) = vBh[j];
    }
#pragma unroll
    for (int j = 0; j < 4; j++)
        vA[j] = *(const float4*)(Aw + (size_t)rw[j] * Cc + 32 + qq[j] * 4);
#pragma unroll
    for (int j = 0; j < 2; j++)
        vBh[j] = *(const uint4*)(pBh + (size_t)frow[j] * Cc + 32 + fq[j] * 8);
    __syncthreads();

    const int nch = Cc / 32;
    for (int i = 0; i < nch; i++) {
        if (i + 1 < nch) {
            char* base = dsm + ((i + 1) & 1) * STAGE_S1;
#pragma unroll
            for (int j = 0; j < 4; j++)
                sts_cvt4(base + rw[j] * SROW80 + qq[j] * 8, vA[j]);
#pragma unroll
            for (int j = 0; j < 2; j++)
                *(uint4*)(base + ATILE + frow[j] * SROW80 + fq[j] * 16) = vBh[j];
        }
        if (i + 2 < nch) {
            int k0 = (i + 2) * 32;
#pragma unroll
            for (int j = 0; j < 4; j++)
                vA[j] = *(const float4*)(Aw + (size_t)rw[j] * Cc + k0 + qq[j] * 4);
#pragma unroll
            for (int j = 0; j < 2; j++)
                vBh[j] = *(const uint4*)(pBh + (size_t)frow[j] * Cc + k0 + fq[j] * 8);
        }
        compute_nt1(smb + (i & 1) * STAGE_S1, wm, wn, lane, acc);
        __syncthreads();
    }

    float* sC = (float*)dsm;
#pragma unroll
    for (int ti = 0; ti < 2; ti++)
#pragma unroll
        for (int j = 0; j < 8; j++) {
            int row0 = wm * 32 + ti * 16 + (lane >> 2);
            int col  = wn * 64 + j * 8 + (lane & 3) * 2;
            *(float2*)(sC + row0 * 132 + col)       = make_float2(acc[ti][j][0], acc[ti][j][1]);
            *(float2*)(sC + (row0 + 8) * 132 + col) = make_float2(acc[ti][j][2], acc[ti][j][3]);
        }
    __syncthreads();

    const int r0 = tid >> 1, half = tid & 1;
    const float* src = sC + r0 * 132 + half * 64;
    size_t base = ((size_t)bz * Cc + bx * 128 + r0) * Cc + by * 128 + half * 64;
#pragma unroll
    for (int j = 0; j < 64; j += 4)
        *(float4*)(Cf + base + j) = *(const float4*)(src + j);
}

// ---------------------------------------------------------------------------
// out GEMM, 1-pass, BK=64, fp16 B from g_Xh: out = Mh Xh + mb. grid (3,32,16).
// ---------------------------------------------------------------------------
__global__ void __launch_bounds__(256) gemm_out(float* __restrict__ out)
{
    extern __shared__ char dsm[];
    const int tid = threadIdx.x, lane = tid & 31, wid = tid >> 5;
    const int wm = wid & 3, wn = wid >> 2;
    const int bx = blockIdx.x, by = blockIdx.y, bz = blockIdx.z;
    const uint32_t smb = smem_u32(dsm);

    const __half* pA = g_Mh + (size_t)bz * Cc * Cc + (size_t)bx * 128 * Cc;
    const __half* pB = g_Xh + (size_t)bz * Cc * Nn + by * 128;

    int arw[4], aq[4];
#pragma unroll
    for (int j = 0; j < 4; j++) { int u = tid + 256 * j; arw[j] = u >> 3; aq[j] = u & 7; }
    int brw[4], bq[4];
#pragma unroll
    for (int j = 0; j < 4; j++) { int u = tid + 256 * j; brw[j] = u >> 4; bq[j] = u & 15; }

    float acc[2][8][4];
#pragma unroll
    for (int i = 0; i < 2; i++)
#pragma unroll
        for (int j = 0; j < 8; j++)
#pragma unroll
            for (int q = 0; q < 4; q++) acc[i][j][q] = 0.f;

    uint4 vA[4], vB[4];
#pragma unroll
    for (int j = 0; j < 4; j++) {
        vA[j] = *(const uint4*)(pA + (size_t)arw[j] * Cc + aq[j] * 8);
        vB[j] = *(const uint4*)(pB + (size_t)brw[j] * Nn + bq[j] * 8);
    }
    {
        char* base = dsm;
#pragma unroll
        for (int j = 0; j < 4; j++) {
            *(uint4*)(base + arw[j] * AROW144 + aq[j] * 16) = vA[j];
            *(uint4*)(base + ATILE_O + brw[j] * BPITCH + bq[j] * 16) = vB[j];
        }
    }
#pragma unroll
    for (int j = 0; j < 4; j++) {
        vA[j] = *(const uint4*)(pA + (size_t)arw[j] * Cc + 64 + aq[j] * 8);
        vB[j] = *(const uint4*)(pB + (size_t)(64 + brw[j]) * Nn + bq[j] * 8);
    }
    __syncthreads();

    const int nch = Cc / 64;
    for (int i = 0; i < nch; i++) {
        if (i + 1 < nch) {
            char* base = dsm + ((i + 1) & 1) * STAGE_O;
#pragma unroll
            for (int j = 0; j < 4; j++) {
                *(uint4*)(base + arw[j] * AROW144 + aq[j] * 16) = vA[j];
                *(uint4*)(base + ATILE_O + brw[j] * BPITCH + bq[j] * 16) = vB[j];
            }
        }
        if (i + 2 < nch) {
            int k0 = (i + 2) * 64;
#pragma unroll
            for (int j = 0; j < 4; j++) {
                vA[j] = *(const uint4*)(pA + (size_t)arw[j] * Cc + k0 + aq[j] * 8);
                vB[j] = *(const uint4*)(pB + (size_t)(k0 + brw[j]) * Nn + bq[j] * 8);
            }
        }
        uint32_t st = smb + (i & 1) * STAGE_O;
        compute_o(st, st + ATILE_O, wm, wn, lane, acc);
        __syncthreads();
    }

    float* sC = (float*)dsm;
#pragma unroll
    for (int ti = 0; ti < 2; ti++)
#pragma unroll
        for (int j = 0; j < 8; j++) {
            int row0 = wm * 32 + ti * 16 + (lane >> 2);
            int col  = wn * 64 + j * 8 + (lane & 3) * 2;
            *(float2*)(sC + row0 * 132 + col)       = make_float2(acc[ti][j][0], acc[ti][j][1]);
            *(float2*)(sC + (row0 + 8) * 132 + col) = make_float2(acc[ti][j][2], acc[ti][j][3]);
        }
    __syncthreads();

    const int r0 = tid >> 1, half = tid & 1;
    const float* src = sC + r0 * 132 + half * 64;
    const int grow = bx * 128 + r0;
    float bias = g_mb[bz * Cc + grow];
    size_t base = ((size_t)bz * Cc + grow) * (size_t)Nn + by * 128 + half * 64;
#pragma unroll
    for (int j = 0; j < 64; j += 4) {
        float4 v4 = *(const float4*)(src + j);
        *(float4*)(out + base + j) = make_float4(v4.x + bias, v4.y + bias,
                                                 v4.z + bias, v4.w + bias);
    }
}

// ---------------------------------------------------------------------------
// k_attn1: split-K partial Gqk + partial row reductions. grid (3, HEADS, Bb).
// ---------------------------------------------------------------------------
__global__ void __launch_bounds__(256) k_attn1(
    const float* __restrict__ w1, const float* __restrict__ w2)
{
    extern __shared__ float satt[];       // sU[48*130], sW[48*130]
    float* sU = satt;
    float* sW = satt + CH * 130;

    const int kt = blockIdx.x, h = blockIdx.y, b = blockIdx.z;
    const int k0 = kt * 128;
    const int tid = threadIdx.x;
    const int warp = tid >> 5, lane = tid & 31;

    const float* U1  = &g_U1[(size_t)b * Cc * Cc + (size_t)h * CH * Cc];
    const float* U2  = &g_U2[(size_t)b * Cc * Cc + (size_t)h * CH * Cc];
    const float* w1h = w1 + (size_t)h * CH * Cc;
    const float* w2h = w2 + (size_t)h * CH * Cc;

    for (int i = tid; i < CH * 128; i += 256) {
        int c = i >> 7, kk = i & 127;
        sU[c * 130 + kk] = U1[c * Cc + k0 + kk];
        sW[c * 130 + kk] = w2h[c * Cc + k0 + kk];
    }
    __syncthreads();

    const int ci0 = (tid >> 4) * 3, di0 = (tid & 15) * 3;
    float acc[3][3];
#pragma unroll
    for (int i = 0; i < 3; i++)
#pragma unroll
        for (int j = 0; j < 3; j++) acc[i][j] = 0.f;
#pragma unroll 8
    for (int kk = 0; kk < 128; kk++) {
        float u[3], w[3];
#pragma unroll
        for (int i = 0; i < 3; i++) u[i] = sU[(ci0 + i) * 130 + kk];
#pragma unroll
        for (int j = 0; j < 3; j++) w[j] = sW[(di0 + j) * 130 + kk];
#pragma unroll
        for (int i = 0; i < 3; i++)
#pragma unroll
            for (int j = 0; j < 3; j++) acc[i][j] += u[i] * w[j];
    }
    float* Gp = g_Gp + (((size_t)kt * Bb + b) * HEADS + h) * (CH * CH);
#pragma unroll
    for (int i = 0; i < 3; i++)
#pragma unroll
        for (int j = 0; j < 3; j++)
            Gp[(ci0 + i) * CH + di0 + j] = acc[i][j];

    float* rp = g_rp + (((size_t)kt * Bb + b) * HEADS + h) * (4 * CH);
    for (int c = warp * 6; c < warp * 6 + 6; c++) {
        float aq = 0.f, ak = 0.f, p1 = 0.f, p2 = 0.f;
#pragma unroll
        for (int it = 0; it < 4; it++) {
            int k = k0 + lane + it * 32;
            float w1v = w1h[c * Cc + k];
            float w2v = w2h[c * Cc + k];
            aq += U1[c * Cc + k] * w1v;
            ak += U2[c * Cc + k] * w2v;
            float sv = g_sxp[(size_t)b * Cc + k]
                     + g_sxp[((size_t)Bb + b) * Cc + k]
                     + g_sxp[((size_t)2 * Bb + b) * Cc + k];
            p1 += w1v * sv;
            p2 += w2v * sv;
        }
#pragma unroll
        for (int o = 16; o; o >>= 1) {
            aq += __shfl_xor_sync(0xffffffffu, aq, o);
            ak += __shfl_xor_sync(0xffffffffu, ak, o);
            p1 += __shfl_xor_sync(0xffffffffu, p1, o);
            p2 += __shfl_xor_sync(0xffffffffu, p2, o);
        }
        if (lane == 0) {
            rp[0 * CH + c] = aq;
            rp[1 * CH + c] = ak;
            rp[2 * CH + c] = p1;
            rp[3 * CH + c] = p2;
        }
    }
}

// ---------------------------------------------------------------------------
// k_foldM: combine partials -> softmax A (redundant per kt), fold M k-slice,
// kt==0 writes mb. grid (3, HEADS, Bb).
// ---------------------------------------------------------------------------
__global__ void __launch_bounds__(256) k_foldM(
    const float* __restrict__ w3, const float* __restrict__ b1,
    const float* __restrict__ b2, const float* __restrict__ b3,
    const float* __restrict__ temp)
{
    __shared__ float sAa[CH * 49];
    __shared__ float sW[CH * 130];
    __shared__ float sNq[CH], sNk[CH], sP1[CH], sP2[CH];
    __shared__ float sB1[CH], sB2[CH], sB3[CH];

    const int kt = blockIdx.x, h = blockIdx.y, b = blockIdx.z;
    const int k0 = kt * 128;
    const int tid = threadIdx.x;
    const int warp = tid >> 5, lane = tid & 31;

    const size_t gstr = (size_t)Bb * HEADS * CH * CH;
    const size_t rstr = (size_t)Bb * HEADS * 4 * CH;
    const float* Gp = g_Gp + ((size_t)b * HEADS + h) * (CH * CH);
    const float* rp = g_rp + ((size_t)b * HEADS + h) * (4 * CH);
    const float* w3h = w3 + (size_t)h * CH * Cc;

    if (tid < CH) {
        sB1[tid] = b1[h * CH + tid];
        sB2[tid] = b2[h * CH + tid];
        sB3[tid] = b3[h * CH + tid];
        sNq[tid] = rp[0 * CH + tid] + rp[rstr + 0 * CH + tid] + rp[2 * rstr + 0 * CH + tid];
        sNk[tid] = rp[1 * CH + tid] + rp[rstr + 1 * CH + tid] + rp[2 * rstr + 1 * CH + tid];
        sP1[tid] = rp[2 * CH + tid] + rp[rstr + 2 * CH + tid] + rp[2 * rstr + 2 * CH + tid];
        sP2[tid] = rp[3 * CH + tid] + rp[rstr + 3 * CH + tid] + rp[2 * rstr + 3 * CH + tid];
    }
    // stage W3 slice while logits are being built
    for (int i = tid; i < CH * 128; i += 256) {
        int d = i >> 7, kk = i & 127;
        sW[d * 130 + kk] = w3h[d * Cc + k0 + kk];
    }
    __syncthreads();

    const float tH = temp[h];
#pragma unroll
    for (int e = 0; e < 9; e++) {
        int idx = tid + 256 * e;
        int c = idx / CH, d = idx - c * CH;
        float g = Gp[idx] + Gp[gstr + idx] + Gp[2 * gstr + idx];
        float b1c = sB1[c], b2d = sB2[d];
        float nq = sqrtf(fmaxf(sNq[c] + 2.f * b1c * sP1[c] + 4096.f * b1c * b1c, 0.f));
        float nk = sqrtf(fmaxf(sNk[d] + 2.f * b2d * sP2[d] + 4096.f * b2d * b2d, 0.f));
        g = g + b1c * sP2[d] + b2d * sP1[c] + 4096.f * b1c * b2d;
        sAa[c * 49 + d] = g / (fmaxf(nq, 1e-12f) * fmaxf(nk, 1e-12f)) * tH;
    }
    __syncthreads();

    for (int c = warp * 6; c < warp * 6 + 6; c++) {
        float a0 = sAa[c * 49 + lane];
        float a1 = (lane < 16) ? sAa[c * 49 + 32 + lane] : -3.402823466e38f;
        float m = fmaxf(a0, a1);
#pragma unroll
        for (int o = 16; o; o >>= 1) m = fmaxf(m, __shfl_xor_sync(0xffffffffu, m, o));
        float e0 = __expf(a0 - m);
        float e1 = (lane < 16) ? __expf(a1 - m) : 0.f;
        float s = e0 + e1;
#pragma unroll
        for (int o = 16; o; o >>= 1) s += __shfl_xor_sync(0xffffffffu, s, o);
        float inv = 1.f / s;
        sAa[c * 49 + lane] = e0 * inv;
        if (lane < 16) sAa[c * 49 + 32 + lane] = e1 * inv;
    }
    __syncthreads();

    if (kt == 0 && tid < CH) {
        float s = sB3[tid];
#pragma unroll 8
        for (int d = 0; d < CH; d++) s += sAa[tid * 49 + d] * sB3[d];
        g_mb[b * Cc + h * CH + tid] = s;
    }

    // fold this k-slice: M = (A+I)W3 + I
    const int kkl = tid & 127, half = tid >> 7;
    float w[CH];
#pragma unroll 12
    for (int d = 0; d < CH; d++) w[d] = sW[d * 130 + kkl];

    __half* Mrow = g_Mh + (size_t)b * Cc * Cc + (size_t)(h * CH) * Cc + k0 + kkl;
    for (int c = half * 24; c < half * 24 + 24; c++) {
        float s = w[0] * sAa[c * 49 + 0] + sW[c * 130 + kkl];
#pragma unroll 12
        for (int d = 1; d < CH; d++) s += sAa[c * 49 + d] * w[d];
        if (h * CH + c == k0 + kkl) s += 1.f;
        Mrow[(size_t)c * Cc] = __float2half_rn(s);
    }
}

// ---------------------------------------------------------------------------
extern "C" void kernel_launch(void* const* d_in, const int* in_sizes, int n_in,
                              void* d_out, int out_size)
{
    (void)in_sizes; (void)n_in; (void)out_size;
    const float* x    = (const float*)d_in[0];
    const float* w1   = (const float*)d_in[1];
    const float* b1   = (const float*)d_in[2];
    const float* w2   = (const float*)d_in[3];
    const float* b2   = (const float*)d_in[4];
    const float* w3   = (const float*)d_in[5];
    const float* b3   = (const float*)d_in[6];
    const float* temp = (const float*)d_in[7];
    float* out = (float*)d_out;

    cudaFuncSetAttribute(gemm_S,   cudaFuncAttributeMaxDynamicSharedMemorySize, DSMEM_S);
    cudaFuncSetAttribute(gemm_U,   cudaFuncAttributeMaxDynamicSharedMemorySize, DSMEM_S);
    cudaFuncSetAttribute(gemm_out, cudaFuncAttributeMaxDynamicSharedMemorySize, DSMEM_O);
    cudaFuncSetAttribute(k_attn1,  cudaFuncAttributeMaxDynamicSharedMemorySize, ATTN1_SM);

    gemm_S<<<dim3(6, 3, Bb), 256, DSMEM_S>>>(x);
    k_Sreduce<<<dim3(16, 6, Bb), 256>>>();

    gemm_U<<<dim3(6, 3, Bb), 256, DSMEM_S>>>(w1, w2);

    k_attn1<<<dim3(3, HEADS, Bb), 256, ATTN1_SM>>>(w1, w2);
    k_foldM<<<dim3(3, HEADS, Bb), 256>>>(w3, b1, b2, b3, temp);

    gemm_out<<<dim3(3, 32, Bb), 256, DSMEM_O>>>(out);
}

// round 11
// speedup vs baseline: 4.0298x; 1.1610x over previous
#include <cuda_runtime.h>
#include <cuda_fp16.h>
#include <math.h>
#include <stdint.h>

#define Bb 16
#define Cc 384
#define Nn 4096
#define HEADS 8
#define CH 48
#define SSZ (Bb*Cc*Cc)

// ---------------- scratch (device globals; allocation-free) ----------------
__device__ __half g_Sh[SSZ];                // S fp16
__device__ __half g_Mh[SSZ];                // folded (A+I)W3 + I (fp16)
__device__ __half g_Xh[(size_t)Bb*Cc*Nn];   // x fp16 [b][c][n]
__device__ float g_U1[SSZ], g_U2[SSZ];
__device__ float g_Sp[3*Bb*6*16384];        // split-K partial S tiles
__device__ float g_sx[Bb*Cc];               // row sums
__device__ float g_mb[Bb*Cc];
__device__ float g_Gp[3*Bb*HEADS*CH*CH];    // split-K partial Gqk
__device__ float g_rp[3*Bb*HEADS*4*CH];     // split-K partial row reductions

// ---------------- PTX helpers (sm_80-class; no 'a'-gated features) ---------
__device__ __forceinline__ uint32_t smem_u32(const void* p) {
    uint32_t a;
    asm("{ .reg .u64 t; cvta.to.shared.u64 t, %1; cvt.u32.u64 %0, t; }"
        : "=r"(a) : "l"(p));
    return a;
}
__device__ __forceinline__ void ldsm4(uint32_t* r, uint32_t addr) {
    asm volatile("ldmatrix.sync.aligned.m8n8.x4.shared.b16 {%0,%1,%2,%3}, [%4];"
                 : "=r"(r[0]), "=r"(r[1]), "=r"(r[2]), "=r"(r[3]) : "r"(addr));
}
__device__ __forceinline__ void ldsm4t(uint32_t* r, uint32_t addr) {
    asm volatile("ldmatrix.sync.aligned.m8n8.x4.trans.shared.b16 {%0,%1,%2,%3}, [%4];"
                 : "=r"(r[0]), "=r"(r[1]), "=r"(r[2]), "=r"(r[3]) : "r"(addr));
}
__device__ __forceinline__ void mma16816(float* c, const uint32_t* a, const uint32_t* b) {
    asm volatile(
        "mma.sync.aligned.m16n8k16.row.col.f32.f16.f16.f32 "
        "{%0,%1,%2,%3}, {%4,%5,%6,%7}, {%8,%9}, {%0,%1,%2,%3};"
        : "+f"(c[0]), "+f"(c[1]), "+f"(c[2]), "+f"(c[3])
        : "r"(a[0]), "r"(a[1]), "r"(a[2]), "r"(a[3]), "r"(b[0]), "r"(b[1]));
}
#define CP_ASYNC16(dst, src) \
    asm volatile("cp.async.cg.shared.global [%0], [%1], 16;" \
                 :: "r"(dst), "l"(__cvta_generic_to_global(src)))
#define CP_COMMIT() asm volatile("cp.async.commit_group;" ::: "memory")
#define CP_WAIT0()  asm volatile("cp.async.wait_group 0;" ::: "memory")
#define CP_WAIT1()  asm volatile("cp.async.wait_group 1;" ::: "memory")

// smem geometry
#define SROW80    80
#define ATILE     10240
#define STAGE_S1  20480     // Ah, Bh (1-pass NT); 3 stages
#define DSMEM_S   69632
#define AROW144   144
#define ATILE_O   18432
#define BPITCH    272
#define STAGE_O   35840     // 2 stages
#define DSMEM_O   71680
#define ATTN1_SM  49920     // 2 * 48 * 130 * 4

// ---------------------------------------------------------------------------
// compute bodies (warp tile 32x64; acc[2][8][4])
// ---------------------------------------------------------------------------
__device__ __forceinline__ void compute_nt1(uint32_t smb, int wm, int wn, int lane,
                                            float acc[2][8][4]) {
    const int grp = lane >> 3, lr = lane & 7;
#pragma unroll
    for (int ks = 0; ks < 2; ks++) {
        const int kc = ks * 16;
        uint32_t ah[2][4];
#pragma unroll
        for (int ti = 0; ti < 2; ti++) {
            int row = wm * 32 + ti * 16 + lr + (grp & 1) * 8;
            int col = kc + (grp >> 1) * 8;
            ldsm4(ah[ti], smb + row * SROW80 + col * 2);
        }
#pragma unroll
        for (int half = 0; half < 2; half++) {
            uint32_t bhf[4][2];
#pragma unroll
            for (int p = 0; p < 2; p++) {
                int nrow = wn * 64 + half * 32 + p * 16 + (grp >> 1) * 8 + lr;
                int col = kc + (grp & 1) * 8;
                uint32_t r4[4];
                ldsm4(r4, smb + ATILE + nrow * SROW80 + col * 2);
                bhf[2*p][0] = r4[0]; bhf[2*p][1] = r4[1];
                bhf[2*p+1][0] = r4[2]; bhf[2*p+1][1] = r4[3];
            }
#pragma unroll
            for (int ti = 0; ti < 2; ti++)
#pragma unroll
                for (int tj = 0; tj < 4; tj++)
                    mma16816(acc[ti][half * 4 + tj], ah[ti], bhf[tj]);
        }
    }
}

__device__ __forceinline__ void compute_o(uint32_t smbA, uint32_t smbB,
                                          int wm, int wn, int lane,
                                          float acc[2][8][4]) {
    const int grp = lane >> 3, lr = lane & 7;
#pragma unroll
    for (int ks = 0; ks < 4; ks++) {
        const int kc = ks * 16;
        uint32_t ah[2][4];
#pragma unroll
        for (int ti = 0; ti < 2; ti++) {
            int row = wm * 32 + ti * 16 + lr + (grp & 1) * 8;
            int col = kc + (grp >> 1) * 8;
            ldsm4(ah[ti], smbA + row * AROW144 + col * 2);
        }
#pragma unroll
        for (int half = 0; half < 2; half++) {
            uint32_t bhf[4][2];
#pragma unroll
            for (int p = 0; p < 2; p++) {
                int krow = kc + ((lane >> 3) & 1) * 8 + (lane & 7);
                int ncol = wn * 64 + half * 32 + p * 16 + (lane >> 4) * 8;
                uint32_t r4[4];
                ldsm4t(r4, smbB + krow * BPITCH + ncol * 2);
                bhf[2*p][0] = r4[0]; bhf[2*p][1] = r4[1];
                bhf[2*p+1][0] = r4[2]; bhf[2*p+1][1] = r4[3];
            }
#pragma unroll
            for (int ti = 0; ti < 2; ti++)
#pragma unroll
                for (int tj = 0; tj < 4; tj++)
                    mma16816(acc[ti][half * 4 + tj], ah[ti], bhf[tj]);
        }
    }
}

__device__ __forceinline__ void sts_cvt4(char* p, float4 f) {
    __half2 h01 = __floats2half2_rn(f.x, f.y);
    __half2 h23 = __floats2half2_rn(f.z, f.w);
    uint2 hh;
    hh.x = *(uint32_t*)&h01; hh.y = *(uint32_t*)&h23;
    *(uint2*)p = hh;
}

// ---------------------------------------------------------------------------
// k_convert: x -> g_Xh (fp16) + g_sx (row sums). grid (Bb*Cc), 256 thr.
// ---------------------------------------------------------------------------
__global__ void __launch_bounds__(256) k_convert(const float* __restrict__ x) {
    const int row = blockIdx.x;
    const float4* xr = (const float4*)(x + (size_t)row * Nn);
    __half* xo = g_Xh + (size_t)row * Nn;
    float s = 0.f;
#pragma unroll
    for (int j = 0; j < 4; j++) {
        int idx = threadIdx.x + 256 * j;
        float4 v = xr[idx];
        s += (v.x + v.y) + (v.z + v.w);
        __half2 h01 = __floats2half2_rn(v.x, v.y);
        __half2 h23 = __floats2half2_rn(v.z, v.w);
        uint2 hh;
        hh.x = *(uint32_t*)&h01; hh.y = *(uint32_t*)&h23;
        *(uint2*)(xo + idx * 4) = hh;
    }
    __shared__ float red[256];
    red[threadIdx.x] = s;
    __syncthreads();
    for (int o = 128; o; o >>= 1) {
        if (threadIdx.x < o) red[threadIdx.x] += red[threadIdx.x + o];
        __syncthreads();
    }
    if (threadIdx.x == 0) g_sx[row] = red[0];
}

// ---------------------------------------------------------------------------
// S GEMM, triangle + split-K=3, 1-pass, cp.async 3-stage, fp16 in.
// grid (6 pairs, 3 kz, 16 batch)
// ---------------------------------------------------------------------------
__global__ void __launch_bounds__(256) gemm_S() {
    extern __shared__ char dsm[];
    const int pxl[6] = {0,0,0,1,1,2}, pyl[6] = {0,1,2,1,2,2};
    const int tid = threadIdx.x, lane = tid & 31, wid = tid >> 5;
    const int wm = wid & 3, wn = wid >> 2;
    const int pair = blockIdx.x, kz = blockIdx.y, bz = blockIdx.z;
    const int bx = pxl[pair], by = pyl[pair];
    const int c0 = (kz == 0) ? 0 : (kz == 1 ? 43 : 86);
    const int c1 = (kz == 0) ? 43 : (kz == 1 ? 86 : 128);
    const int nch = c1 - c0;
    const uint32_t smb = smem_u32(dsm);

    const __half* Ax = g_Xh + ((size_t)bz * Cc + bx * 128) * Nn + c0 * 32;
    const __half* Bx = g_Xh + ((size_t)bz * Cc + by * 128) * Nn + c0 * 32;

    // loader: 2 x 16B for A + 2 for B per thread; rows of 64B = 4 x 16B
    int rw[2], qq[2];
#pragma unroll
    for (int j = 0; j < 2; j++) { int u = tid + 256 * j; rw[j] = u >> 2; qq[j] = u & 3; }

    float acc[2][8][4];
#pragma unroll
    for (int i = 0; i < 2; i++)
#pragma unroll
        for (int j = 0; j < 8; j++)
#pragma unroll
            for (int q = 0; q < 4; q++) acc[i][j][q] = 0.f;

#define ISSUE_S(chunk, stage) do { \
    uint32_t _b = smb + (stage) * STAGE_S1; \
    int _k = (chunk) * 32; \
    _Pragma("unroll") \
    for (int _j = 0; _j < 2; _j++) { \
        CP_ASYNC16(_b + rw[_j] * SROW80 + qq[_j] * 16, \
                   Ax + (size_t)rw[_j] * Nn + _k + qq[_j] * 8); \
        CP_ASYNC16(_b + ATILE + rw[_j] * SROW80 + qq[_j] * 16, \
                   Bx + (size_t)rw[_j] * Nn + _k + qq[_j] * 8); \
    } } while (0)

    ISSUE_S(0, 0); CP_COMMIT();
    ISSUE_S(1, 1); CP_COMMIT();

    int st = 0;
    for (int i = 0; i < nch; i++) {
        if (i == nch - 1) CP_WAIT0(); else CP_WAIT1();
        __syncthreads();
        if (i + 2 < nch) {
            int s2 = st + 2; if (s2 >= 3) s2 -= 3;
            ISSUE_S(i + 2, s2); CP_COMMIT();
        }
        compute_nt1(smb + st * STAGE_S1, wm, wn, lane, acc);
        if (++st == 3) st = 0;
    }
    __syncthreads();
#undef ISSUE_S

    float* sC = (float*)dsm;
#pragma unroll
    for (int ti = 0; ti < 2; ti++)
#pragma unroll
        for (int j = 0; j < 8; j++) {
            int row0 = wm * 32 + ti * 16 + (lane >> 2);
            int col  = wn * 64 + j * 8 + (lane & 3) * 2;
            *(float2*)(sC + row0 * 132 + col)       = make_float2(acc[ti][j][0], acc[ti][j][1]);
            *(float2*)(sC + (row0 + 8) * 132 + col) = make_float2(acc[ti][j][2], acc[ti][j][3]);
        }
    __syncthreads();

    float* outp = g_Sp + (((size_t)kz * Bb + bz) * 6 + pair) * 16384;
    const int r0 = tid >> 1, half = tid & 1;
    const float* src = sC + r0 * 132 + half * 64;
#pragma unroll
    for (int j = 0; j < 64; j += 4)
        *(float4*)(outp + r0 * 128 + half * 64 + j) = *(const float4*)(src + j);
}

// ---------------------------------------------------------------------------
// S reduce: sum 3 partials -> fp16 Sh (tile + transpose).
// grid (16 subtiles, 6 pairs, 16 batch)
// ---------------------------------------------------------------------------
__global__ void __launch_bounds__(256) k_Sreduce() {
    __shared__ float t[32][33];
    const int pxl[6] = {0,0,0,1,1,2}, pyl[6] = {0,1,2,1,2,2};
    const int sub = blockIdx.x, pair = blockIdx.y, bz = blockIdx.z;
    const int px = pxl[pair], py = pyl[pair];
    const int si = sub >> 2, sj = sub & 3;
    const int cc = threadIdx.x & 31, rb = threadIdx.x >> 5;

    const size_t stride = (size_t)Bb * 6 * 16384;
    const float* p0 = g_Sp + ((size_t)bz * 6 + pair) * 16384;
    const float* p1 = p0 + stride;
    const float* p2 = p0 + 2 * stride;
    const size_t gb = (size_t)bz * Cc * Cc;

#pragma unroll
    for (int r = 0; r < 4; r++) {
        int rr = rb + r * 8;
        int li = (si * 32 + rr) * 128 + sj * 32 + cc;
        float s = p0[li] + p1[li] + p2[li];
        t[rr][cc] = s;
        size_t o = gb + (size_t)(px * 128 + si * 32 + rr) * Cc + py * 128 + sj * 32 + cc;
        g_Sh[o] = __float2half_rn(s);
    }
    if (px == py) return;
    __syncthreads();
#pragma unroll
    for (int r = 0; r < 4; r++) {
        int rr = rb + r * 8;
        float s = t[cc][rr];
        size_t o = gb + (size_t)(py * 128 + sj * 32 + rr) * Cc + px * 128 + si * 32 + cc;
        g_Sh[o] = __float2half_rn(s);
    }
}

// ---------------------------------------------------------------------------
// U GEMM (fused U1+U2), 1-pass: U = Wh Sh. grid (6,3,16).
// ---------------------------------------------------------------------------
__global__ void __launch_bounds__(256) gemm_U(const float* __restrict__ w1,
                                              const float* __restrict__ w2) {
    extern __shared__ char dsm[];
    const int tid = threadIdx.x, lane = tid & 31, wid = tid >> 5;
    const int wm = wid & 3, wn = wid >> 2;
    const int sel = blockIdx.x >= 3;
    const int bx = blockIdx.x - (sel ? 3 : 0);
    const int by = blockIdx.y, bz = blockIdx.z;
    const uint32_t smb = smem_u32(dsm);

    const float* Aw = (sel ? w2 : w1) + (size_t)bx * 128 * Cc;
    const __half* pBh = g_Sh + (size_t)bz * Cc * Cc + (size_t)by * 128 * Cc;
    float* Cf = sel ? g_U2 : g_U1;

    int rw[4], qq[4];
#pragma unroll
    for (int j = 0; j < 4; j++) { int u = tid + 256 * j; rw[j] = u >> 3; qq[j] = u & 7; }
    int frow[2], fq[2];
#pragma unroll
    for (int j = 0; j < 2; j++) { int u = tid + 256 * j; frow[j] = u >> 2; fq[j] = u & 3; }

    float acc[2][8][4];
#pragma unroll
    for (int i = 0; i < 2; i++)
#pragma unroll
        for (int j = 0; j < 8; j++)
#pragma unroll
            for (int q = 0; q < 4; q++) acc[i][j][q] = 0.f;

    float4 vA[4];
    uint4 vBh[2];
#pragma unroll
    for (int j = 0; j < 4; j++)
        vA[j] = *(const float4*)(Aw + (size_t)rw[j] * Cc + qq[j] * 4);
#pragma unroll
    for (int j = 0; j < 2; j++)
        vBh[j] = *(const uint4*)(pBh + (size_t)frow[j] * Cc + fq[j] * 8);
    {
        char* base = dsm;
#pragma unroll
        for (int j = 0; j < 4; j++)
            sts_cvt4(base + rw[j] * SROW80 + qq[j] * 8, vA[j]);
#pragma unroll
        for (int j = 0; j < 2; j++)
            *(uint4*)(base + ATILE + frow[j] * SROW80 + fq[j] * 16) = vBh[j];
    }
#pragma unroll
    for (int j = 0; j < 4; j++)
        vA[j] = *(const float4*)(Aw + (size_t)rw[j] * Cc + 32 + qq[j] * 4);
#pragma unroll
    for (int j = 0; j < 2; j++)
        vBh[j] = *(const uint4*)(pBh + (size_t)frow[j] * Cc + 32 + fq[j] * 8);
    __syncthreads();

    const int nch = Cc / 32;
    for (int i = 0; i < nch; i++) {
        if (i + 1 < nch) {
            char* base = dsm + ((i + 1) & 1) * STAGE_S1;
#pragma unroll
            for (int j = 0; j < 4; j++)
                sts_cvt4(base + rw[j] * SROW80 + qq[j] * 8, vA[j]);
#pragma unroll
            for (int j = 0; j < 2; j++)
                *(uint4*)(base + ATILE + frow[j] * SROW80 + fq[j] * 16) = vBh[j];
        }
        if (i + 2 < nch) {
            int k0 = (i + 2) * 32;
#pragma unroll
            for (int j = 0; j < 4; j++)
                vA[j] = *(const float4*)(Aw + (size_t)rw[j] * Cc + k0 + qq[j] * 4);
#pragma unroll
            for (int j = 0; j < 2; j++)
                vBh[j] = *(const uint4*)(pBh + (size_t)frow[j] * Cc + k0 + fq[j] * 8);
        }
        compute_nt1(smb + (i & 1) * STAGE_S1, wm, wn, lane, acc);
        __syncthreads();
    }

    float* sC = (float*)dsm;
#pragma unroll
    for (int ti = 0; ti < 2; ti++)
#pragma unroll
        for (int j = 0; j < 8; j++) {
            int row0 = wm * 32 + ti * 16 + (lane >> 2);
            int col  = wn * 64 + j * 8 + (lane & 3) * 2;
            *(float2*)(sC + row0 * 132 + col)       = make_float2(acc[ti][j][0], acc[ti][j][1]);
            *(float2*)(sC + (row0 + 8) * 132 + col) = make_float2(acc[ti][j][2], acc[ti][j][3]);
        }
    __syncthreads();

    const int r0 = tid >> 1, half = tid & 1;
    const float* src = sC + r0 * 132 + half * 64;
    size_t base = ((size_t)bz * Cc + bx * 128 + r0) * Cc + by * 128 + half * 64;
#pragma unroll
    for (int j = 0; j < 64; j += 4)
        *(float4*)(Cf + base + j) = *(const float4*)(src + j);
}

// ---------------------------------------------------------------------------
// out GEMM, 1-pass, BK=64, cp.async 2-stage: out = Mh Xh + mb. grid (3,32,16).
// ---------------------------------------------------------------------------
__global__ void __launch_bounds__(256) gemm_out(float* __restrict__ out)
{
    extern __shared__ char dsm[];
    const int tid = threadIdx.x, lane = tid & 31, wid = tid >> 5;
    const int wm = wid & 3, wn = wid >> 2;
    const int bx = blockIdx.x, by = blockIdx.y, bz = blockIdx.z;
    const uint32_t smb = smem_u32(dsm);

    const __half* pA = g_Mh + (size_t)bz * Cc * Cc + (size_t)bx * 128 * Cc;
    const __half* pB = g_Xh + (size_t)bz * Cc * Nn + by * 128;

    int arw[4], aq[4];
#pragma unroll
    for (int j = 0; j < 4; j++) { int u = tid + 256 * j; arw[j] = u >> 3; aq[j] = u & 7; }
    int brw[4], bq[4];
#pragma unroll
    for (int j = 0; j < 4; j++) { int u = tid + 256 * j; brw[j] = u >> 4; bq[j] = u & 15; }

    float acc[2][8][4];
#pragma unroll
    for (int i = 0; i < 2; i++)
#pragma unroll
        for (int j = 0; j < 8; j++)
#pragma unroll
            for (int q = 0; q < 4; q++) acc[i][j][q] = 0.f;

#define ISSUE_O(chunk, stage) do { \
    uint32_t _b = smb + (stage) * STAGE_O; \
    int _k = (chunk) * 64; \
    _Pragma("unroll") \
    for (int _j = 0; _j < 4; _j++) { \
        CP_ASYNC16(_b + arw[_j] * AROW144 + aq[_j] * 16, \
                   pA + (size_t)arw[_j] * Cc + _k + aq[_j] * 8); \
        CP_ASYNC16(_b + ATILE_O + brw[_j] * BPITCH + bq[_j] * 16, \
                   pB + (size_t)(_k + brw[_j]) * Nn + bq[_j] * 8); \
    } } while (0)

    ISSUE_O(0, 0); CP_COMMIT();

    const int nch = Cc / 64;   // 6
    for (int i = 0; i < nch; i++) {
        CP_WAIT0();
        __syncthreads();
        if (i + 1 < nch) { ISSUE_O(i + 1, (i + 1) & 1); CP_COMMIT(); }
        uint32_t st = smb + (i & 1) * STAGE_O;
        compute_o(st, st + ATILE_O, wm, wn, lane, acc);
    }
    __syncthreads();
#undef ISSUE_O

    float* sC = (float*)dsm;
#pragma unroll
    for (int ti = 0; ti < 2; ti++)
#pragma unroll
        for (int j = 0; j < 8; j++) {
            int row0 = wm * 32 + ti * 16 + (lane >> 2);
            int col  = wn * 64 + j * 8 + (lane & 3) * 2;
            *(float2*)(sC + row0 * 132 + col)       = make_float2(acc[ti][j][0], acc[ti][j][1]);
            *(float2*)(sC + (row0 + 8) * 132 + col) = make_float2(acc[ti][j][2], acc[ti][j][3]);
        }
    __syncthreads();

    const int r0 = tid >> 1, half = tid & 1;
    const float* src = sC + r0 * 132 + half * 64;
    const int grow = bx * 128 + r0;
    float bias = g_mb[bz * Cc + grow];
    size_t base = ((size_t)bz * Cc + grow) * (size_t)Nn + by * 128 + half * 64;
#pragma unroll
    for (int j = 0; j < 64; j += 4) {
        float4 v4 = *(const float4*)(src + j);
        *(float4*)(out + base + j) = make_float4(v4.x + bias, v4.y + bias,
                                                 v4.z + bias, v4.w + bias);
    }
}

// ---------------------------------------------------------------------------
// k_attn1: split-K partial Gqk + partial row reductions. grid (3, HEADS, Bb).
// ---------------------------------------------------------------------------
__global__ void __launch_bounds__(256) k_attn1(
    const float* __restrict__ w1, const float* __restrict__ w2)
{
    extern __shared__ float satt[];       // sU[48*130], sW[48*130]
    float* sU = satt;
    float* sW = satt + CH * 130;

    const int kt = blockIdx.x, h = blockIdx.y, b = blockIdx.z;
    const int k0 = kt * 128;
    const int tid = threadIdx.x;
    const int warp = tid >> 5, lane = tid & 31;

    const float* U1  = &g_U1[(size_t)b * Cc * Cc + (size_t)h * CH * Cc];
    const float* U2  = &g_U2[(size_t)b * Cc * Cc + (size_t)h * CH * Cc];
    const float* w1h = w1 + (size_t)h * CH * Cc;
    const float* w2h = w2 + (size_t)h * CH * Cc;

    for (int i = tid; i < CH * 128; i += 256) {
        int c = i >> 7, kk = i & 127;
        sU[c * 130 + kk] = U1[c * Cc + k0 + kk];
        sW[c * 130 + kk] = w2h[c * Cc + k0 + kk];
    }
    __syncthreads();

    const int ci0 = (tid >> 4) * 3, di0 = (tid & 15) * 3;
    float acc[3][3];
#pragma unroll
    for (int i = 0; i < 3; i++)
#pragma unroll
        for (int j = 0; j < 3; j++) acc[i][j] = 0.f;
#pragma unroll 8
    for (int kk = 0; kk < 128; kk++) {
        float u[3], w[3];
#pragma unroll
        for (int i = 0; i < 3; i++) u[i] = sU[(ci0 + i) * 130 + kk];
#pragma unroll
        for (int j = 0; j < 3; j++) w[j] = sW[(di0 + j) * 130 + kk];
#pragma unroll
        for (int i = 0; i < 3; i++)
#pragma unroll
            for (int j = 0; j < 3; j++) acc[i][j] += u[i] * w[j];
    }
    float* Gp = g_Gp + (((size_t)kt * Bb + b) * HEADS + h) * (CH * CH);
#pragma unroll
    for (int i = 0; i < 3; i++)
#pragma unroll
        for (int j = 0; j < 3; j++)
            Gp[(ci0 + i) * CH + di0 + j] = acc[i][j];

    float* rp = g_rp + (((size_t)kt * Bb + b) * HEADS + h) * (4 * CH);
    for (int c = warp * 6; c < warp * 6 + 6; c++) {
        float aq = 0.f, ak = 0.f, p1 = 0.f, p2 = 0.f;
#pragma unroll
        for (int it = 0; it < 4; it++) {
            int k = k0 + lane + it * 32;
            float w1v = w1h[c * Cc + k];
            float w2v = w2h[c * Cc + k];
            aq += U1[c * Cc + k] * w1v;
            ak += U2[c * Cc + k] * w2v;
            float sv = g_sx[(size_t)b * Cc + k];
            p1 += w1v * sv;
            p2 += w2v * sv;
        }
#pragma unroll
        for (int o = 16; o; o >>= 1) {
            aq += __shfl_xor_sync(0xffffffffu, aq, o);
            ak += __shfl_xor_sync(0xffffffffu, ak, o);
            p1 += __shfl_xor_sync(0xffffffffu, p1, o);
            p2 += __shfl_xor_sync(0xffffffffu, p2, o);
        }
        if (lane == 0) {
            rp[0 * CH + c] = aq;
            rp[1 * CH + c] = ak;
            rp[2 * CH + c] = p1;
            rp[3 * CH + c] = p2;
        }
    }
}

// ---------------------------------------------------------------------------
// k_foldM: combine partials -> softmax A (redundant per kt), fold M k-slice,
// kt==0 writes mb. grid (3, HEADS, Bb).
// ---------------------------------------------------------------------------
__global__ void __launch_bounds__(256) k_foldM(
    const float* __restrict__ w3, const float* __restrict__ b1,
    const float* __restrict__ b2, const float* __restrict__ b3,
    const float* __restrict__ temp)
{
    __shared__ float sAa[CH * 49];
    __shared__ float sW[CH * 130];
    __shared__ float sNq[CH], sNk[CH], sP1[CH], sP2[CH];
    __shared__ float sB1[CH], sB2[CH], sB3[CH];

    const int kt = blockIdx.x, h = blockIdx.y, b = blockIdx.z;
    const int k0 = kt * 128;
    const int tid = threadIdx.x;
    const int warp = tid >> 5, lane = tid & 31;

    const size_t gstr = (size_t)Bb * HEADS * CH * CH;
    const size_t rstr = (size_t)Bb * HEADS * 4 * CH;
    const float* Gp = g_Gp + ((size_t)b * HEADS + h) * (CH * CH);
    const float* rp = g_rp + ((size_t)b * HEADS + h) * (4 * CH);
    const float* w3h = w3 + (size_t)h * CH * Cc;

    if (tid < CH) {
        sB1[tid] = b1[h * CH + tid];
        sB2[tid] = b2[h * CH + tid];
        sB3[tid] = b3[h * CH + tid];
        sNq[tid] = rp[0 * CH + tid] + rp[rstr + 0 * CH + tid] + rp[2 * rstr + 0 * CH + tid];
        sNk[tid] = rp[1 * CH + tid] + rp[rstr + 1 * CH + tid] + rp[2 * rstr + 1 * CH + tid];
        sP1[tid] = rp[2 * CH + tid] + rp[rstr + 2 * CH + tid] + rp[2 * rstr + 2 * CH + tid];
        sP2[tid] = rp[3 * CH + tid] + rp[rstr + 3 * CH + tid] + rp[2 * rstr + 3 * CH + tid];
    }
    for (int i = tid; i < CH * 128; i += 256) {
        int d = i >> 7, kk = i & 127;
        sW[d * 130 + kk] = w3h[d * Cc + k0 + kk];
    }
    __syncthreads();

    const float tH = temp[h];
#pragma unroll
    for (int e = 0; e < 9; e++) {
        int idx = tid + 256 * e;
        int c = idx / CH, d = idx - c * CH;
        float g = Gp[idx] + Gp[gstr + idx] + Gp[2 * gstr + idx];
        float b1c = sB1[c], b2d = sB2[d];
        float nq = sqrtf(fmaxf(sNq[c] + 2.f * b1c * sP1[c] + 4096.f * b1c * b1c, 0.f));
        float nk = sqrtf(fmaxf(sNk[d] + 2.f * b2d * sP2[d] + 4096.f * b2d * b2d, 0.f));
        g = g + b1c * sP2[d] + b2d * sP1[c] + 4096.f * b1c * b2d;
        sAa[c * 49 + d] = g / (fmaxf(nq, 1e-12f) * fmaxf(nk, 1e-12f)) * tH;
    }
    __syncthreads();

    for (int c = warp * 6; c < warp * 6 + 6; c++) {
        float a0 = sAa[c * 49 + lane];
        float a1 = (lane < 16) ? sAa[c * 49 + 32 + lane] : -3.402823466e38f;
        float m = fmaxf(a0, a1);
#pragma unroll
        for (int o = 16; o; o >>= 1) m = fmaxf(m, __shfl_xor_sync(0xffffffffu, m, o));
        float e0 = __expf(a0 - m);
        float e1 = (lane < 16) ? __expf(a1 - m) : 0.f;
        float s = e0 + e1;
#pragma unroll
        for (int o = 16; o; o >>= 1) s += __shfl_xor_sync(0xffffffffu, s, o);
        float inv = 1.f / s;
        sAa[c * 49 + lane] = e0 * inv;
        if (lane < 16) sAa[c * 49 + 32 + lane] = e1 * inv;
    }
    __syncthreads();

    if (kt == 0 && tid < CH) {
        float s = sB3[tid];
#pragma unroll 8
        for (int d = 0; d < CH; d++) s += sAa[tid * 49 + d] * sB3[d];
        g_mb[b * Cc + h * CH + tid] = s;
    }

    const int kkl = tid & 127, half = tid >> 7;
    float w[CH];
#pragma unroll 12
    for (int d = 0; d < CH; d++) w[d] = sW[d * 130 + kkl];

    __half* Mrow = g_Mh + (size_t)b * Cc * Cc + (size_t)(h * CH) * Cc + k0 + kkl;
    for (int c = half * 24; c < half * 24 + 24; c++) {
        float s = w[0] * sAa[c * 49 + 0] + sW[c * 130 + kkl];
#pragma unroll 12
        for (int d = 1; d < CH; d++) s += sAa[c * 49 + d] * w[d];
        if (h * CH + c == k0 + kkl) s += 1.f;
        Mrow[(size_t)c * Cc] = __float2half_rn(s);
    }
}

// ---------------------------------------------------------------------------
extern "C" void kernel_launch(void* const* d_in, const int* in_sizes, int n_in,
                              void* d_out, int out_size)
{
    (void)in_sizes; (void)n_in; (void)out_size;
    const float* x    = (const float*)d_in[0];
    const float* w1   = (const float*)d_in[1];
    const float* b1   = (const float*)d_in[2];
    const float* w2   = (const float*)d_in[3];
    const float* b2   = (const float*)d_in[4];
    const float* w3   = (const float*)d_in[5];
    const float* b3   = (const float*)d_in[6];
    const float* temp = (const float*)d_in[7];
    float* out = (float*)d_out;

    cudaFuncSetAttribute(gemm_S,   cudaFuncAttributeMaxDynamicSharedMemorySize, DSMEM_S);
    cudaFuncSetAttribute(gemm_U,   cudaFuncAttributeMaxDynamicSharedMemorySize, DSMEM_S);
    cudaFuncSetAttribute(gemm_out, cudaFuncAttributeMaxDynamicSharedMemorySize, DSMEM_O);
    cudaFuncSetAttribute(k_attn1,  cudaFuncAttributeMaxDynamicSharedMemorySize, ATTN1_SM);

    k_convert<<<Bb * Cc, 256>>>(x);

    gemm_S<<<dim3(6, 3, Bb), 256, DSMEM_S>>>();
    k_Sreduce<<<dim3(16, 6, Bb), 256>>>();

    gemm_U<<<dim3(6, 3, Bb), 256, DSMEM_S>>>(w1, w2);

    k_attn1<<<dim3(3, HEADS, Bb), 256, ATTN1_SM>>>(w1, w2);
    k_foldM<<<dim3(3, HEADS, Bb), 256>>>(w3, b1, b2, b3, temp);

    gemm_out<<<dim3(3, 32, Bb), 256, DSMEM_O>>>(out);
}